// round 2
// baseline (speedup 1.0000x reference)
#include <cuda_runtime.h>
#include <cuda_bf16.h>
#include <math.h>

// ---------------------------------------------------------------------------
// Problem constants
// ---------------------------------------------------------------------------
#define Bz   8
#define Tt   512
#define Dd   768
#define Hh   8
#define HD   96
#define NEXP 4
#define RH   128
#define D3   (3*Dd)     // 2304
#define D4   (4*Dd)     // 3072
#define SCALE_V (0.10206207261596575f)  // 1/sqrt(96)
#define LN_EPS 1e-5f

// ---------------------------------------------------------------------------
// Scratch (static device arrays -- no allocation allowed)
// ---------------------------------------------------------------------------
__device__ float g_scores[(long long)Bz*Hh*Tt*Tt];   // 64*512*512
__device__ float g_qkv   [(long long)Bz*Tt*D3];
__device__ float g_qkv2  [(long long)Bz*Tt*D3];
__device__ float g_xn    [(long long)Bz*Tt*Dd];
__device__ float g_xt    [(long long)Bz*Tt*Dd];
__device__ float g_attno [(long long)Bz*Tt*Dd];
__device__ float g_spout [(long long)Bz*Tt*Dd];
__device__ float g_tpout [(long long)Bz*Tt*Dd];
__device__ float g_x1    [(long long)Bz*Tt*Dd];
__device__ float g_hid   [(long long)Bz*Tt*D4];
__device__ int   g_idx   [16];   // [0..7]=idx_s, [8..15]=idx_t

__device__ __forceinline__ float gelu_exact(float v) {
    return 0.5f * v * (1.0f + erff(v * 0.70710678118654752f));
}

// ---------------------------------------------------------------------------
// Router: mean over T, 2-layer MLP, argmax per half
// one block per batch, 768 threads
// ---------------------------------------------------------------------------
__global__ void router_kernel(const float* __restrict__ x,
                              const float* __restrict__ w1, const float* __restrict__ b1,
                              const float* __restrict__ w2, const float* __restrict__ b2,
                              int* __restrict__ idx_s, int* __restrict__ idx_t)
{
    __shared__ float xm[Dd];
    __shared__ float hbuf[RH];
    __shared__ float lg[8];
    int b = blockIdx.x;
    int d = threadIdx.x;
    const float* xb = x + (long long)b * Tt * Dd;
    float s = 0.f;
    for (int t = 0; t < Tt; t++) s += xb[(long long)t * Dd + d];
    xm[d] = s * (1.0f / Tt);
    __syncthreads();
    if (d < RH) {
        float a = b1[d];
        const float* wr = w1 + (long long)d * Dd;
        for (int k = 0; k < Dd; k++) a += xm[k] * wr[k];
        hbuf[d] = gelu_exact(a);
    }
    __syncthreads();
    if (d < 8) {
        float a = b2[d];
        const float* wr = w2 + d * RH;
        for (int k = 0; k < RH; k++) a += hbuf[k] * wr[k];
        lg[d] = a;
    }
    __syncthreads();
    if (d == 0) {
        int is = 0; for (int i = 1; i < NEXP; i++) if (lg[i] > lg[is]) is = i;
        int it = 0; for (int i = 1; i < NEXP; i++) if (lg[NEXP+i] > lg[NEXP+it]) it = i;
        idx_s[b] = is;
        idx_t[b] = it;
    }
}

// ---------------------------------------------------------------------------
// LayerNorm over last dim (768). one block per row, 256 threads x 3 elems
// ---------------------------------------------------------------------------
__global__ __launch_bounds__(256) void ln_kernel(const float* __restrict__ x,
                                                 const float* __restrict__ g,
                                                 const float* __restrict__ bb,
                                                 float* __restrict__ y)
{
    __shared__ float sd[256];
    long long row = blockIdx.x;
    int t = threadIdx.x;
    const float* xr = x + row * Dd;
    float a0 = xr[t], a1 = xr[t+256], a2 = xr[t+512];
    sd[t] = a0 + a1 + a2;
    __syncthreads();
    for (int s = 128; s > 0; s >>= 1) { if (t < s) sd[t] += sd[t+s]; __syncthreads(); }
    float mean = sd[0] * (1.0f / Dd);
    __syncthreads();
    float d0 = a0 - mean, d1 = a1 - mean, d2 = a2 - mean;
    sd[t] = d0*d0 + d1*d1 + d2*d2;
    __syncthreads();
    for (int s = 128; s > 0; s >>= 1) { if (t < s) sd[t] += sd[t+s]; __syncthreads(); }
    float inv = rsqrtf(sd[0] * (1.0f / Dd) + LN_EPS);
    float* yr = y + row * Dd;
    yr[t]     = d0 * inv * g[t]     + bb[t];
    yr[t+256] = d1 * inv * g[t+256] + bb[t+256];
    yr[t+512] = d2 * inv * g[t+512] + bb[t+512];
}

// ---------------------------------------------------------------------------
// Softmax over rows of length 512. one block per row, 256 threads x 2 elems
// ---------------------------------------------------------------------------
__global__ __launch_bounds__(256) void softmax_kernel(float* __restrict__ S, int causal)
{
    __shared__ float sd[256];
    long long row = blockIdx.x;
    int q = (int)(row & (Tt - 1));
    float* p = S + row * Tt;
    int t = threadIdx.x;
    float v0 = p[t], v1 = p[t + 256];
    if (causal) {
        if (t > q) v0 = -INFINITY;
        if (t + 256 > q) v1 = -INFINITY;
    }
    sd[t] = fmaxf(v0, v1);
    __syncthreads();
    for (int s = 128; s > 0; s >>= 1) { if (t < s) sd[t] = fmaxf(sd[t], sd[t+s]); __syncthreads(); }
    float rowmax = sd[0];
    __syncthreads();
    float e0 = expf(v0 - rowmax);
    float e1 = expf(v1 - rowmax);
    sd[t] = e0 + e1;
    __syncthreads();
    for (int s = 128; s > 0; s >>= 1) { if (t < s) sd[t] += sd[t+s]; __syncthreads(); }
    float inv = 1.0f / sd[0];
    p[t]       = e0 * inv;
    p[t + 256] = e1 * inv;
}

// ---------------------------------------------------------------------------
// Generic NT GEMM:  C[m,n] = alpha * sum_k A[m,k]*W[n,k]  (+bias)(gelu)(+res)
// BM=BN=64, BK=16, 256 threads, 4x4 per thread. Exact tiling assumed
// (M%64==0, N%64==0, K%16==0 -- true for every call in this model).
// Per-z offsets: b = z/Hn, h = z%Hn; expert index applied to W/bias if eidx.
// ---------------------------------------------------------------------------
__global__ __launch_bounds__(256) void gemm_nt_kernel(
    const float* __restrict__ A, int lda, long long bsA, long long hsA,
    const float* __restrict__ W, int ldw, long long bsW, long long hsW,
    long long esW, const int* __restrict__ eidx,
    const float* __restrict__ bias, int esBias,
    const float* __restrict__ res, int ldr, long long bsR,
    float* __restrict__ C, int ldc, long long bsC, long long hsC,
    int Kd, int Hn, float alpha, int act)
{
    int z = blockIdx.z;
    int b = z / Hn, h = z - b * Hn;
    A += (long long)b * bsA + (long long)h * hsA;
    long long woff = (long long)b * bsW + (long long)h * hsW;
    const float* biasp = bias;
    if (eidx) {
        int e = eidx[b];
        woff += (long long)e * esW;
        if (bias) biasp = bias + (long long)e * esBias;
    }
    W += woff;
    if (res) res += (long long)b * bsR;
    C += (long long)b * bsC + (long long)h * hsC;

    __shared__ float As[16][64];
    __shared__ float Ws[16][64];

    int tid = threadIdx.x;
    int tx = tid & 15, ty = tid >> 4;
    int m0 = blockIdx.y * 64, n0 = blockIdx.x * 64;

    int lr = tid >> 2;
    int lc = (tid & 3) << 2;

    float acc[4][4];
    #pragma unroll
    for (int i = 0; i < 4; i++)
        #pragma unroll
        for (int j = 0; j < 4; j++) acc[i][j] = 0.f;

    const float* Ap = A + (long long)(m0 + lr) * lda + lc;
    const float* Wp = W + (long long)(n0 + lr) * ldw + lc;

    for (int k0 = 0; k0 < Kd; k0 += 16) {
        float4 av = *(const float4*)(Ap + k0);
        float4 wv = *(const float4*)(Wp + k0);
        As[lc+0][lr] = av.x; As[lc+1][lr] = av.y; As[lc+2][lr] = av.z; As[lc+3][lr] = av.w;
        Ws[lc+0][lr] = wv.x; Ws[lc+1][lr] = wv.y; Ws[lc+2][lr] = wv.z; Ws[lc+3][lr] = wv.w;
        __syncthreads();
        #pragma unroll
        for (int kk = 0; kk < 16; kk++) {
            float4 a = *(const float4*)(&As[kk][ty << 2]);
            float4 w = *(const float4*)(&Ws[kk][tx << 2]);
            float ar[4] = {a.x, a.y, a.z, a.w};
            float wr[4] = {w.x, w.y, w.z, w.w};
            #pragma unroll
            for (int i = 0; i < 4; i++)
                #pragma unroll
                for (int j = 0; j < 4; j++)
                    acc[i][j] = fmaf(ar[i], wr[j], acc[i][j]);
        }
        __syncthreads();
    }

    #pragma unroll
    for (int i = 0; i < 4; i++) {
        int m = m0 + (ty << 2) + i;
        #pragma unroll
        for (int j = 0; j < 4; j++) {
            int n = n0 + (tx << 2) + j;
            float v = acc[i][j] * alpha;
            if (biasp) v += biasp[n];
            if (act)  v = gelu_exact(v);
            if (res)  v += res[(long long)m * ldr + n];
            C[(long long)m * ldc + n] = v;
        }
    }
}

// ---------------------------------------------------------------------------
// NN GEMM for P@V:  C[m,n] = sum_k A[m,k]*Bm[k,n], N=96 exactly.
// BM=64, BN=96, BK=16, 256 threads, 4x6 per thread.
// ---------------------------------------------------------------------------
__global__ __launch_bounds__(256) void gemm_nn_kernel(
    const float* __restrict__ A, int lda, long long bsA, long long hsA,
    const float* __restrict__ Bm, int ldb, long long bsB, long long hsB,
    float* __restrict__ C, int ldc, long long bsC, long long hsC,
    int Kd, int Hn)
{
    int z = blockIdx.z;
    int b = z / Hn, h = z - b * Hn;
    A  += (long long)b * bsA + (long long)h * hsA;
    Bm += (long long)b * bsB + (long long)h * hsB;
    C  += (long long)b * bsC + (long long)h * hsC;

    __shared__ float As[16][64];
    __shared__ float Bs[16][96];

    int tid = threadIdx.x;
    int tx = tid & 15, ty = tid >> 4;
    int m0 = blockIdx.y * 64;

    int lr = tid >> 2;
    int lc = (tid & 3) << 2;
    int br = tid >> 4;          // 0..15 (B tile row)
    int bc = (tid & 15) * 6;    // 0..90 (B tile col)

    float acc[4][6];
    #pragma unroll
    for (int i = 0; i < 4; i++)
        #pragma unroll
        for (int j = 0; j < 6; j++) acc[i][j] = 0.f;

    for (int k0 = 0; k0 < Kd; k0 += 16) {
        float4 av = *(const float4*)(A + (long long)(m0 + lr) * lda + k0 + lc);
        As[lc+0][lr] = av.x; As[lc+1][lr] = av.y; As[lc+2][lr] = av.z; As[lc+3][lr] = av.w;
        const float* bp = Bm + (long long)(k0 + br) * ldb + bc;
        #pragma unroll
        for (int j = 0; j < 6; j++) Bs[br][bc + j] = bp[j];
        __syncthreads();
        #pragma unroll
        for (int kk = 0; kk < 16; kk++) {
            float4 a = *(const float4*)(&As[kk][ty << 2]);
            float ar[4] = {a.x, a.y, a.z, a.w};
            float wr[6];
            #pragma unroll
            for (int j = 0; j < 6; j++) wr[j] = Bs[kk][tx * 6 + j];
            #pragma unroll
            for (int i = 0; i < 4; i++)
                #pragma unroll
                for (int j = 0; j < 6; j++)
                    acc[i][j] = fmaf(ar[i], wr[j], acc[i][j]);
        }
        __syncthreads();
    }

    #pragma unroll
    for (int i = 0; i < 4; i++) {
        int m = m0 + (ty << 2) + i;
        #pragma unroll
        for (int j = 0; j < 6; j++) {
            int n = tx * 6 + j;
            C[(long long)m * ldc + n] = acc[i][j];
        }
    }
}

// ---------------------------------------------------------------------------
// Orchestration
// ---------------------------------------------------------------------------
extern "C" void kernel_launch(void* const* d_in, const int* in_sizes, int n_in,
                              void* d_out, int out_size)
{
    const float* x        = (const float*)d_in[0];
    const float* rw1      = (const float*)d_in[1];
    const float* rb1      = (const float*)d_in[2];
    const float* rw2      = (const float*)d_in[3];
    const float* rb2      = (const float*)d_in[4];
    const float* nsg      = (const float*)d_in[5];
    const float* nsb      = (const float*)d_in[6];
    const float* ntg      = (const float*)d_in[7];
    const float* ntb      = (const float*)d_in[8];
    const float* nmg      = (const float*)d_in[9];
    const float* nmb      = (const float*)d_in[10];
    const float* sp_wqkv  = (const float*)d_in[11];
    const float* sp_bqkv  = (const float*)d_in[12];
    const float* sp_wo    = (const float*)d_in[13];
    const float* sp_bo    = (const float*)d_in[14];
    const float* tp_wq    = (const float*)d_in[15];
    const float* tp_bq    = (const float*)d_in[16];
    const float* tp_wk    = (const float*)d_in[17];
    const float* tp_bk    = (const float*)d_in[18];
    const float* tp_wv    = (const float*)d_in[19];
    const float* tp_bv    = (const float*)d_in[20];
    const float* tp_wo    = (const float*)d_in[21];
    const float* tp_bo    = (const float*)d_in[22];
    const float* c_wqkv   = (const float*)d_in[23];
    const float* c_bqkv   = (const float*)d_in[24];
    const float* c_wo     = (const float*)d_in[25];
    const float* c_bo     = (const float*)d_in[26];
    const float* mlp_w1   = (const float*)d_in[27];
    const float* mlp_b1   = (const float*)d_in[28];
    const float* mlp_w2   = (const float*)d_in[29];
    const float* mlp_b2   = (const float*)d_in[30];
    float* out = (float*)d_out;

    float *scores, *qkv, *qkv2, *xn, *xt, *attno, *spout, *tpout, *x1, *hid;
    int* idx;
    cudaGetSymbolAddress((void**)&scores, g_scores);
    cudaGetSymbolAddress((void**)&qkv,    g_qkv);
    cudaGetSymbolAddress((void**)&qkv2,   g_qkv2);
    cudaGetSymbolAddress((void**)&xn,     g_xn);
    cudaGetSymbolAddress((void**)&xt,     g_xt);
    cudaGetSymbolAddress((void**)&attno,  g_attno);
    cudaGetSymbolAddress((void**)&spout,  g_spout);
    cudaGetSymbolAddress((void**)&tpout,  g_tpout);
    cudaGetSymbolAddress((void**)&x1,     g_x1);
    cudaGetSymbolAddress((void**)&hid,    g_hid);
    cudaGetSymbolAddress((void**)&idx,    g_idx);

    const long long rowsBT  = (long long)Bz * Tt;        // 4096
    const long long sQKV    = (long long)Tt * D3;        // per-batch stride in qkv buffers
    const long long sD      = (long long)Tt * Dd;        // per-batch stride in [B,T,D] buffers
    const long long sScB    = (long long)Hh * Tt * Tt;   // per-batch stride in scores
    const long long sScH    = (long long)Tt * Tt;        // per-head stride in scores

    // ---- router ----
    router_kernel<<<Bz, Dd>>>(x, rw1, rb1, rw2, rb2, idx, idx + 8);

    // ---- spatial branch ----
    ln_kernel<<<(int)rowsBT, 256>>>(x, nsg, nsb, xn);

    // qkv = xn @ sp_wqkv[idx_s]^T + sp_bqkv[idx_s]   [B,512,2304]
    gemm_nt_kernel<<<dim3(D3/64, Tt/64, Bz), 256>>>(
        xn, Dd, sD, 0,
        sp_wqkv, Dd, 0, 0, (long long)D3 * Dd, idx,
        sp_bqkv, D3,
        nullptr, 0, 0,
        qkv, D3, sQKV, 0,
        Dd, 1, 1.0f, 0);

    // scores = SCALE * Q @ K^T   per (b,h)
    gemm_nt_kernel<<<dim3(Tt/64, Tt/64, Bz*Hh), 256>>>(
        qkv, D3, sQKV, HD,
        qkv + Dd, D3, sQKV, HD, 0, nullptr,
        nullptr, 0,
        nullptr, 0, 0,
        scores, Tt, sScB, sScH,
        HD, Hh, SCALE_V, 0);

    softmax_kernel<<<Bz*Hh*Tt, 256>>>(scores, 0);

    gemm_nn_kernel<<<dim3(1, Tt/64, Bz*Hh), 256>>>(
        scores, Tt, sScB, sScH,
        qkv + 2*Dd, D3, sQKV, HD,
        attno, Dd, sD, HD,
        Tt, Hh);

    // spatial_out = attno @ sp_wo[idx_s]^T + sp_bo[idx_s]
    gemm_nt_kernel<<<dim3(Dd/64, Tt/64, Bz), 256>>>(
        attno, Dd, sD, 0,
        sp_wo, Dd, 0, 0, (long long)Dd * Dd, idx,
        sp_bo, Dd,
        nullptr, 0, 0,
        spout, Dd, sD, 0,
        Dd, 1, 1.0f, 0);

    // ---- temporal branch ----
    ln_kernel<<<(int)rowsBT, 256>>>(x, ntg, ntb, xt);

    gemm_nt_kernel<<<dim3(Dd/64, Tt/64, Bz), 256>>>(
        xt, Dd, sD, 0, tp_wq, Dd, 0, 0, (long long)Dd*Dd, idx + 8,
        tp_bq, Dd, nullptr, 0, 0,
        qkv2, D3, sQKV, 0, Dd, 1, 1.0f, 0);
    gemm_nt_kernel<<<dim3(Dd/64, Tt/64, Bz), 256>>>(
        xt, Dd, sD, 0, tp_wk, Dd, 0, 0, (long long)Dd*Dd, idx + 8,
        tp_bk, Dd, nullptr, 0, 0,
        qkv2 + Dd, D3, sQKV, 0, Dd, 1, 1.0f, 0);
    gemm_nt_kernel<<<dim3(Dd/64, Tt/64, Bz), 256>>>(
        xt, Dd, sD, 0, tp_wv, Dd, 0, 0, (long long)Dd*Dd, idx + 8,
        tp_bv, Dd, nullptr, 0, 0,
        qkv2 + 2*Dd, D3, sQKV, 0, Dd, 1, 1.0f, 0);

    gemm_nt_kernel<<<dim3(Tt/64, Tt/64, Bz*Hh), 256>>>(
        qkv2, D3, sQKV, HD,
        qkv2 + Dd, D3, sQKV, HD, 0, nullptr,
        nullptr, 0,
        nullptr, 0, 0,
        scores, Tt, sScB, sScH,
        HD, Hh, SCALE_V, 0);

    softmax_kernel<<<Bz*Hh*Tt, 256>>>(scores, 1);   // causal

    gemm_nn_kernel<<<dim3(1, Tt/64, Bz*Hh), 256>>>(
        scores, Tt, sScB, sScH,
        qkv2 + 2*Dd, D3, sQKV, HD,
        attno, Dd, sD, HD,
        Tt, Hh);

    // temporal_out = xt + attno @ tp_wo[idx_t]^T + tp_bo[idx_t]
    gemm_nt_kernel<<<dim3(Dd/64, Tt/64, Bz), 256>>>(
        attno, Dd, sD, 0,
        tp_wo, Dd, 0, 0, (long long)Dd * Dd, idx + 8,
        tp_bo, Dd,
        xt, Dd, sD,
        tpout, Dd, sD, 0,
        Dd, 1, 1.0f, 0);

    // ---- cross attention ----
    // cq from spatial_out, ck/cv from temporal_out -> into qkv buffer cols
    gemm_nt_kernel<<<dim3(Dd/64, Tt/64, Bz), 256>>>(
        spout, Dd, sD, 0,
        c_wqkv, Dd, 0, 0, 0, nullptr,
        c_bqkv, 0, nullptr, 0, 0,
        qkv, D3, sQKV, 0, Dd, 1, 1.0f, 0);
    gemm_nt_kernel<<<dim3(Dd/64, Tt/64, Bz), 256>>>(
        tpout, Dd, sD, 0,
        c_wqkv + (long long)Dd * Dd, Dd, 0, 0, 0, nullptr,
        c_bqkv + Dd, 0, nullptr, 0, 0,
        qkv + Dd, D3, sQKV, 0, Dd, 1, 1.0f, 0);
    gemm_nt_kernel<<<dim3(Dd/64, Tt/64, Bz), 256>>>(
        tpout, Dd, sD, 0,
        c_wqkv + 2LL * Dd * Dd, Dd, 0, 0, 0, nullptr,
        c_bqkv + 2*Dd, 0, nullptr, 0, 0,
        qkv + 2*Dd, D3, sQKV, 0, Dd, 1, 1.0f, 0);

    gemm_nt_kernel<<<dim3(Tt/64, Tt/64, Bz*Hh), 256>>>(
        qkv, D3, sQKV, HD,
        qkv + Dd, D3, sQKV, HD, 0, nullptr,
        nullptr, 0,
        nullptr, 0, 0,
        scores, Tt, sScB, sScH,
        HD, Hh, SCALE_V, 0);

    softmax_kernel<<<Bz*Hh*Tt, 256>>>(scores, 0);

    gemm_nn_kernel<<<dim3(1, Tt/64, Bz*Hh), 256>>>(
        scores, Tt, sScB, sScH,
        qkv + 2*Dd, D3, sQKV, HD,
        attno, Dd, sD, HD,
        Tt, Hh);

    // x1 = x + attno @ cross_wo^T + cross_bo
    gemm_nt_kernel<<<dim3(Dd/64, Tt/64, Bz), 256>>>(
        attno, Dd, sD, 0,
        c_wo, Dd, 0, 0, 0, nullptr,
        c_bo, 0,
        x, Dd, sD,
        x1, Dd, sD, 0,
        Dd, 1, 1.0f, 0);

    // ---- MLP ----
    ln_kernel<<<(int)rowsBT, 256>>>(x1, nmg, nmb, xn);

    // hid = gelu(xn @ mlp_w1^T + mlp_b1)  : single big GEMM M=4096
    gemm_nt_kernel<<<dim3(D4/64, (int)(rowsBT/64), 1), 256>>>(
        xn, Dd, 0, 0,
        mlp_w1, Dd, 0, 0, 0, nullptr,
        mlp_b1, 0,
        nullptr, 0, 0,
        hid, D4, 0, 0,
        Dd, 1, 1.0f, 1);

    // out = x1 + hid @ mlp_w2^T + mlp_b2
    gemm_nt_kernel<<<dim3(Dd/64, (int)(rowsBT/64), 1), 256>>>(
        hid, D4, 0, 0,
        mlp_w2, D4, 0, 0, 0, nullptr,
        mlp_b2, 0,
        x1, Dd, 0,
        out, Dd, 0, 0,
        D4, 1, 1.0f, 0);
}

// round 3
// speedup vs baseline: 2.1627x; 2.1627x over previous
#include <cuda_runtime.h>
#include <cuda_bf16.h>
#include <math.h>
#include <stdint.h>

// ---------------------------------------------------------------------------
// Problem constants
// ---------------------------------------------------------------------------
#define Bz   8
#define Tt   512
#define Dd   768
#define Hh   8
#define HD   96
#define NEXP 4
#define RH   128
#define D3   (3*Dd)     // 2304
#define D4   (4*Dd)     // 3072
#define SCALE_V (0.10206207261596575f)  // 1/sqrt(96)
#define LN_EPS 1e-5f

// ---------------------------------------------------------------------------
// Scratch (static device arrays -- no allocation allowed)
// ---------------------------------------------------------------------------
__device__ float g_scores[(long long)Bz*Hh*Tt*Tt];   // 64*512*512
__device__ float g_qkv   [(long long)Bz*Tt*D3];
__device__ float g_qkv2  [(long long)Bz*Tt*D3];
__device__ float g_xn    [(long long)Bz*Tt*Dd];
__device__ float g_xt    [(long long)Bz*Tt*Dd];
__device__ float g_attno [(long long)Bz*Tt*Dd];
__device__ float g_spout [(long long)Bz*Tt*Dd];
__device__ float g_tpout [(long long)Bz*Tt*Dd];
__device__ float g_x1    [(long long)Bz*Tt*Dd];
__device__ float g_hid   [(long long)Bz*Tt*D4];
__device__ int   g_idx   [16];   // [0..7]=idx_s, [8..15]=idx_t

__device__ __forceinline__ float gelu_exact(float v) {
    return 0.5f * v * (1.0f + erff(v * 0.70710678118654752f));
}

__device__ __forceinline__ uint32_t f2tf(float x) {
    uint32_t r;
    asm("cvt.rna.tf32.f32 %0, %1;" : "=r"(r) : "f"(x));
    return r;
}

__device__ __forceinline__ void mma_tf32(float* c, const uint32_t* a, const uint32_t* b) {
    asm volatile(
        "mma.sync.aligned.m16n8k8.row.col.f32.tf32.tf32.f32 "
        "{%0,%1,%2,%3}, {%4,%5,%6,%7}, {%8,%9}, {%0,%1,%2,%3};"
        : "+f"(c[0]), "+f"(c[1]), "+f"(c[2]), "+f"(c[3])
        : "r"(a[0]), "r"(a[1]), "r"(a[2]), "r"(a[3]),
          "r"(b[0]), "r"(b[1]));
}

// ---------------------------------------------------------------------------
// Router
// ---------------------------------------------------------------------------
__global__ void router_kernel(const float* __restrict__ x,
                              const float* __restrict__ w1, const float* __restrict__ b1,
                              const float* __restrict__ w2, const float* __restrict__ b2,
                              int* __restrict__ idx_s, int* __restrict__ idx_t)
{
    __shared__ float xm[Dd];
    __shared__ float hbuf[RH];
    __shared__ float lg[8];
    int b = blockIdx.x;
    int d = threadIdx.x;
    const float* xb = x + (long long)b * Tt * Dd;
    float s = 0.f;
    for (int t = 0; t < Tt; t++) s += xb[(long long)t * Dd + d];
    xm[d] = s * (1.0f / Tt);
    __syncthreads();
    if (d < RH) {
        float a = b1[d];
        const float* wr = w1 + (long long)d * Dd;
        for (int k = 0; k < Dd; k++) a += xm[k] * wr[k];
        hbuf[d] = gelu_exact(a);
    }
    __syncthreads();
    if (d < 8) {
        float a = b2[d];
        const float* wr = w2 + d * RH;
        for (int k = 0; k < RH; k++) a += hbuf[k] * wr[k];
        lg[d] = a;
    }
    __syncthreads();
    if (d == 0) {
        int is = 0; for (int i = 1; i < NEXP; i++) if (lg[i] > lg[is]) is = i;
        int it = 0; for (int i = 1; i < NEXP; i++) if (lg[NEXP+i] > lg[NEXP+it]) it = i;
        idx_s[b] = is;
        idx_t[b] = it;
    }
}

// ---------------------------------------------------------------------------
// LayerNorm over last dim (768)
// ---------------------------------------------------------------------------
__global__ __launch_bounds__(256) void ln_kernel(const float* __restrict__ x,
                                                 const float* __restrict__ g,
                                                 const float* __restrict__ bb,
                                                 float* __restrict__ y)
{
    __shared__ float sd[256];
    long long row = blockIdx.x;
    int t = threadIdx.x;
    const float* xr = x + row * Dd;
    float a0 = xr[t], a1 = xr[t+256], a2 = xr[t+512];
    sd[t] = a0 + a1 + a2;
    __syncthreads();
    for (int s = 128; s > 0; s >>= 1) { if (t < s) sd[t] += sd[t+s]; __syncthreads(); }
    float mean = sd[0] * (1.0f / Dd);
    __syncthreads();
    float d0 = a0 - mean, d1 = a1 - mean, d2 = a2 - mean;
    sd[t] = d0*d0 + d1*d1 + d2*d2;
    __syncthreads();
    for (int s = 128; s > 0; s >>= 1) { if (t < s) sd[t] += sd[t+s]; __syncthreads(); }
    float inv = rsqrtf(sd[0] * (1.0f / Dd) + LN_EPS);
    float* yr = y + row * Dd;
    yr[t]     = d0 * inv * g[t]     + bb[t];
    yr[t+256] = d1 * inv * g[t+256] + bb[t+256];
    yr[t+512] = d2 * inv * g[t+512] + bb[t+512];
}

// ---------------------------------------------------------------------------
// Softmax over rows of length 512
// ---------------------------------------------------------------------------
__global__ __launch_bounds__(256) void softmax_kernel(float* __restrict__ S, int causal)
{
    __shared__ float sd[256];
    long long row = blockIdx.x;
    int q = (int)(row & (Tt - 1));
    float* p = S + row * Tt;
    int t = threadIdx.x;
    float v0 = p[t], v1 = p[t + 256];
    if (causal) {
        if (t > q) v0 = -INFINITY;
        if (t + 256 > q) v1 = -INFINITY;
    }
    sd[t] = fmaxf(v0, v1);
    __syncthreads();
    for (int s = 128; s > 0; s >>= 1) { if (t < s) sd[t] = fmaxf(sd[t], sd[t+s]); __syncthreads(); }
    float rowmax = sd[0];
    __syncthreads();
    float e0 = expf(v0 - rowmax);
    float e1 = expf(v1 - rowmax);
    sd[t] = e0 + e1;
    __syncthreads();
    for (int s = 128; s > 0; s >>= 1) { if (t < s) sd[t] += sd[t+s]; __syncthreads(); }
    float inv = 1.0f / sd[0];
    p[t]       = e0 * inv;
    p[t + 256] = e1 * inv;
}

// ---------------------------------------------------------------------------
// TF32 tensor-core NT GEMM: C[m,n] = alpha*sum_k A[m,k]*W[n,k] (+bias)(gelu)(+res)
// BM=128, BN=128, BK=16. 256 threads = 8 warps in 4(m) x 2(n); warp tile 32x64.
// M%128==0, N%128==0, K%16==0 for every call.
// ---------------------------------------------------------------------------
#define AS_LD 20    // 16 + 4 pad : (20*m + k) % 32 conflict-free for frag loads
#define BS_LD 136   // 128 + 8    : (8*k + n) % 32 conflict-free

__global__ __launch_bounds__(256, 2) void tgemm_nt_kernel(
    const float* __restrict__ A, int lda, long long bsA, long long hsA,
    const float* __restrict__ W, int ldw, long long bsW, long long hsW,
    long long esW, const int* __restrict__ eidx,
    const float* __restrict__ bias, int esBias,
    const float* __restrict__ res, int ldr, long long bsR,
    float* __restrict__ C, int ldc, long long bsC, long long hsC,
    int Kd, int Hn, float alpha, int act)
{
    int z = blockIdx.z;
    int b = z / Hn, h = z - b * Hn;
    A += (long long)b * bsA + (long long)h * hsA;
    long long woff = (long long)b * bsW + (long long)h * hsW;
    const float* biasp = bias;
    if (eidx) {
        int e = eidx[b];
        woff += (long long)e * esW;
        if (bias) biasp = bias + (long long)e * esBias;
    }
    W += woff;
    if (res) res += (long long)b * bsR;
    C += (long long)b * bsC + (long long)h * hsC;

    __shared__ uint32_t As[128 * AS_LD];
    __shared__ uint32_t Bs[16 * BS_LD];

    int tid  = threadIdx.x;
    int lane = tid & 31;
    int warp = tid >> 5;
    int wm = warp & 3, wn = warp >> 2;     // 4 x 2 warps
    int wmb = wm * 32, wnb = wn * 64;
    int g  = lane >> 2;
    int t4 = lane & 3;

    int m0 = blockIdx.y * 128, n0 = blockIdx.x * 128;

    int lr = tid >> 1;           // 0..127
    int lc = (tid & 1) * 8;      // 0 or 8

    float acc[2][8][4];
    #pragma unroll
    for (int i = 0; i < 2; i++)
        #pragma unroll
        for (int j = 0; j < 8; j++)
            #pragma unroll
            for (int q = 0; q < 4; q++) acc[i][j][q] = 0.f;

    const float* Ap = A + (long long)(m0 + lr) * lda + lc;
    const float* Wp = W + (long long)(n0 + lr) * ldw + lc;

    for (int k0 = 0; k0 < Kd; k0 += 16) {
        float4 av0 = *(const float4*)(Ap + k0);
        float4 av1 = *(const float4*)(Ap + k0 + 4);
        float4 wv0 = *(const float4*)(Wp + k0);
        float4 wv1 = *(const float4*)(Wp + k0 + 4);

        uint32_t* ar = &As[lr * AS_LD + lc];
        ar[0] = f2tf(av0.x); ar[1] = f2tf(av0.y); ar[2] = f2tf(av0.z); ar[3] = f2tf(av0.w);
        ar[4] = f2tf(av1.x); ar[5] = f2tf(av1.y); ar[6] = f2tf(av1.z); ar[7] = f2tf(av1.w);

        // transpose W tile into Bs[k][n]
        Bs[(lc+0) * BS_LD + lr] = f2tf(wv0.x);
        Bs[(lc+1) * BS_LD + lr] = f2tf(wv0.y);
        Bs[(lc+2) * BS_LD + lr] = f2tf(wv0.z);
        Bs[(lc+3) * BS_LD + lr] = f2tf(wv0.w);
        Bs[(lc+4) * BS_LD + lr] = f2tf(wv1.x);
        Bs[(lc+5) * BS_LD + lr] = f2tf(wv1.y);
        Bs[(lc+6) * BS_LD + lr] = f2tf(wv1.z);
        Bs[(lc+7) * BS_LD + lr] = f2tf(wv1.w);
        __syncthreads();

        #pragma unroll
        for (int ks = 0; ks < 2; ks++) {
            int kb = ks * 8;
            uint32_t afr[2][4];
            #pragma unroll
            for (int im = 0; im < 2; im++) {
                int mb = wmb + im * 16;
                afr[im][0] = As[(mb + g    ) * AS_LD + kb + t4];
                afr[im][1] = As[(mb + g + 8) * AS_LD + kb + t4];
                afr[im][2] = As[(mb + g    ) * AS_LD + kb + t4 + 4];
                afr[im][3] = As[(mb + g + 8) * AS_LD + kb + t4 + 4];
            }
            uint32_t bfr[8][2];
            #pragma unroll
            for (int jn = 0; jn < 8; jn++) {
                int nb = wnb + jn * 8;
                bfr[jn][0] = Bs[(kb + t4    ) * BS_LD + nb + g];
                bfr[jn][1] = Bs[(kb + t4 + 4) * BS_LD + nb + g];
            }
            #pragma unroll
            for (int im = 0; im < 2; im++)
                #pragma unroll
                for (int jn = 0; jn < 8; jn++)
                    mma_tf32(acc[im][jn], afr[im], bfr[jn]);
        }
        __syncthreads();
    }

    // epilogue
    #pragma unroll
    for (int im = 0; im < 2; im++) {
        int r0 = m0 + wmb + im * 16 + g;
        #pragma unroll
        for (int jn = 0; jn < 8; jn++) {
            int c = n0 + wnb + jn * 8 + 2 * t4;
            float bv0 = biasp ? biasp[c]     : 0.f;
            float bv1 = biasp ? biasp[c + 1] : 0.f;
            #pragma unroll
            for (int half = 0; half < 2; half++) {
                int r = r0 + half * 8;
                float v0 = acc[im][jn][half*2+0] * alpha + bv0;
                float v1 = acc[im][jn][half*2+1] * alpha + bv1;
                if (act) { v0 = gelu_exact(v0); v1 = gelu_exact(v1); }
                if (res) {
                    const float* rp = res + (long long)r * ldr + c;
                    v0 += rp[0]; v1 += rp[1];
                }
                float2 o = make_float2(v0, v1);
                *(float2*)(C + (long long)r * ldc + c) = o;
            }
        }
    }
}

// ---------------------------------------------------------------------------
// TF32 tensor-core NN GEMM for P@V: C[m,n]=sum_k A[m,k]*Bm[k,n], N=96 exactly.
// BM=128, BN=96, BK=16. 8 warps 4(m) x 2(n); warp tile 32x48 (2x6 frags).
// ---------------------------------------------------------------------------
#define BSN_LD 104  // 96 + 8

__global__ __launch_bounds__(256, 2) void tgemm_nn_kernel(
    const float* __restrict__ A, int lda, long long bsA, long long hsA,
    const float* __restrict__ Bm, int ldb, long long bsB, long long hsB,
    float* __restrict__ C, int ldc, long long bsC, long long hsC,
    int Kd, int Hn)
{
    int z = blockIdx.z;
    int b = z / Hn, h = z - b * Hn;
    A  += (long long)b * bsA + (long long)h * hsA;
    Bm += (long long)b * bsB + (long long)h * hsB;
    C  += (long long)b * bsC + (long long)h * hsC;

    __shared__ uint32_t As[128 * AS_LD];
    __shared__ uint32_t Bs[16 * BSN_LD];

    int tid  = threadIdx.x;
    int lane = tid & 31;
    int warp = tid >> 5;
    int wm = warp & 3, wn = warp >> 2;
    int wmb = wm * 32, wnb = wn * 48;
    int g  = lane >> 2;
    int t4 = lane & 3;

    int m0 = blockIdx.y * 128;

    int lr = tid >> 1;
    int lc = (tid & 1) * 8;
    int br = tid >> 4;           // 0..15
    int bc = (tid & 15) * 6;     // 0..90

    float acc[2][6][4];
    #pragma unroll
    for (int i = 0; i < 2; i++)
        #pragma unroll
        for (int j = 0; j < 6; j++)
            #pragma unroll
            for (int q = 0; q < 4; q++) acc[i][j][q] = 0.f;

    const float* Ap = A + (long long)(m0 + lr) * lda + lc;

    for (int k0 = 0; k0 < Kd; k0 += 16) {
        float4 av0 = *(const float4*)(Ap + k0);
        float4 av1 = *(const float4*)(Ap + k0 + 4);
        uint32_t* ar = &As[lr * AS_LD + lc];
        ar[0] = f2tf(av0.x); ar[1] = f2tf(av0.y); ar[2] = f2tf(av0.z); ar[3] = f2tf(av0.w);
        ar[4] = f2tf(av1.x); ar[5] = f2tf(av1.y); ar[6] = f2tf(av1.z); ar[7] = f2tf(av1.w);

        const float* bp = Bm + (long long)(k0 + br) * ldb + bc;
        #pragma unroll
        for (int j = 0; j < 6; j++)
            Bs[br * BSN_LD + bc + j] = f2tf(bp[j]);
        __syncthreads();

        #pragma unroll
        for (int ks = 0; ks < 2; ks++) {
            int kb = ks * 8;
            uint32_t afr[2][4];
            #pragma unroll
            for (int im = 0; im < 2; im++) {
                int mb = wmb + im * 16;
                afr[im][0] = As[(mb + g    ) * AS_LD + kb + t4];
                afr[im][1] = As[(mb + g + 8) * AS_LD + kb + t4];
                afr[im][2] = As[(mb + g    ) * AS_LD + kb + t4 + 4];
                afr[im][3] = As[(mb + g + 8) * AS_LD + kb + t4 + 4];
            }
            uint32_t bfr[6][2];
            #pragma unroll
            for (int jn = 0; jn < 6; jn++) {
                int nb = wnb + jn * 8;
                bfr[jn][0] = Bs[(kb + t4    ) * BSN_LD + nb + g];
                bfr[jn][1] = Bs[(kb + t4 + 4) * BSN_LD + nb + g];
            }
            #pragma unroll
            for (int im = 0; im < 2; im++)
                #pragma unroll
                for (int jn = 0; jn < 6; jn++)
                    mma_tf32(acc[im][jn], afr[im], bfr[jn]);
        }
        __syncthreads();
    }

    #pragma unroll
    for (int im = 0; im < 2; im++) {
        int r0 = m0 + wmb + im * 16 + g;
        #pragma unroll
        for (int jn = 0; jn < 6; jn++) {
            int c = wnb + jn * 8 + 2 * t4;
            #pragma unroll
            for (int half = 0; half < 2; half++) {
                int r = r0 + half * 8;
                float2 o = make_float2(acc[im][jn][half*2+0], acc[im][jn][half*2+1]);
                *(float2*)(C + (long long)r * ldc + c) = o;
            }
        }
    }
}

// ---------------------------------------------------------------------------
// Orchestration
// ---------------------------------------------------------------------------
extern "C" void kernel_launch(void* const* d_in, const int* in_sizes, int n_in,
                              void* d_out, int out_size)
{
    const float* x        = (const float*)d_in[0];
    const float* rw1      = (const float*)d_in[1];
    const float* rb1      = (const float*)d_in[2];
    const float* rw2      = (const float*)d_in[3];
    const float* rb2      = (const float*)d_in[4];
    const float* nsg      = (const float*)d_in[5];
    const float* nsb      = (const float*)d_in[6];
    const float* ntg      = (const float*)d_in[7];
    const float* ntb      = (const float*)d_in[8];
    const float* nmg      = (const float*)d_in[9];
    const float* nmb      = (const float*)d_in[10];
    const float* sp_wqkv  = (const float*)d_in[11];
    const float* sp_bqkv  = (const float*)d_in[12];
    const float* sp_wo    = (const float*)d_in[13];
    const float* sp_bo    = (const float*)d_in[14];
    const float* tp_wq    = (const float*)d_in[15];
    const float* tp_bq    = (const float*)d_in[16];
    const float* tp_wk    = (const float*)d_in[17];
    const float* tp_bk    = (const float*)d_in[18];
    const float* tp_wv    = (const float*)d_in[19];
    const float* tp_bv    = (const float*)d_in[20];
    const float* tp_wo    = (const float*)d_in[21];
    const float* tp_bo    = (const float*)d_in[22];
    const float* c_wqkv   = (const float*)d_in[23];
    const float* c_bqkv   = (const float*)d_in[24];
    const float* c_wo     = (const float*)d_in[25];
    const float* c_bo     = (const float*)d_in[26];
    const float* mlp_w1   = (const float*)d_in[27];
    const float* mlp_b1   = (const float*)d_in[28];
    const float* mlp_w2   = (const float*)d_in[29];
    const float* mlp_b2   = (const float*)d_in[30];
    float* out = (float*)d_out;

    float *scores, *qkv, *qkv2, *xn, *xt, *attno, *spout, *tpout, *x1, *hid;
    int* idx;
    cudaGetSymbolAddress((void**)&scores, g_scores);
    cudaGetSymbolAddress((void**)&qkv,    g_qkv);
    cudaGetSymbolAddress((void**)&qkv2,   g_qkv2);
    cudaGetSymbolAddress((void**)&xn,     g_xn);
    cudaGetSymbolAddress((void**)&xt,     g_xt);
    cudaGetSymbolAddress((void**)&attno,  g_attno);
    cudaGetSymbolAddress((void**)&spout,  g_spout);
    cudaGetSymbolAddress((void**)&tpout,  g_tpout);
    cudaGetSymbolAddress((void**)&x1,     g_x1);
    cudaGetSymbolAddress((void**)&hid,    g_hid);
    cudaGetSymbolAddress((void**)&idx,    g_idx);

    const long long rowsBT  = (long long)Bz * Tt;        // 4096
    const long long sQKV    = (long long)Tt * D3;
    const long long sD      = (long long)Tt * Dd;
    const long long sScB    = (long long)Hh * Tt * Tt;
    const long long sScH    = (long long)Tt * Tt;

    // ---- router ----
    router_kernel<<<Bz, Dd>>>(x, rw1, rb1, rw2, rb2, idx, idx + 8);

    // ---- spatial branch ----
    ln_kernel<<<(int)rowsBT, 256>>>(x, nsg, nsb, xn);

    tgemm_nt_kernel<<<dim3(D3/128, Tt/128, Bz), 256>>>(
        xn, Dd, sD, 0,
        sp_wqkv, Dd, 0, 0, (long long)D3 * Dd, idx,
        sp_bqkv, D3,
        nullptr, 0, 0,
        qkv, D3, sQKV, 0,
        Dd, 1, 1.0f, 0);

    tgemm_nt_kernel<<<dim3(Tt/128, Tt/128, Bz*Hh), 256>>>(
        qkv, D3, sQKV, HD,
        qkv + Dd, D3, sQKV, HD, 0, nullptr,
        nullptr, 0,
        nullptr, 0, 0,
        scores, Tt, sScB, sScH,
        HD, Hh, SCALE_V, 0);

    softmax_kernel<<<Bz*Hh*Tt, 256>>>(scores, 0);

    tgemm_nn_kernel<<<dim3(1, Tt/128, Bz*Hh), 256>>>(
        scores, Tt, sScB, sScH,
        qkv + 2*Dd, D3, sQKV, HD,
        attno, Dd, sD, HD,
        Tt, Hh);

    tgemm_nt_kernel<<<dim3(Dd/128, Tt/128, Bz), 256>>>(
        attno, Dd, sD, 0,
        sp_wo, Dd, 0, 0, (long long)Dd * Dd, idx,
        sp_bo, Dd,
        nullptr, 0, 0,
        spout, Dd, sD, 0,
        Dd, 1, 1.0f, 0);

    // ---- temporal branch ----
    ln_kernel<<<(int)rowsBT, 256>>>(x, ntg, ntb, xt);

    tgemm_nt_kernel<<<dim3(Dd/128, Tt/128, Bz), 256>>>(
        xt, Dd, sD, 0, tp_wq, Dd, 0, 0, (long long)Dd*Dd, idx + 8,
        tp_bq, Dd, nullptr, 0, 0,
        qkv2, D3, sQKV, 0, Dd, 1, 1.0f, 0);
    tgemm_nt_kernel<<<dim3(Dd/128, Tt/128, Bz), 256>>>(
        xt, Dd, sD, 0, tp_wk, Dd, 0, 0, (long long)Dd*Dd, idx + 8,
        tp_bk, Dd, nullptr, 0, 0,
        qkv2 + Dd, D3, sQKV, 0, Dd, 1, 1.0f, 0);
    tgemm_nt_kernel<<<dim3(Dd/128, Tt/128, Bz), 256>>>(
        xt, Dd, sD, 0, tp_wv, Dd, 0, 0, (long long)Dd*Dd, idx + 8,
        tp_bv, Dd, nullptr, 0, 0,
        qkv2 + 2*Dd, D3, sQKV, 0, Dd, 1, 1.0f, 0);

    tgemm_nt_kernel<<<dim3(Tt/128, Tt/128, Bz*Hh), 256>>>(
        qkv2, D3, sQKV, HD,
        qkv2 + Dd, D3, sQKV, HD, 0, nullptr,
        nullptr, 0,
        nullptr, 0, 0,
        scores, Tt, sScB, sScH,
        HD, Hh, SCALE_V, 0);

    softmax_kernel<<<Bz*Hh*Tt, 256>>>(scores, 1);   // causal

    tgemm_nn_kernel<<<dim3(1, Tt/128, Bz*Hh), 256>>>(
        scores, Tt, sScB, sScH,
        qkv2 + 2*Dd, D3, sQKV, HD,
        attno, Dd, sD, HD,
        Tt, Hh);

    tgemm_nt_kernel<<<dim3(Dd/128, Tt/128, Bz), 256>>>(
        attno, Dd, sD, 0,
        tp_wo, Dd, 0, 0, (long long)Dd * Dd, idx + 8,
        tp_bo, Dd,
        xt, Dd, sD,
        tpout, Dd, sD, 0,
        Dd, 1, 1.0f, 0);

    // ---- cross attention ----
    tgemm_nt_kernel<<<dim3(Dd/128, Tt/128, Bz), 256>>>(
        spout, Dd, sD, 0,
        c_wqkv, Dd, 0, 0, 0, nullptr,
        c_bqkv, 0, nullptr, 0, 0,
        qkv, D3, sQKV, 0, Dd, 1, 1.0f, 0);
    tgemm_nt_kernel<<<dim3(Dd/128, Tt/128, Bz), 256>>>(
        tpout, Dd, sD, 0,
        c_wqkv + (long long)Dd * Dd, Dd, 0, 0, 0, nullptr,
        c_bqkv + Dd, 0, nullptr, 0, 0,
        qkv + Dd, D3, sQKV, 0, Dd, 1, 1.0f, 0);
    tgemm_nt_kernel<<<dim3(Dd/128, Tt/128, Bz), 256>>>(
        tpout, Dd, sD, 0,
        c_wqkv + 2LL * Dd * Dd, Dd, 0, 0, 0, nullptr,
        c_bqkv + 2*Dd, 0, nullptr, 0, 0,
        qkv + 2*Dd, D3, sQKV, 0, Dd, 1, 1.0f, 0);

    tgemm_nt_kernel<<<dim3(Tt/128, Tt/128, Bz*Hh), 256>>>(
        qkv, D3, sQKV, HD,
        qkv + Dd, D3, sQKV, HD, 0, nullptr,
        nullptr, 0,
        nullptr, 0, 0,
        scores, Tt, sScB, sScH,
        HD, Hh, SCALE_V, 0);

    softmax_kernel<<<Bz*Hh*Tt, 256>>>(scores, 0);

    tgemm_nn_kernel<<<dim3(1, Tt/128, Bz*Hh), 256>>>(
        scores, Tt, sScB, sScH,
        qkv + 2*Dd, D3, sQKV, HD,
        attno, Dd, sD, HD,
        Tt, Hh);

    tgemm_nt_kernel<<<dim3(Dd/128, Tt/128, Bz), 256>>>(
        attno, Dd, sD, 0,
        c_wo, Dd, 0, 0, 0, nullptr,
        c_bo, 0,
        x, Dd, sD,
        x1, Dd, sD, 0,
        Dd, 1, 1.0f, 0);

    // ---- MLP ----
    ln_kernel<<<(int)rowsBT, 256>>>(x1, nmg, nmb, xn);

    tgemm_nt_kernel<<<dim3(D4/128, (int)(rowsBT/128), 1), 256>>>(
        xn, Dd, 0, 0,
        mlp_w1, Dd, 0, 0, 0, nullptr,
        mlp_b1, 0,
        nullptr, 0, 0,
        hid, D4, 0, 0,
        Dd, 1, 1.0f, 1);

    tgemm_nt_kernel<<<dim3(Dd/128, (int)(rowsBT/128), 1), 256>>>(
        hid, D4, 0, 0,
        mlp_w2, D4, 0, 0, 0, nullptr,
        mlp_b2, 0,
        x1, Dd, 0,
        out, Dd, 0, 0,
        D4, 1, 1.0f, 0);
}

// round 4
// speedup vs baseline: 2.5898x; 1.1975x over previous
#include <cuda_runtime.h>
#include <cuda_bf16.h>
#include <math.h>
#include <stdint.h>

// ---------------------------------------------------------------------------
// Problem constants
// ---------------------------------------------------------------------------
#define Bz   8
#define Tt   512
#define Dd   768
#define Hh   8
#define HD   96
#define NEXP 4
#define RH   128
#define D3   (3*Dd)     // 2304
#define D4   (4*Dd)     // 3072
#define SCALE_V (0.10206207261596575f)  // 1/sqrt(96)
#define LN_EPS 1e-5f

// ---------------------------------------------------------------------------
// Scratch (static device arrays -- no allocation allowed)
// ---------------------------------------------------------------------------
__device__ float g_scores[(long long)Bz*Hh*Tt*Tt];
__device__ float g_qkv   [(long long)Bz*Tt*D3];
__device__ float g_qkv2  [(long long)Bz*Tt*D3];
__device__ float g_xn    [(long long)Bz*Tt*Dd];
__device__ float g_xt    [(long long)Bz*Tt*Dd];
__device__ float g_attno [(long long)Bz*Tt*Dd];
__device__ float g_spout [(long long)Bz*Tt*Dd];
__device__ float g_tpout [(long long)Bz*Tt*Dd];
__device__ float g_x1    [(long long)Bz*Tt*Dd];
__device__ float g_hid   [(long long)Bz*Tt*D4];
__device__ int   g_idx   [16];

__device__ __forceinline__ float gelu_exact(float v) {
    return 0.5f * v * (1.0f + erff(v * 0.70710678118654752f));
}

__device__ __forceinline__ void mma_tf32(float* c, const uint32_t* a, const uint32_t* b) {
    asm volatile(
        "mma.sync.aligned.m16n8k8.row.col.f32.tf32.tf32.f32 "
        "{%0,%1,%2,%3}, {%4,%5,%6,%7}, {%8,%9}, {%0,%1,%2,%3};"
        : "+f"(c[0]), "+f"(c[1]), "+f"(c[2]), "+f"(c[3])
        : "r"(a[0]), "r"(a[1]), "r"(a[2]), "r"(a[3]),
          "r"(b[0]), "r"(b[1]));
}

#define CP_ASYNC_16(dst_u32, src_ptr) \
    asm volatile("cp.async.cg.shared.global [%0], [%1], 16;\n" :: "r"(dst_u32), "l"(src_ptr))
#define CP_COMMIT() asm volatile("cp.async.commit_group;\n")
#define CP_WAIT(N)  asm volatile("cp.async.wait_group %0;\n" :: "n"(N))

__device__ __forceinline__ uint32_t smem_u32(const void* p) {
    return (uint32_t)__cvta_generic_to_shared(p);
}

// ---------------------------------------------------------------------------
// Router
// ---------------------------------------------------------------------------
__global__ void router_kernel(const float* __restrict__ x,
                              const float* __restrict__ w1, const float* __restrict__ b1,
                              const float* __restrict__ w2, const float* __restrict__ b2,
                              int* __restrict__ idx_s, int* __restrict__ idx_t)
{
    __shared__ float xm[Dd];
    __shared__ float hbuf[RH];
    __shared__ float lg[8];
    int b = blockIdx.x;
    int d = threadIdx.x;
    const float* xb = x + (long long)b * Tt * Dd;
    float s = 0.f;
    for (int t = 0; t < Tt; t++) s += xb[(long long)t * Dd + d];
    xm[d] = s * (1.0f / Tt);
    __syncthreads();
    if (d < RH) {
        float a = b1[d];
        const float* wr = w1 + (long long)d * Dd;
        for (int k = 0; k < Dd; k++) a += xm[k] * wr[k];
        hbuf[d] = gelu_exact(a);
    }
    __syncthreads();
    if (d < 8) {
        float a = b2[d];
        const float* wr = w2 + d * RH;
        for (int k = 0; k < RH; k++) a += hbuf[k] * wr[k];
        lg[d] = a;
    }
    __syncthreads();
    if (d == 0) {
        int is = 0; for (int i = 1; i < NEXP; i++) if (lg[i] > lg[is]) is = i;
        int it = 0; for (int i = 1; i < NEXP; i++) if (lg[NEXP+i] > lg[NEXP+it]) it = i;
        idx_s[b] = is;
        idx_t[b] = it;
    }
}

// ---------------------------------------------------------------------------
// LayerNorm over last dim (768)
// ---------------------------------------------------------------------------
__global__ __launch_bounds__(256) void ln_kernel(const float* __restrict__ x,
                                                 const float* __restrict__ g,
                                                 const float* __restrict__ bb,
                                                 float* __restrict__ y)
{
    __shared__ float sd[256];
    long long row = blockIdx.x;
    int t = threadIdx.x;
    const float* xr = x + row * Dd;
    float a0 = xr[t], a1 = xr[t+256], a2 = xr[t+512];
    sd[t] = a0 + a1 + a2;
    __syncthreads();
    for (int s = 128; s > 0; s >>= 1) { if (t < s) sd[t] += sd[t+s]; __syncthreads(); }
    float mean = sd[0] * (1.0f / Dd);
    __syncthreads();
    float d0 = a0 - mean, d1 = a1 - mean, d2 = a2 - mean;
    sd[t] = d0*d0 + d1*d1 + d2*d2;
    __syncthreads();
    for (int s = 128; s > 0; s >>= 1) { if (t < s) sd[t] += sd[t+s]; __syncthreads(); }
    float inv = rsqrtf(sd[0] * (1.0f / Dd) + LN_EPS);
    float* yr = y + row * Dd;
    yr[t]     = d0 * inv * g[t]     + bb[t];
    yr[t+256] = d1 * inv * g[t+256] + bb[t+256];
    yr[t+512] = d2 * inv * g[t+512] + bb[t+512];
}

// ---------------------------------------------------------------------------
// Softmax over rows of length 512
// ---------------------------------------------------------------------------
__global__ __launch_bounds__(256) void softmax_kernel(float* __restrict__ S, int causal)
{
    __shared__ float sd[256];
    long long row = blockIdx.x;
    int q = (int)(row & (Tt - 1));
    float* p = S + row * Tt;
    int t = threadIdx.x;
    float v0 = p[t], v1 = p[t + 256];
    if (causal) {
        if (t > q) v0 = -INFINITY;
        if (t + 256 > q) v1 = -INFINITY;
    }
    sd[t] = fmaxf(v0, v1);
    __syncthreads();
    for (int s = 128; s > 0; s >>= 1) { if (t < s) sd[t] = fmaxf(sd[t], sd[t+s]); __syncthreads(); }
    float rowmax = sd[0];
    __syncthreads();
    float e0 = expf(v0 - rowmax);
    float e1 = expf(v1 - rowmax);
    sd[t] = e0 + e1;
    __syncthreads();
    for (int s = 128; s > 0; s >>= 1) { if (t < s) sd[t] += sd[t+s]; __syncthreads(); }
    float inv = 1.0f / sd[0];
    p[t]       = e0 * inv;
    p[t + 256] = e1 * inv;
}

// ---------------------------------------------------------------------------
// TF32 tensor-core NT GEMM with 2-stage cp.async pipeline.
// C[m,n] = alpha*sum_k A[m,k]*W[n,k] (+bias)(gelu)(+res)
// BM=128, BN=128, BK=16, 8 warps (4m x 2n), warp tile 32x64.
// Smem tiles stored in natural [row][k] layout (raw fp32 bits; tf32 MMA
// truncates mantissa in hardware).
// ---------------------------------------------------------------------------
#define TLD 20   // 16 + 4 pad floats: row starts 80B (16B aligned), frag loads conflict-free

__global__ __launch_bounds__(256, 2) void tgemm_nt_kernel(
    const float* __restrict__ A, int lda, long long bsA, long long hsA,
    const float* __restrict__ W, int ldw, long long bsW, long long hsW,
    long long esW, const int* __restrict__ eidx,
    const float* __restrict__ bias, int esBias,
    const float* __restrict__ res, int ldr, long long bsR,
    float* __restrict__ C, int ldc, long long bsC, long long hsC,
    int Kd, int Hn, float alpha, int act)
{
    int z = blockIdx.z;
    int b = z / Hn, h = z - b * Hn;
    A += (long long)b * bsA + (long long)h * hsA;
    long long woff = (long long)b * bsW + (long long)h * hsW;
    const float* biasp = bias;
    if (eidx) {
        int e = eidx[b];
        woff += (long long)e * esW;
        if (bias) biasp = bias + (long long)e * esBias;
    }
    W += woff;
    if (res) res += (long long)b * bsR;
    C += (long long)b * bsC + (long long)h * hsC;

    __shared__ uint32_t As[2][128 * TLD];
    __shared__ uint32_t Ws[2][128 * TLD];

    int tid  = threadIdx.x;
    int lane = tid & 31;
    int warp = tid >> 5;
    int wm = warp & 3, wn = warp >> 2;
    int wmb = wm * 32, wnb = wn * 64;
    int g  = lane >> 2;
    int t4 = lane & 3;

    int m0 = blockIdx.y * 128, n0 = blockIdx.x * 128;

    int lr = tid >> 1;           // 0..127
    int lc = (tid & 1) * 8;      // 0 or 8

    float acc[2][8][4];
    #pragma unroll
    for (int i = 0; i < 2; i++)
        #pragma unroll
        for (int j = 0; j < 8; j++)
            #pragma unroll
            for (int q = 0; q < 4; q++) acc[i][j][q] = 0.f;

    const float* Ap = A + (long long)(m0 + lr) * lda + lc;
    const float* Wp = W + (long long)(n0 + lr) * ldw + lc;

    uint32_t sA0 = smem_u32(&As[0][lr * TLD + lc]);
    uint32_t sA1 = smem_u32(&As[1][lr * TLD + lc]);
    uint32_t sW0 = smem_u32(&Ws[0][lr * TLD + lc]);
    uint32_t sW1 = smem_u32(&Ws[1][lr * TLD + lc]);

    int kTiles = Kd >> 4;

    // prologue: stage 0
    {
        CP_ASYNC_16(sA0,      Ap);
        CP_ASYNC_16(sA0 + 16, Ap + 4);
        CP_ASYNC_16(sW0,      Wp);
        CP_ASYNC_16(sW0 + 16, Wp + 4);
        CP_COMMIT();
    }

    for (int kt = 0; kt < kTiles; kt++) {
        int cur = kt & 1;
        if (kt + 1 < kTiles) {
            const float* Apn = Ap + (kt + 1) * 16;
            const float* Wpn = Wp + (kt + 1) * 16;
            uint32_t dA = cur ? sA0 : sA1;
            uint32_t dW = cur ? sW0 : sW1;
            CP_ASYNC_16(dA,      Apn);
            CP_ASYNC_16(dA + 16, Apn + 4);
            CP_ASYNC_16(dW,      Wpn);
            CP_ASYNC_16(dW + 16, Wpn + 4);
            CP_COMMIT();
            CP_WAIT(1);
        } else {
            CP_WAIT(0);
        }
        __syncthreads();

        const uint32_t* as = As[cur];
        const uint32_t* ws = Ws[cur];
        #pragma unroll
        for (int ks = 0; ks < 2; ks++) {
            int kb = ks * 8;
            uint32_t afr[2][4];
            #pragma unroll
            for (int im = 0; im < 2; im++) {
                int mb = wmb + im * 16;
                afr[im][0] = as[(mb + g    ) * TLD + kb + t4];
                afr[im][1] = as[(mb + g + 8) * TLD + kb + t4];
                afr[im][2] = as[(mb + g    ) * TLD + kb + t4 + 4];
                afr[im][3] = as[(mb + g + 8) * TLD + kb + t4 + 4];
            }
            uint32_t bfr[8][2];
            #pragma unroll
            for (int jn = 0; jn < 8; jn++) {
                int nb = wnb + jn * 8;
                bfr[jn][0] = ws[(nb + g) * TLD + kb + t4];
                bfr[jn][1] = ws[(nb + g) * TLD + kb + t4 + 4];
            }
            #pragma unroll
            for (int im = 0; im < 2; im++)
                #pragma unroll
                for (int jn = 0; jn < 8; jn++)
                    mma_tf32(acc[im][jn], afr[im], bfr[jn]);
        }
        __syncthreads();
    }

    // epilogue
    #pragma unroll
    for (int im = 0; im < 2; im++) {
        int r0 = m0 + wmb + im * 16 + g;
        #pragma unroll
        for (int jn = 0; jn < 8; jn++) {
            int c = n0 + wnb + jn * 8 + 2 * t4;
            float bv0 = biasp ? biasp[c]     : 0.f;
            float bv1 = biasp ? biasp[c + 1] : 0.f;
            #pragma unroll
            for (int half = 0; half < 2; half++) {
                int r = r0 + half * 8;
                float v0 = acc[im][jn][half*2+0] * alpha + bv0;
                float v1 = acc[im][jn][half*2+1] * alpha + bv1;
                if (act) { v0 = gelu_exact(v0); v1 = gelu_exact(v1); }
                if (res) {
                    const float* rp = res + (long long)r * ldr + c;
                    v0 += rp[0]; v1 += rp[1];
                }
                *(float2*)(C + (long long)r * ldc + c) = make_float2(v0, v1);
            }
        }
    }
}

// ---------------------------------------------------------------------------
// TF32 tensor-core NN GEMM for P@V with 2-stage cp.async pipeline.
// C[m,n]=sum_k A[m,k]*Bm[k,n], N=96 exactly. BM=128, BK=16.
// ---------------------------------------------------------------------------
#define BSN_LD 104  // 96 + 8 : rows 416B (16B aligned), frag loads conflict-free

__global__ __launch_bounds__(256, 2) void tgemm_nn_kernel(
    const float* __restrict__ A, int lda, long long bsA, long long hsA,
    const float* __restrict__ Bm, int ldb, long long bsB, long long hsB,
    float* __restrict__ C, int ldc, long long bsC, long long hsC,
    int Kd, int Hn)
{
    int z = blockIdx.z;
    int b = z / Hn, h = z - b * Hn;
    A  += (long long)b * bsA + (long long)h * hsA;
    Bm += (long long)b * bsB + (long long)h * hsB;
    C  += (long long)b * bsC + (long long)h * hsC;

    __shared__ uint32_t As[2][128 * TLD];
    __shared__ uint32_t Bs[2][16 * BSN_LD];

    int tid  = threadIdx.x;
    int lane = tid & 31;
    int warp = tid >> 5;
    int wm = warp & 3, wn = warp >> 2;
    int wmb = wm * 32, wnb = wn * 48;
    int g  = lane >> 2;
    int t4 = lane & 3;

    int m0 = blockIdx.y * 128;

    int lr = tid >> 1;
    int lc = (tid & 1) * 8;

    float acc[2][6][4];
    #pragma unroll
    for (int i = 0; i < 2; i++)
        #pragma unroll
        for (int j = 0; j < 6; j++)
            #pragma unroll
            for (int q = 0; q < 4; q++) acc[i][j][q] = 0.f;

    const float* Ap = A + (long long)(m0 + lr) * lda + lc;
    uint32_t sA0 = smem_u32(&As[0][lr * TLD + lc]);
    uint32_t sA1 = smem_u32(&As[1][lr * TLD + lc]);

    // B copy: 16 rows x 96 floats = 384 16B-segments
    int seg0 = tid;          // < 384
    int seg1 = tid + 256;    // < 384 for tid < 128
    int r0s = seg0 / 24, c0s = (seg0 % 24) * 4;
    int r1s = seg1 / 24, c1s = (seg1 % 24) * 4;
    uint32_t sB0a = smem_u32(&Bs[0][r0s * BSN_LD + c0s]);
    uint32_t sB0b = smem_u32(&Bs[0][r1s * BSN_LD + c1s]);
    uint32_t sB1a = smem_u32(&Bs[1][r0s * BSN_LD + c0s]);
    uint32_t sB1b = smem_u32(&Bs[1][r1s * BSN_LD + c1s]);

    int kTiles = Kd >> 4;

    {
        CP_ASYNC_16(sA0,      Ap);
        CP_ASYNC_16(sA0 + 16, Ap + 4);
        CP_ASYNC_16(sB0a, Bm + (long long)r0s * ldb + c0s);
        if (tid < 128) CP_ASYNC_16(sB0b, Bm + (long long)r1s * ldb + c1s);
        CP_COMMIT();
    }

    for (int kt = 0; kt < kTiles; kt++) {
        int cur = kt & 1;
        if (kt + 1 < kTiles) {
            int k0n = (kt + 1) * 16;
            const float* Apn = Ap + k0n;
            uint32_t dA = cur ? sA0 : sA1;
            CP_ASYNC_16(dA,      Apn);
            CP_ASYNC_16(dA + 16, Apn + 4);
            const float* Bp = Bm + (long long)k0n * ldb;
            CP_ASYNC_16(cur ? sB0a : sB1a, Bp + (long long)r0s * ldb + c0s);
            if (tid < 128) CP_ASYNC_16(cur ? sB0b : sB1b, Bp + (long long)r1s * ldb + c1s);
            CP_COMMIT();
            CP_WAIT(1);
        } else {
            CP_WAIT(0);
        }
        __syncthreads();

        const uint32_t* as = As[cur];
        const uint32_t* bs = Bs[cur];
        #pragma unroll
        for (int ks = 0; ks < 2; ks++) {
            int kb = ks * 8;
            uint32_t afr[2][4];
            #pragma unroll
            for (int im = 0; im < 2; im++) {
                int mb = wmb + im * 16;
                afr[im][0] = as[(mb + g    ) * TLD + kb + t4];
                afr[im][1] = as[(mb + g + 8) * TLD + kb + t4];
                afr[im][2] = as[(mb + g    ) * TLD + kb + t4 + 4];
                afr[im][3] = as[(mb + g + 8) * TLD + kb + t4 + 4];
            }
            uint32_t bfr[6][2];
            #pragma unroll
            for (int jn = 0; jn < 6; jn++) {
                int nb = wnb + jn * 8;
                bfr[jn][0] = bs[(kb + t4    ) * BSN_LD + nb + g];
                bfr[jn][1] = bs[(kb + t4 + 4) * BSN_LD + nb + g];
            }
            #pragma unroll
            for (int im = 0; im < 2; im++)
                #pragma unroll
                for (int jn = 0; jn < 6; jn++)
                    mma_tf32(acc[im][jn], afr[im], bfr[jn]);
        }
        __syncthreads();
    }

    #pragma unroll
    for (int im = 0; im < 2; im++) {
        int r0 = m0 + wmb + im * 16 + g;
        #pragma unroll
        for (int jn = 0; jn < 6; jn++) {
            int c = wnb + jn * 8 + 2 * t4;
            #pragma unroll
            for (int half = 0; half < 2; half++) {
                int r = r0 + half * 8;
                *(float2*)(C + (long long)r * ldc + c) =
                    make_float2(acc[im][jn][half*2+0], acc[im][jn][half*2+1]);
            }
        }
    }
}

// ---------------------------------------------------------------------------
// Orchestration
// ---------------------------------------------------------------------------
extern "C" void kernel_launch(void* const* d_in, const int* in_sizes, int n_in,
                              void* d_out, int out_size)
{
    const float* x        = (const float*)d_in[0];
    const float* rw1      = (const float*)d_in[1];
    const float* rb1      = (const float*)d_in[2];
    const float* rw2      = (const float*)d_in[3];
    const float* rb2      = (const float*)d_in[4];
    const float* nsg      = (const float*)d_in[5];
    const float* nsb      = (const float*)d_in[6];
    const float* ntg      = (const float*)d_in[7];
    const float* ntb      = (const float*)d_in[8];
    const float* nmg      = (const float*)d_in[9];
    const float* nmb      = (const float*)d_in[10];
    const float* sp_wqkv  = (const float*)d_in[11];
    const float* sp_bqkv  = (const float*)d_in[12];
    const float* sp_wo    = (const float*)d_in[13];
    const float* sp_bo    = (const float*)d_in[14];
    const float* tp_wq    = (const float*)d_in[15];
    const float* tp_bq    = (const float*)d_in[16];
    const float* tp_wk    = (const float*)d_in[17];
    const float* tp_bk    = (const float*)d_in[18];
    const float* tp_wv    = (const float*)d_in[19];
    const float* tp_bv    = (const float*)d_in[20];
    const float* tp_wo    = (const float*)d_in[21];
    const float* tp_bo    = (const float*)d_in[22];
    const float* c_wqkv   = (const float*)d_in[23];
    const float* c_bqkv   = (const float*)d_in[24];
    const float* c_wo     = (const float*)d_in[25];
    const float* c_bo     = (const float*)d_in[26];
    const float* mlp_w1   = (const float*)d_in[27];
    const float* mlp_b1   = (const float*)d_in[28];
    const float* mlp_w2   = (const float*)d_in[29];
    const float* mlp_b2   = (const float*)d_in[30];
    float* out = (float*)d_out;

    float *scores, *qkv, *qkv2, *xn, *xt, *attno, *spout, *tpout, *x1, *hid;
    int* idx;
    cudaGetSymbolAddress((void**)&scores, g_scores);
    cudaGetSymbolAddress((void**)&qkv,    g_qkv);
    cudaGetSymbolAddress((void**)&qkv2,   g_qkv2);
    cudaGetSymbolAddress((void**)&xn,     g_xn);
    cudaGetSymbolAddress((void**)&xt,     g_xt);
    cudaGetSymbolAddress((void**)&attno,  g_attno);
    cudaGetSymbolAddress((void**)&spout,  g_spout);
    cudaGetSymbolAddress((void**)&tpout,  g_tpout);
    cudaGetSymbolAddress((void**)&x1,     g_x1);
    cudaGetSymbolAddress((void**)&hid,    g_hid);
    cudaGetSymbolAddress((void**)&idx,    g_idx);

    const long long rowsBT  = (long long)Bz * Tt;
    const long long sQKV    = (long long)Tt * D3;
    const long long sD      = (long long)Tt * Dd;
    const long long sScB    = (long long)Hh * Tt * Tt;
    const long long sScH    = (long long)Tt * Tt;

    // ---- router ----
    router_kernel<<<Bz, Dd>>>(x, rw1, rb1, rw2, rb2, idx, idx + 8);

    // ---- spatial branch ----
    ln_kernel<<<(int)rowsBT, 256>>>(x, nsg, nsb, xn);

    tgemm_nt_kernel<<<dim3(D3/128, Tt/128, Bz), 256>>>(
        xn, Dd, sD, 0,
        sp_wqkv, Dd, 0, 0, (long long)D3 * Dd, idx,
        sp_bqkv, D3,
        nullptr, 0, 0,
        qkv, D3, sQKV, 0,
        Dd, 1, 1.0f, 0);

    tgemm_nt_kernel<<<dim3(Tt/128, Tt/128, Bz*Hh), 256>>>(
        qkv, D3, sQKV, HD,
        qkv + Dd, D3, sQKV, HD, 0, nullptr,
        nullptr, 0,
        nullptr, 0, 0,
        scores, Tt, sScB, sScH,
        HD, Hh, SCALE_V, 0);

    softmax_kernel<<<Bz*Hh*Tt, 256>>>(scores, 0);

    tgemm_nn_kernel<<<dim3(1, Tt/128, Bz*Hh), 256>>>(
        scores, Tt, sScB, sScH,
        qkv + 2*Dd, D3, sQKV, HD,
        attno, Dd, sD, HD,
        Tt, Hh);

    tgemm_nt_kernel<<<dim3(Dd/128, Tt/128, Bz), 256>>>(
        attno, Dd, sD, 0,
        sp_wo, Dd, 0, 0, (long long)Dd * Dd, idx,
        sp_bo, Dd,
        nullptr, 0, 0,
        spout, Dd, sD, 0,
        Dd, 1, 1.0f, 0);

    // ---- temporal branch ----
    ln_kernel<<<(int)rowsBT, 256>>>(x, ntg, ntb, xt);

    tgemm_nt_kernel<<<dim3(Dd/128, Tt/128, Bz), 256>>>(
        xt, Dd, sD, 0, tp_wq, Dd, 0, 0, (long long)Dd*Dd, idx + 8,
        tp_bq, Dd, nullptr, 0, 0,
        qkv2, D3, sQKV, 0, Dd, 1, 1.0f, 0);
    tgemm_nt_kernel<<<dim3(Dd/128, Tt/128, Bz), 256>>>(
        xt, Dd, sD, 0, tp_wk, Dd, 0, 0, (long long)Dd*Dd, idx + 8,
        tp_bk, Dd, nullptr, 0, 0,
        qkv2 + Dd, D3, sQKV, 0, Dd, 1, 1.0f, 0);
    tgemm_nt_kernel<<<dim3(Dd/128, Tt/128, Bz), 256>>>(
        xt, Dd, sD, 0, tp_wv, Dd, 0, 0, (long long)Dd*Dd, idx + 8,
        tp_bv, Dd, nullptr, 0, 0,
        qkv2 + 2*Dd, D3, sQKV, 0, Dd, 1, 1.0f, 0);

    tgemm_nt_kernel<<<dim3(Tt/128, Tt/128, Bz*Hh), 256>>>(
        qkv2, D3, sQKV, HD,
        qkv2 + Dd, D3, sQKV, HD, 0, nullptr,
        nullptr, 0,
        nullptr, 0, 0,
        scores, Tt, sScB, sScH,
        HD, Hh, SCALE_V, 0);

    softmax_kernel<<<Bz*Hh*Tt, 256>>>(scores, 1);   // causal

    tgemm_nn_kernel<<<dim3(1, Tt/128, Bz*Hh), 256>>>(
        scores, Tt, sScB, sScH,
        qkv2 + 2*Dd, D3, sQKV, HD,
        attno, Dd, sD, HD,
        Tt, Hh);

    tgemm_nt_kernel<<<dim3(Dd/128, Tt/128, Bz), 256>>>(
        attno, Dd, sD, 0,
        tp_wo, Dd, 0, 0, (long long)Dd * Dd, idx + 8,
        tp_bo, Dd,
        xt, Dd, sD,
        tpout, Dd, sD, 0,
        Dd, 1, 1.0f, 0);

    // ---- cross attention ----
    tgemm_nt_kernel<<<dim3(Dd/128, Tt/128, Bz), 256>>>(
        spout, Dd, sD, 0,
        c_wqkv, Dd, 0, 0, 0, nullptr,
        c_bqkv, 0, nullptr, 0, 0,
        qkv, D3, sQKV, 0, Dd, 1, 1.0f, 0);
    tgemm_nt_kernel<<<dim3(Dd/128, Tt/128, Bz), 256>>>(
        tpout, Dd, sD, 0,
        c_wqkv + (long long)Dd * Dd, Dd, 0, 0, 0, nullptr,
        c_bqkv + Dd, 0, nullptr, 0, 0,
        qkv + Dd, D3, sQKV, 0, Dd, 1, 1.0f, 0);
    tgemm_nt_kernel<<<dim3(Dd/128, Tt/128, Bz), 256>>>(
        tpout, Dd, sD, 0,
        c_wqkv + 2LL * Dd * Dd, Dd, 0, 0, 0, nullptr,
        c_bqkv + 2*Dd, 0, nullptr, 0, 0,
        qkv + 2*Dd, D3, sQKV, 0, Dd, 1, 1.0f, 0);

    tgemm_nt_kernel<<<dim3(Tt/128, Tt/128, Bz*Hh), 256>>>(
        qkv, D3, sQKV, HD,
        qkv + Dd, D3, sQKV, HD, 0, nullptr,
        nullptr, 0,
        nullptr, 0, 0,
        scores, Tt, sScB, sScH,
        HD, Hh, SCALE_V, 0);

    softmax_kernel<<<Bz*Hh*Tt, 256>>>(scores, 0);

    tgemm_nn_kernel<<<dim3(1, Tt/128, Bz*Hh), 256>>>(
        scores, Tt, sScB, sScH,
        qkv + 2*Dd, D3, sQKV, HD,
        attno, Dd, sD, HD,
        Tt, Hh);

    tgemm_nt_kernel<<<dim3(Dd/128, Tt/128, Bz), 256>>>(
        attno, Dd, sD, 0,
        c_wo, Dd, 0, 0, 0, nullptr,
        c_bo, 0,
        x, Dd, sD,
        x1, Dd, sD, 0,
        Dd, 1, 1.0f, 0);

    // ---- MLP ----
    ln_kernel<<<(int)rowsBT, 256>>>(x1, nmg, nmb, xn);

    tgemm_nt_kernel<<<dim3(D4/128, (int)(rowsBT/128), 1), 256>>>(
        xn, Dd, 0, 0,
        mlp_w1, Dd, 0, 0, 0, nullptr,
        mlp_b1, 0,
        nullptr, 0, 0,
        hid, D4, 0, 0,
        Dd, 1, 1.0f, 1);

    tgemm_nt_kernel<<<dim3(Dd/128, (int)(rowsBT/128), 1), 256>>>(
        hid, D4, 0, 0,
        mlp_w2, D4, 0, 0, 0, nullptr,
        mlp_b2, 0,
        x1, Dd, 0,
        out, Dd, 0, 0,
        D4, 1, 1.0f, 0);
}

// round 5
// speedup vs baseline: 2.6320x; 1.0163x over previous
#include <cuda_runtime.h>
#include <cuda_bf16.h>
#include <math.h>
#include <stdint.h>

// ---------------------------------------------------------------------------
// Problem constants
// ---------------------------------------------------------------------------
#define Bz   8
#define Tt   512
#define Dd   768
#define Hh   8
#define HD   96
#define NEXP 4
#define RH   128
#define D3   (3*Dd)     // 2304
#define D4   (4*Dd)     // 3072
#define SCALE_V (0.10206207261596575f)  // 1/sqrt(96)
#define LN_EPS 1e-5f

// ---------------------------------------------------------------------------
// Scratch (static device arrays -- no allocation allowed)
// ---------------------------------------------------------------------------
__device__ float g_scores[(long long)Bz*Hh*Tt*Tt];
__device__ float g_qkv   [(long long)Bz*Tt*D3];
__device__ float g_qkv2  [(long long)Bz*Tt*D3];
__device__ float g_xn    [(long long)Bz*Tt*Dd];
__device__ float g_xt    [(long long)Bz*Tt*Dd];
__device__ float g_attno [(long long)Bz*Tt*Dd];
__device__ float g_spout [(long long)Bz*Tt*Dd];
__device__ float g_tpout [(long long)Bz*Tt*Dd];
__device__ float g_x1    [(long long)Bz*Tt*Dd];
__device__ float g_hid   [(long long)Bz*Tt*D4];
__device__ int   g_idx   [16];

__device__ __forceinline__ float gelu_exact(float v) {
    return 0.5f * v * (1.0f + erff(v * 0.70710678118654752f));
}

// round-to-nearest tf32 (so subsequent RZ truncation in MMA is exact)
__device__ __forceinline__ float tf32r(float v) {
    uint32_t u = __float_as_uint(v);
    u = (u + 0x1000u) & 0xFFFFE000u;
    return __uint_as_float(u);
}

__device__ __forceinline__ void mma_tf32(float* c, const uint32_t* a, const uint32_t* b) {
    asm volatile(
        "mma.sync.aligned.m16n8k8.row.col.f32.tf32.tf32.f32 "
        "{%0,%1,%2,%3}, {%4,%5,%6,%7}, {%8,%9}, {%0,%1,%2,%3};"
        : "+f"(c[0]), "+f"(c[1]), "+f"(c[2]), "+f"(c[3])
        : "r"(a[0]), "r"(a[1]), "r"(a[2]), "r"(a[3]),
          "r"(b[0]), "r"(b[1]));
}

#define CP_ASYNC_16(dst_u32, src_ptr) \
    asm volatile("cp.async.cg.shared.global [%0], [%1], 16;\n" :: "r"(dst_u32), "l"(src_ptr))
#define CP_COMMIT() asm volatile("cp.async.commit_group;\n")
#define CP_WAIT(N)  asm volatile("cp.async.wait_group %0;\n" :: "n"(N))

__device__ __forceinline__ uint32_t smem_u32(const void* p) {
    return (uint32_t)__cvta_generic_to_shared(p);
}

#define STAGES 4

// ---------------------------------------------------------------------------
// Router
// ---------------------------------------------------------------------------
__global__ void router_kernel(const float* __restrict__ x,
                              const float* __restrict__ w1, const float* __restrict__ b1,
                              const float* __restrict__ w2, const float* __restrict__ b2,
                              int* __restrict__ idx_s, int* __restrict__ idx_t)
{
    __shared__ float xm[Dd];
    __shared__ float hbuf[RH];
    __shared__ float lg[8];
    int b = blockIdx.x;
    int d = threadIdx.x;
    const float* xb = x + (long long)b * Tt * Dd;
    float s = 0.f;
    for (int t = 0; t < Tt; t++) s += xb[(long long)t * Dd + d];
    xm[d] = s * (1.0f / Tt);
    __syncthreads();
    if (d < RH) {
        float a = b1[d];
        const float* wr = w1 + (long long)d * Dd;
        for (int k = 0; k < Dd; k++) a += xm[k] * wr[k];
        hbuf[d] = gelu_exact(a);
    }
    __syncthreads();
    if (d < 8) {
        float a = b2[d];
        const float* wr = w2 + d * RH;
        for (int k = 0; k < RH; k++) a += hbuf[k] * wr[k];
        lg[d] = a;
    }
    __syncthreads();
    if (d == 0) {
        int is = 0; for (int i = 1; i < NEXP; i++) if (lg[i] > lg[is]) is = i;
        int it = 0; for (int i = 1; i < NEXP; i++) if (lg[NEXP+i] > lg[NEXP+it]) it = i;
        idx_s[b] = is;
        idx_t[b] = it;
    }
}

// ---------------------------------------------------------------------------
// LayerNorm over last dim (768); outputs rounded to tf32 (GEMM inputs only)
// ---------------------------------------------------------------------------
__global__ __launch_bounds__(256) void ln_kernel(const float* __restrict__ x,
                                                 const float* __restrict__ g,
                                                 const float* __restrict__ bb,
                                                 float* __restrict__ y)
{
    __shared__ float sd[256];
    long long row = blockIdx.x;
    int t = threadIdx.x;
    const float* xr = x + row * Dd;
    float a0 = xr[t], a1 = xr[t+256], a2 = xr[t+512];
    sd[t] = a0 + a1 + a2;
    __syncthreads();
    for (int s = 128; s > 0; s >>= 1) { if (t < s) sd[t] += sd[t+s]; __syncthreads(); }
    float mean = sd[0] * (1.0f / Dd);
    __syncthreads();
    float d0 = a0 - mean, d1 = a1 - mean, d2 = a2 - mean;
    sd[t] = d0*d0 + d1*d1 + d2*d2;
    __syncthreads();
    for (int s = 128; s > 0; s >>= 1) { if (t < s) sd[t] += sd[t+s]; __syncthreads(); }
    float inv = rsqrtf(sd[0] * (1.0f / Dd) + LN_EPS);
    float* yr = y + row * Dd;
    yr[t]     = tf32r(d0 * inv * g[t]     + bb[t]);
    yr[t+256] = tf32r(d1 * inv * g[t+256] + bb[t+256]);
    yr[t+512] = tf32r(d2 * inv * g[t+512] + bb[t+512]);
}

// ---------------------------------------------------------------------------
// Softmax over rows of length 512; outputs rounded to tf32
// ---------------------------------------------------------------------------
__global__ __launch_bounds__(256) void softmax_kernel(float* __restrict__ S, int causal)
{
    __shared__ float sd[256];
    long long row = blockIdx.x;
    int q = (int)(row & (Tt - 1));
    float* p = S + row * Tt;
    int t = threadIdx.x;
    float v0 = p[t], v1 = p[t + 256];
    if (causal) {
        if (t > q) v0 = -INFINITY;
        if (t + 256 > q) v1 = -INFINITY;
    }
    sd[t] = fmaxf(v0, v1);
    __syncthreads();
    for (int s = 128; s > 0; s >>= 1) { if (t < s) sd[t] = fmaxf(sd[t], sd[t+s]); __syncthreads(); }
    float rowmax = sd[0];
    __syncthreads();
    float e0 = expf(v0 - rowmax);
    float e1 = expf(v1 - rowmax);
    sd[t] = e0 + e1;
    __syncthreads();
    for (int s = 128; s > 0; s >>= 1) { if (t < s) sd[t] += sd[t+s]; __syncthreads(); }
    float inv = 1.0f / sd[0];
    p[t]       = tf32r(e0 * inv);
    p[t + 256] = tf32r(e1 * inv);
}

// ---------------------------------------------------------------------------
// TF32 tensor-core NT GEMM, 4-stage cp.async pipeline, one barrier per tile.
// C[m,n] = alpha*sum_k A[m,k]*W[n,k] (+bias)(gelu)(+res)(round)
// BM=128, BN=128, BK=16, 8 warps (4m x 2n), warp tile 32x64.
// ---------------------------------------------------------------------------
#define TLD 20              // 16 + 4 pad floats
#define SSZ (128 * TLD)     // u32 per stage per operand
#define SSZB (SSZ * 4)      // bytes
#define NT_SMEM (2 * STAGES * SSZB)   // 81920 B

__global__ __launch_bounds__(256, 2) void tgemm_nt_kernel(
    const float* __restrict__ A, int lda, long long bsA, long long hsA,
    const float* __restrict__ W, int ldw, long long bsW, long long hsW,
    long long esW, const int* __restrict__ eidx,
    const float* __restrict__ bias, int esBias,
    const float* __restrict__ res, int ldr, long long bsR,
    float* __restrict__ C, int ldc, long long bsC, long long hsC,
    int Kd, int Hn, float alpha, int act, int rnd)
{
    extern __shared__ uint32_t dynsm[];
    uint32_t* Asm = dynsm;                    // STAGES * SSZ
    uint32_t* Wsm = dynsm + STAGES * SSZ;

    int z = blockIdx.z;
    int b = z / Hn, h = z - b * Hn;
    A += (long long)b * bsA + (long long)h * hsA;
    long long woff = (long long)b * bsW + (long long)h * hsW;
    const float* biasp = bias;
    if (eidx) {
        int e = eidx[b];
        woff += (long long)e * esW;
        if (bias) biasp = bias + (long long)e * esBias;
    }
    W += woff;
    if (res) res += (long long)b * bsR;
    C += (long long)b * bsC + (long long)h * hsC;

    int tid  = threadIdx.x;
    int lane = tid & 31;
    int warp = tid >> 5;
    int wm = warp & 3, wn = warp >> 2;
    int wmb = wm * 32, wnb = wn * 64;
    int g  = lane >> 2;
    int t4 = lane & 3;

    int m0 = blockIdx.y * 128, n0 = blockIdx.x * 128;

    int lr = tid >> 1;           // 0..127
    int lc = (tid & 1) * 8;      // 0 or 8

    float acc[2][8][4];
    #pragma unroll
    for (int i = 0; i < 2; i++)
        #pragma unroll
        for (int j = 0; j < 8; j++)
            #pragma unroll
            for (int q = 0; q < 4; q++) acc[i][j][q] = 0.f;

    const float* Ap = A + (long long)(m0 + lr) * lda + lc;
    const float* Wp = W + (long long)(n0 + lr) * ldw + lc;

    uint32_t offT = (uint32_t)((lr * TLD + lc) * 4);
    uint32_t sAb = smem_u32(Asm) + offT;
    uint32_t sWb = smem_u32(Wsm) + offT;

    int kTiles = Kd >> 4;

    // prologue: fill stages 0..STAGES-2
    #pragma unroll
    for (int s = 0; s < STAGES - 1; s++) {
        if (s < kTiles) {
            const float* Apn = Ap + s * 16;
            const float* Wpn = Wp + s * 16;
            uint32_t dA = sAb + s * SSZB;
            uint32_t dW = sWb + s * SSZB;
            CP_ASYNC_16(dA,      Apn);
            CP_ASYNC_16(dA + 16, Apn + 4);
            CP_ASYNC_16(dW,      Wpn);
            CP_ASYNC_16(dW + 16, Wpn + 4);
        }
        CP_COMMIT();
    }

    for (int kt = 0; kt < kTiles; kt++) {
        CP_WAIT(STAGES - 2);
        __syncthreads();

        // prefetch tile kt+STAGES-1 into stage (kt+STAGES-1)%STAGES
        int pf = kt + STAGES - 1;
        if (pf < kTiles) {
            int ps = pf & (STAGES - 1);
            const float* Apn = Ap + pf * 16;
            const float* Wpn = Wp + pf * 16;
            uint32_t dA = sAb + ps * SSZB;
            uint32_t dW = sWb + ps * SSZB;
            CP_ASYNC_16(dA,      Apn);
            CP_ASYNC_16(dA + 16, Apn + 4);
            CP_ASYNC_16(dW,      Wpn);
            CP_ASYNC_16(dW + 16, Wpn + 4);
        }
        CP_COMMIT();

        const uint32_t* as = Asm + (kt & (STAGES - 1)) * SSZ;
        const uint32_t* ws = Wsm + (kt & (STAGES - 1)) * SSZ;
        #pragma unroll
        for (int ks = 0; ks < 2; ks++) {
            int kb = ks * 8;
            uint32_t afr[2][4];
            #pragma unroll
            for (int im = 0; im < 2; im++) {
                int mb = wmb + im * 16;
                afr[im][0] = as[(mb + g    ) * TLD + kb + t4];
                afr[im][1] = as[(mb + g + 8) * TLD + kb + t4];
                afr[im][2] = as[(mb + g    ) * TLD + kb + t4 + 4];
                afr[im][3] = as[(mb + g + 8) * TLD + kb + t4 + 4];
            }
            uint32_t bfr[8][2];
            #pragma unroll
            for (int jn = 0; jn < 8; jn++) {
                int nb = wnb + jn * 8;
                bfr[jn][0] = ws[(nb + g) * TLD + kb + t4];
                bfr[jn][1] = ws[(nb + g) * TLD + kb + t4 + 4];
            }
            #pragma unroll
            for (int im = 0; im < 2; im++)
                #pragma unroll
                for (int jn = 0; jn < 8; jn++)
                    mma_tf32(acc[im][jn], afr[im], bfr[jn]);
        }
    }

    // epilogue
    #pragma unroll
    for (int im = 0; im < 2; im++) {
        int r0 = m0 + wmb + im * 16 + g;
        #pragma unroll
        for (int jn = 0; jn < 8; jn++) {
            int c = n0 + wnb + jn * 8 + 2 * t4;
            float bv0 = biasp ? biasp[c]     : 0.f;
            float bv1 = biasp ? biasp[c + 1] : 0.f;
            #pragma unroll
            for (int half = 0; half < 2; half++) {
                int r = r0 + half * 8;
                float v0 = acc[im][jn][half*2+0] * alpha + bv0;
                float v1 = acc[im][jn][half*2+1] * alpha + bv1;
                if (act) { v0 = gelu_exact(v0); v1 = gelu_exact(v1); }
                if (res) {
                    const float* rp = res + (long long)r * ldr + c;
                    v0 += rp[0]; v1 += rp[1];
                }
                if (rnd) { v0 = tf32r(v0); v1 = tf32r(v1); }
                *(float2*)(C + (long long)r * ldc + c) = make_float2(v0, v1);
            }
        }
    }
}

// ---------------------------------------------------------------------------
// TF32 tensor-core NN GEMM for P@V, 4-stage pipeline. N=96. BM=128, BK=16.
// Output rounded to tf32 (always a GEMM input downstream).
// ---------------------------------------------------------------------------
#define BSN_LD 104                 // 96 + 8
#define SSZB_B (16 * BSN_LD * 4)   // bytes per B stage (6656)
#define SSZ_B  (16 * BSN_LD)
#define NN_SMEM (STAGES * SSZB + STAGES * SSZB_B)   // 40960 + 26624 = 67584

__global__ __launch_bounds__(256, 2) void tgemm_nn_kernel(
    const float* __restrict__ A, int lda, long long bsA, long long hsA,
    const float* __restrict__ Bm, int ldb, long long bsB, long long hsB,
    float* __restrict__ C, int ldc, long long bsC, long long hsC,
    int Kd, int Hn)
{
    extern __shared__ uint32_t dynsm[];
    uint32_t* Asm = dynsm;                    // STAGES * SSZ
    uint32_t* Bsm = dynsm + STAGES * SSZ;

    int z = blockIdx.z;
    int b = z / Hn, h = z - b * Hn;
    A  += (long long)b * bsA + (long long)h * hsA;
    Bm += (long long)b * bsB + (long long)h * hsB;
    C  += (long long)b * bsC + (long long)h * hsC;

    int tid  = threadIdx.x;
    int lane = tid & 31;
    int warp = tid >> 5;
    int wm = warp & 3, wn = warp >> 2;
    int wmb = wm * 32, wnb = wn * 48;
    int g  = lane >> 2;
    int t4 = lane & 3;

    int m0 = blockIdx.y * 128;

    int lr = tid >> 1;
    int lc = (tid & 1) * 8;

    float acc[2][6][4];
    #pragma unroll
    for (int i = 0; i < 2; i++)
        #pragma unroll
        for (int j = 0; j < 6; j++)
            #pragma unroll
            for (int q = 0; q < 4; q++) acc[i][j][q] = 0.f;

    const float* Ap = A + (long long)(m0 + lr) * lda + lc;
    uint32_t offT = (uint32_t)((lr * TLD + lc) * 4);
    uint32_t sAb = smem_u32(Asm) + offT;

    // B copy: 16 rows x 96 floats = 384 16B-segments; 256 threads do 1, first 128 do 2
    int seg0 = tid;
    int seg1 = tid + 256;
    int r0s = seg0 / 24, c0s = (seg0 % 24) * 4;
    int r1s = seg1 / 24, c1s = (seg1 % 24) * 4;
    uint32_t sB0 = smem_u32(Bsm) + (uint32_t)((r0s * BSN_LD + c0s) * 4);
    uint32_t sB1 = smem_u32(Bsm) + (uint32_t)((r1s * BSN_LD + c1s) * 4);

    int kTiles = Kd >> 4;

    #pragma unroll
    for (int s = 0; s < STAGES - 1; s++) {
        if (s < kTiles) {
            const float* Apn = Ap + s * 16;
            uint32_t dA = sAb + s * SSZB;
            CP_ASYNC_16(dA,      Apn);
            CP_ASYNC_16(dA + 16, Apn + 4);
            const float* Bp = Bm + (long long)(s * 16) * ldb;
            CP_ASYNC_16(sB0 + s * SSZB_B, Bp + (long long)r0s * ldb + c0s);
            if (tid < 128) CP_ASYNC_16(sB1 + s * SSZB_B, Bp + (long long)r1s * ldb + c1s);
        }
        CP_COMMIT();
    }

    for (int kt = 0; kt < kTiles; kt++) {
        CP_WAIT(STAGES - 2);
        __syncthreads();

        int pf = kt + STAGES - 1;
        if (pf < kTiles) {
            int ps = pf & (STAGES - 1);
            const float* Apn = Ap + pf * 16;
            uint32_t dA = sAb + ps * SSZB;
            CP_ASYNC_16(dA,      Apn);
            CP_ASYNC_16(dA + 16, Apn + 4);
            const float* Bp = Bm + (long long)(pf * 16) * ldb;
            CP_ASYNC_16(sB0 + ps * SSZB_B, Bp + (long long)r0s * ldb + c0s);
            if (tid < 128) CP_ASYNC_16(sB1 + ps * SSZB_B, Bp + (long long)r1s * ldb + c1s);
        }
        CP_COMMIT();

        const uint32_t* as = Asm + (kt & (STAGES - 1)) * SSZ;
        const uint32_t* bs = Bsm + (kt & (STAGES - 1)) * SSZ_B;
        #pragma unroll
        for (int ks = 0; ks < 2; ks++) {
            int kb = ks * 8;
            uint32_t afr[2][4];
            #pragma unroll
            for (int im = 0; im < 2; im++) {
                int mb = wmb + im * 16;
                afr[im][0] = as[(mb + g    ) * TLD + kb + t4];
                afr[im][1] = as[(mb + g + 8) * TLD + kb + t4];
                afr[im][2] = as[(mb + g    ) * TLD + kb + t4 + 4];
                afr[im][3] = as[(mb + g + 8) * TLD + kb + t4 + 4];
            }
            uint32_t bfr[6][2];
            #pragma unroll
            for (int jn = 0; jn < 6; jn++) {
                int nb = wnb + jn * 8;
                bfr[jn][0] = bs[(kb + t4    ) * BSN_LD + nb + g];
                bfr[jn][1] = bs[(kb + t4 + 4) * BSN_LD + nb + g];
            }
            #pragma unroll
            for (int im = 0; im < 2; im++)
                #pragma unroll
                for (int jn = 0; jn < 6; jn++)
                    mma_tf32(acc[im][jn], afr[im], bfr[jn]);
        }
    }

    #pragma unroll
    for (int im = 0; im < 2; im++) {
        int r0 = m0 + wmb + im * 16 + g;
        #pragma unroll
        for (int jn = 0; jn < 6; jn++) {
            int c = wnb + jn * 8 + 2 * t4;
            #pragma unroll
            for (int half = 0; half < 2; half++) {
                int r = r0 + half * 8;
                *(float2*)(C + (long long)r * ldc + c) =
                    make_float2(tf32r(acc[im][jn][half*2+0]), tf32r(acc[im][jn][half*2+1]));
            }
        }
    }
}

// ---------------------------------------------------------------------------
// Orchestration
// ---------------------------------------------------------------------------
extern "C" void kernel_launch(void* const* d_in, const int* in_sizes, int n_in,
                              void* d_out, int out_size)
{
    const float* x        = (const float*)d_in[0];
    const float* rw1      = (const float*)d_in[1];
    const float* rb1      = (const float*)d_in[2];
    const float* rw2      = (const float*)d_in[3];
    const float* rb2      = (const float*)d_in[4];
    const float* nsg      = (const float*)d_in[5];
    const float* nsb      = (const float*)d_in[6];
    const float* ntg      = (const float*)d_in[7];
    const float* ntb      = (const float*)d_in[8];
    const float* nmg      = (const float*)d_in[9];
    const float* nmb      = (const float*)d_in[10];
    const float* sp_wqkv  = (const float*)d_in[11];
    const float* sp_bqkv  = (const float*)d_in[12];
    const float* sp_wo    = (const float*)d_in[13];
    const float* sp_bo    = (const float*)d_in[14];
    const float* tp_wq    = (const float*)d_in[15];
    const float* tp_bq    = (const float*)d_in[16];
    const float* tp_wk    = (const float*)d_in[17];
    const float* tp_bk    = (const float*)d_in[18];
    const float* tp_wv    = (const float*)d_in[19];
    const float* tp_bv    = (const float*)d_in[20];
    const float* tp_wo    = (const float*)d_in[21];
    const float* tp_bo    = (const float*)d_in[22];
    const float* c_wqkv   = (const float*)d_in[23];
    const float* c_bqkv   = (const float*)d_in[24];
    const float* c_wo     = (const float*)d_in[25];
    const float* c_bo     = (const float*)d_in[26];
    const float* mlp_w1   = (const float*)d_in[27];
    const float* mlp_b1   = (const float*)d_in[28];
    const float* mlp_w2   = (const float*)d_in[29];
    const float* mlp_b2   = (const float*)d_in[30];
    float* out = (float*)d_out;

    static int attr_done = 0;
    if (!attr_done) {
        cudaFuncSetAttribute(tgemm_nt_kernel, cudaFuncAttributeMaxDynamicSharedMemorySize, NT_SMEM);
        cudaFuncSetAttribute(tgemm_nn_kernel, cudaFuncAttributeMaxDynamicSharedMemorySize, NN_SMEM);
        attr_done = 1;
    }

    float *scores, *qkv, *qkv2, *xn, *xt, *attno, *spout, *tpout, *x1, *hid;
    int* idx;
    cudaGetSymbolAddress((void**)&scores, g_scores);
    cudaGetSymbolAddress((void**)&qkv,    g_qkv);
    cudaGetSymbolAddress((void**)&qkv2,   g_qkv2);
    cudaGetSymbolAddress((void**)&xn,     g_xn);
    cudaGetSymbolAddress((void**)&xt,     g_xt);
    cudaGetSymbolAddress((void**)&attno,  g_attno);
    cudaGetSymbolAddress((void**)&spout,  g_spout);
    cudaGetSymbolAddress((void**)&tpout,  g_tpout);
    cudaGetSymbolAddress((void**)&x1,     g_x1);
    cudaGetSymbolAddress((void**)&hid,    g_hid);
    cudaGetSymbolAddress((void**)&idx,    g_idx);

    const long long rowsBT  = (long long)Bz * Tt;
    const long long sQKV    = (long long)Tt * D3;
    const long long sD      = (long long)Tt * Dd;
    const long long sScB    = (long long)Hh * Tt * Tt;
    const long long sScH    = (long long)Tt * Tt;

    // ---- router ----
    router_kernel<<<Bz, Dd>>>(x, rw1, rb1, rw2, rb2, idx, idx + 8);

    // ---- spatial branch ----
    ln_kernel<<<(int)rowsBT, 256>>>(x, nsg, nsb, xn);

    tgemm_nt_kernel<<<dim3(D3/128, Tt/128, Bz), 256, NT_SMEM>>>(
        xn, Dd, sD, 0,
        sp_wqkv, Dd, 0, 0, (long long)D3 * Dd, idx,
        sp_bqkv, D3,
        nullptr, 0, 0,
        qkv, D3, sQKV, 0,
        Dd, 1, 1.0f, 0, 1);

    tgemm_nt_kernel<<<dim3(Tt/128, Tt/128, Bz*Hh), 256, NT_SMEM>>>(
        qkv, D3, sQKV, HD,
        qkv + Dd, D3, sQKV, HD, 0, nullptr,
        nullptr, 0,
        nullptr, 0, 0,
        scores, Tt, sScB, sScH,
        HD, Hh, SCALE_V, 0, 0);

    softmax_kernel<<<Bz*Hh*Tt, 256>>>(scores, 0);

    tgemm_nn_kernel<<<dim3(1, Tt/128, Bz*Hh), 256, NN_SMEM>>>(
        scores, Tt, sScB, sScH,
        qkv + 2*Dd, D3, sQKV, HD,
        attno, Dd, sD, HD,
        Tt, Hh);

    tgemm_nt_kernel<<<dim3(Dd/128, Tt/128, Bz), 256, NT_SMEM>>>(
        attno, Dd, sD, 0,
        sp_wo, Dd, 0, 0, (long long)Dd * Dd, idx,
        sp_bo, Dd,
        nullptr, 0, 0,
        spout, Dd, sD, 0,
        Dd, 1, 1.0f, 0, 1);

    // ---- temporal branch ----
    ln_kernel<<<(int)rowsBT, 256>>>(x, ntg, ntb, xt);

    tgemm_nt_kernel<<<dim3(Dd/128, Tt/128, Bz), 256, NT_SMEM>>>(
        xt, Dd, sD, 0, tp_wq, Dd, 0, 0, (long long)Dd*Dd, idx + 8,
        tp_bq, Dd, nullptr, 0, 0,
        qkv2, D3, sQKV, 0, Dd, 1, 1.0f, 0, 1);
    tgemm_nt_kernel<<<dim3(Dd/128, Tt/128, Bz), 256, NT_SMEM>>>(
        xt, Dd, sD, 0, tp_wk, Dd, 0, 0, (long long)Dd*Dd, idx + 8,
        tp_bk, Dd, nullptr, 0, 0,
        qkv2 + Dd, D3, sQKV, 0, Dd, 1, 1.0f, 0, 1);
    tgemm_nt_kernel<<<dim3(Dd/128, Tt/128, Bz), 256, NT_SMEM>>>(
        xt, Dd, sD, 0, tp_wv, Dd, 0, 0, (long long)Dd*Dd, idx + 8,
        tp_bv, Dd, nullptr, 0, 0,
        qkv2 + 2*Dd, D3, sQKV, 0, Dd, 1, 1.0f, 0, 1);

    tgemm_nt_kernel<<<dim3(Tt/128, Tt/128, Bz*Hh), 256, NT_SMEM>>>(
        qkv2, D3, sQKV, HD,
        qkv2 + Dd, D3, sQKV, HD, 0, nullptr,
        nullptr, 0,
        nullptr, 0, 0,
        scores, Tt, sScB, sScH,
        HD, Hh, SCALE_V, 0, 0);

    softmax_kernel<<<Bz*Hh*Tt, 256>>>(scores, 1);   // causal

    tgemm_nn_kernel<<<dim3(1, Tt/128, Bz*Hh), 256, NN_SMEM>>>(
        scores, Tt, sScB, sScH,
        qkv2 + 2*Dd, D3, sQKV, HD,
        attno, Dd, sD, HD,
        Tt, Hh);

    tgemm_nt_kernel<<<dim3(Dd/128, Tt/128, Bz), 256, NT_SMEM>>>(
        attno, Dd, sD, 0,
        tp_wo, Dd, 0, 0, (long long)Dd * Dd, idx + 8,
        tp_bo, Dd,
        xt, Dd, sD,
        tpout, Dd, sD, 0,
        Dd, 1, 1.0f, 0, 1);

    // ---- cross attention ----
    tgemm_nt_kernel<<<dim3(Dd/128, Tt/128, Bz), 256, NT_SMEM>>>(
        spout, Dd, sD, 0,
        c_wqkv, Dd, 0, 0, 0, nullptr,
        c_bqkv, 0, nullptr, 0, 0,
        qkv, D3, sQKV, 0, Dd, 1, 1.0f, 0, 1);
    tgemm_nt_kernel<<<dim3(Dd/128, Tt/128, Bz), 256, NT_SMEM>>>(
        tpout, Dd, sD, 0,
        c_wqkv + (long long)Dd * Dd, Dd, 0, 0, 0, nullptr,
        c_bqkv + Dd, 0, nullptr, 0, 0,
        qkv + Dd, D3, sQKV, 0, Dd, 1, 1.0f, 0, 1);
    tgemm_nt_kernel<<<dim3(Dd/128, Tt/128, Bz), 256, NT_SMEM>>>(
        tpout, Dd, sD, 0,
        c_wqkv + 2LL * Dd * Dd, Dd, 0, 0, 0, nullptr,
        c_bqkv + 2*Dd, 0, nullptr, 0, 0,
        qkv + 2*Dd, D3, sQKV, 0, Dd, 1, 1.0f, 0, 1);

    tgemm_nt_kernel<<<dim3(Tt/128, Tt/128, Bz*Hh), 256, NT_SMEM>>>(
        qkv, D3, sQKV, HD,
        qkv + Dd, D3, sQKV, HD, 0, nullptr,
        nullptr, 0,
        nullptr, 0, 0,
        scores, Tt, sScB, sScH,
        HD, Hh, SCALE_V, 0, 0);

    softmax_kernel<<<Bz*Hh*Tt, 256>>>(scores, 0);

    tgemm_nn_kernel<<<dim3(1, Tt/128, Bz*Hh), 256, NN_SMEM>>>(
        scores, Tt, sScB, sScH,
        qkv + 2*Dd, D3, sQKV, HD,
        attno, Dd, sD, HD,
        Tt, Hh);

    tgemm_nt_kernel<<<dim3(Dd/128, Tt/128, Bz), 256, NT_SMEM>>>(
        attno, Dd, sD, 0,
        c_wo, Dd, 0, 0, 0, nullptr,
        c_bo, 0,
        x, Dd, sD,
        x1, Dd, sD, 0,
        Dd, 1, 1.0f, 0, 0);

    // ---- MLP ----
    ln_kernel<<<(int)rowsBT, 256>>>(x1, nmg, nmb, xn);

    tgemm_nt_kernel<<<dim3(D4/128, (int)(rowsBT/128), 1), 256, NT_SMEM>>>(
        xn, Dd, 0, 0,
        mlp_w1, Dd, 0, 0, 0, nullptr,
        mlp_b1, 0,
        nullptr, 0, 0,
        hid, D4, 0, 0,
        Dd, 1, 1.0f, 1, 1);

    tgemm_nt_kernel<<<dim3(Dd/128, (int)(rowsBT/128), 1), 256, NT_SMEM>>>(
        hid, D4, 0, 0,
        mlp_w2, D4, 0, 0, 0, nullptr,
        mlp_b2, 0,
        x1, Dd, 0,
        out, Dd, 0, 0,
        D4, 1, 1.0f, 0, 0);
}

// round 6
// speedup vs baseline: 4.7496x; 1.8045x over previous
#include <cuda_runtime.h>
#include <cuda_fp16.h>
#include <math.h>
#include <stdint.h>

typedef long long ll;

// ---------------------------------------------------------------------------
// Problem constants
// ---------------------------------------------------------------------------
#define Bz   8
#define Tt   512
#define Dd   768
#define Hh   8
#define HD   96
#define NEXP 4
#define RH   128
#define D3   (3*Dd)     // 2304
#define D4   (4*Dd)     // 3072
#define SCALE_V (0.10206207261596575f)  // 1/sqrt(96)
#define LN_EPS 1e-5f
#define STAGES 4

// ---------------------------------------------------------------------------
// Scratch (static device arrays -- no allocation allowed)
// ---------------------------------------------------------------------------
__device__ float  g_scores[(ll)Bz*Hh*Tt*Tt];
__device__ __half g_probs [(ll)Bz*Hh*Tt*Tt];
__device__ __half g_qkvh  [(ll)Bz*Tt*D3];
__device__ __half g_qkv2h [(ll)Bz*Tt*D3];
__device__ __half g_xnh   [(ll)Bz*Tt*Dd];
__device__ __half g_xth   [(ll)Bz*Tt*Dd];
__device__ float  g_xtf   [(ll)Bz*Tt*Dd];
__device__ __half g_attno [(ll)Bz*Tt*Dd];
__device__ __half g_spout [(ll)Bz*Tt*Dd];
__device__ __half g_tpout [(ll)Bz*Tt*Dd];
__device__ float  g_x1    [(ll)Bz*Tt*Dd];
__device__ __half g_hid   [(ll)Bz*Tt*D4];
__device__ int    g_idx   [16];
// fp16 weight copies
__device__ __half g_wspqkv[(ll)NEXP*D3*Dd];
__device__ __half g_wspo  [(ll)NEXP*Dd*Dd];
__device__ __half g_wtpq  [(ll)NEXP*Dd*Dd];
__device__ __half g_wtpk  [(ll)NEXP*Dd*Dd];
__device__ __half g_wtpv  [(ll)NEXP*Dd*Dd];
__device__ __half g_wtpo  [(ll)NEXP*Dd*Dd];
__device__ __half g_wcqkv [(ll)3*Dd*Dd];
__device__ __half g_wco   [(ll)Dd*Dd];
__device__ __half g_wm1   [(ll)D4*Dd];
__device__ __half g_wm2   [(ll)Dd*D4];

__device__ __forceinline__ float gelu_exact(float v) {
    return 0.5f * v * (1.0f + erff(v * 0.70710678118654752f));
}

__device__ __forceinline__ uint32_t smem_u32(const void* p) {
    return (uint32_t)__cvta_generic_to_shared(p);
}

#define CP_ASYNC_16(dst_u32, src_ptr) \
    asm volatile("cp.async.cg.shared.global [%0], [%1], 16;\n" :: "r"(dst_u32), "l"(src_ptr))
#define CP_COMMIT() asm volatile("cp.async.commit_group;\n")
#define CP_WAIT(N)  asm volatile("cp.async.wait_group %0;\n" :: "n"(N))

__device__ __forceinline__ void ldsm_x4(uint32_t* r, uint32_t addr) {
    asm volatile("ldmatrix.sync.aligned.m8n8.x4.shared.b16 {%0,%1,%2,%3}, [%4];"
        : "=r"(r[0]), "=r"(r[1]), "=r"(r[2]), "=r"(r[3]) : "r"(addr));
}
__device__ __forceinline__ void ldsm_x4_t(uint32_t* r, uint32_t addr) {
    asm volatile("ldmatrix.sync.aligned.m8n8.x4.trans.shared.b16 {%0,%1,%2,%3}, [%4];"
        : "=r"(r[0]), "=r"(r[1]), "=r"(r[2]), "=r"(r[3]) : "r"(addr));
}
__device__ __forceinline__ void mma_fp16(float* c, const uint32_t* a, const uint32_t* b) {
    asm volatile(
        "mma.sync.aligned.m16n8k16.row.col.f32.f16.f16.f32 "
        "{%0,%1,%2,%3}, {%4,%5,%6,%7}, {%8,%9}, {%0,%1,%2,%3};"
        : "+f"(c[0]), "+f"(c[1]), "+f"(c[2]), "+f"(c[3])
        : "r"(a[0]), "r"(a[1]), "r"(a[2]), "r"(a[3]),
          "r"(b[0]), "r"(b[1]));
}

// ---------------------------------------------------------------------------
// fp32 -> fp16 conversion (n % 4 == 0)
// ---------------------------------------------------------------------------
__global__ __launch_bounds__(256) void f2h_kernel(const float* __restrict__ s,
                                                  __half* __restrict__ d, int n)
{
    int i = (blockIdx.x * blockDim.x + threadIdx.x) * 4;
    if (i < n) {
        float4 v = *(const float4*)(s + i);
        *(__half2*)(d + i)     = __floats2half2_rn(v.x, v.y);
        *(__half2*)(d + i + 2) = __floats2half2_rn(v.z, v.w);
    }
}

// ---------------------------------------------------------------------------
// Router
// ---------------------------------------------------------------------------
__global__ void router_kernel(const float* __restrict__ x,
                              const float* __restrict__ w1, const float* __restrict__ b1,
                              const float* __restrict__ w2, const float* __restrict__ b2,
                              int* __restrict__ idx_s, int* __restrict__ idx_t)
{
    __shared__ float xm[Dd];
    __shared__ float hbuf[RH];
    __shared__ float lg[8];
    int b = blockIdx.x;
    int d = threadIdx.x;
    const float* xb = x + (ll)b * Tt * Dd;
    float s = 0.f;
    for (int t = 0; t < Tt; t++) s += xb[(ll)t * Dd + d];
    xm[d] = s * (1.0f / Tt);
    __syncthreads();
    if (d < RH) {
        float a = b1[d];
        const float* wr = w1 + (ll)d * Dd;
        for (int k = 0; k < Dd; k++) a += xm[k] * wr[k];
        hbuf[d] = gelu_exact(a);
    }
    __syncthreads();
    if (d < 8) {
        float a = b2[d];
        const float* wr = w2 + d * RH;
        for (int k = 0; k < RH; k++) a += hbuf[k] * wr[k];
        lg[d] = a;
    }
    __syncthreads();
    if (d == 0) {
        int is = 0; for (int i = 1; i < NEXP; i++) if (lg[i] > lg[is]) is = i;
        int it = 0; for (int i = 1; i < NEXP; i++) if (lg[NEXP+i] > lg[NEXP+it]) it = i;
        idx_s[b] = is;
        idx_t[b] = it;
    }
}

// ---------------------------------------------------------------------------
// LayerNorm over last dim (768): fp16 output (+ optional fp32 copy)
// ---------------------------------------------------------------------------
__global__ __launch_bounds__(256) void ln_kernel(const float* __restrict__ x,
                                                 const float* __restrict__ g,
                                                 const float* __restrict__ bb,
                                                 __half* __restrict__ yh,
                                                 float* __restrict__ yf)
{
    __shared__ float sd[256];
    ll row = blockIdx.x;
    int t = threadIdx.x;
    const float* xr = x + row * Dd;
    float a0 = xr[t], a1 = xr[t+256], a2 = xr[t+512];
    sd[t] = a0 + a1 + a2;
    __syncthreads();
    for (int s = 128; s > 0; s >>= 1) { if (t < s) sd[t] += sd[t+s]; __syncthreads(); }
    float mean = sd[0] * (1.0f / Dd);
    __syncthreads();
    float d0 = a0 - mean, d1 = a1 - mean, d2 = a2 - mean;
    sd[t] = d0*d0 + d1*d1 + d2*d2;
    __syncthreads();
    for (int s = 128; s > 0; s >>= 1) { if (t < s) sd[t] += sd[t+s]; __syncthreads(); }
    float inv = rsqrtf(sd[0] * (1.0f / Dd) + LN_EPS);
    float v0 = d0 * inv * g[t]     + bb[t];
    float v1 = d1 * inv * g[t+256] + bb[t+256];
    float v2 = d2 * inv * g[t+512] + bb[t+512];
    __half* yr = yh + row * Dd;
    yr[t]     = __float2half_rn(v0);
    yr[t+256] = __float2half_rn(v1);
    yr[t+512] = __float2half_rn(v2);
    if (yf) {
        float* yfr = yf + row * Dd;
        yfr[t] = v0; yfr[t+256] = v1; yfr[t+512] = v2;
    }
}

// ---------------------------------------------------------------------------
// Softmax rows of 512: fp32 in, fp16 out
// ---------------------------------------------------------------------------
__global__ __launch_bounds__(256) void softmax_kernel(const float* __restrict__ S,
                                                      __half* __restrict__ P, int causal)
{
    __shared__ float sd[256];
    ll row = blockIdx.x;
    int q = (int)(row & (Tt - 1));
    const float* p = S + row * Tt;
    int t = threadIdx.x;
    float v0 = p[t], v1 = p[t + 256];
    if (causal) {
        if (t > q) v0 = -INFINITY;
        if (t + 256 > q) v1 = -INFINITY;
    }
    sd[t] = fmaxf(v0, v1);
    __syncthreads();
    for (int s = 128; s > 0; s >>= 1) { if (t < s) sd[t] = fmaxf(sd[t], sd[t+s]); __syncthreads(); }
    float rowmax = sd[0];
    __syncthreads();
    float e0 = expf(v0 - rowmax);
    float e1 = expf(v1 - rowmax);
    sd[t] = e0 + e1;
    __syncthreads();
    for (int s = 128; s > 0; s >>= 1) { if (t < s) sd[t] += sd[t+s]; __syncthreads(); }
    float inv = 1.0f / sd[0];
    __half* o = P + row * Tt;
    o[t]       = __float2half_rn(e0 * inv);
    o[t + 256] = __float2half_rn(e1 * inv);
}

// ---------------------------------------------------------------------------
// FP16 tensor-core NT GEMM, 4-stage cp.async, ldmatrix fragments.
// C[m,n] = alpha*sum_k A[m,k]*W[n,k] (+bias)(gelu)(+res), out fp16 or fp32.
// BM=128, BN=128, BK=32, 8 warps (4m x 2n), warp tile 32x64.
// ---------------------------------------------------------------------------
#define ALD   40                 // halfs per smem row (32 + 8 pad); stride 80B
#define ASTG  (128 * ALD)        // halfs per stage per operand
#define ASTGB (ASTG * 2)         // 10240 bytes
#define NT_SMEM (2 * STAGES * ASTGB)   // 81920

__global__ __launch_bounds__(256, 2) void hgemm_nt_kernel(
    const __half* __restrict__ A, int lda, ll bsA, ll hsA,
    const __half* __restrict__ W, int ldw, ll bsW, ll hsW,
    ll esW, const int* __restrict__ eidx,
    const float* __restrict__ bias, int esBias,
    const float* __restrict__ res, int ldr, ll bsR,
    void* __restrict__ Cv, int ldc, ll bsC, ll hsC, int cHalf,
    int Kd, int Hn, float alpha, int act)
{
    extern __shared__ __half hsm[];
    __half* Asm = hsm;
    __half* Wsm = hsm + STAGES * ASTG;

    int z = blockIdx.z;
    int b = z / Hn, h = z - b * Hn;
    A += (ll)b * bsA + (ll)h * hsA;
    ll woff = (ll)b * bsW + (ll)h * hsW;
    const float* biasp = bias;
    if (eidx) {
        int e = eidx[b];
        woff += (ll)e * esW;
        if (bias) biasp = bias + (ll)e * esBias;
    }
    W += woff;
    if (res) res += (ll)b * bsR;

    int tid = threadIdx.x, lane = tid & 31, warp = tid >> 5;
    int wm = warp & 3, wn = warp >> 2;
    int wmb = wm * 32, wnb = wn * 64;
    int g = lane >> 2, t4 = lane & 3;
    int m0 = blockIdx.y * 128, n0 = blockIdx.x * 128;

    // copy lanes: 512 16B-segs per operand; thread does rows r0 and r0+64
    int r0 = tid >> 2, c0 = (tid & 3) * 8;
    const __half* Ap = A + (ll)(m0 + r0) * lda + c0;
    const __half* Wp = W + (ll)(n0 + r0) * ldw + c0;
    ll ldA64 = (ll)64 * lda, ldW64 = (ll)64 * ldw;
    uint32_t dA = smem_u32(Asm) + (uint32_t)((r0 * ALD + c0) * 2);
    uint32_t dW = smem_u32(Wsm) + (uint32_t)((r0 * ALD + c0) * 2);
    const uint32_t rowOff = 64 * ALD * 2;

    float acc[2][8][4];
    #pragma unroll
    for (int i = 0; i < 2; i++)
        #pragma unroll
        for (int j = 0; j < 8; j++)
            #pragma unroll
            for (int q = 0; q < 4; q++) acc[i][j][q] = 0.f;

    // ldmatrix lane bases (byte offsets within a stage)
    uint32_t aBase = smem_u32(Asm) +
        (uint32_t)((((lane & 15) + wmb) * ALD + ((lane >> 4) << 3)) * 2);
    uint32_t bBase = smem_u32(Wsm) +
        (uint32_t)((((lane & 7) + ((lane >> 4) << 3) + wnb) * ALD + (((lane >> 3) & 1) << 3)) * 2);

    int kTiles = Kd >> 5;

    #pragma unroll
    for (int s = 0; s < STAGES - 1; s++) {
        if (s < kTiles) {
            const __half* a = Ap + s * 32;
            const __half* w = Wp + s * 32;
            CP_ASYNC_16(dA + s * ASTGB,          a);
            CP_ASYNC_16(dA + s * ASTGB + rowOff, a + ldA64);
            CP_ASYNC_16(dW + s * ASTGB,          w);
            CP_ASYNC_16(dW + s * ASTGB + rowOff, w + ldW64);
        }
        CP_COMMIT();
    }

    for (int kt = 0; kt < kTiles; kt++) {
        CP_WAIT(STAGES - 2);
        __syncthreads();

        int pf = kt + STAGES - 1;
        if (pf < kTiles) {
            int ps = pf & (STAGES - 1);
            const __half* a = Ap + pf * 32;
            const __half* w = Wp + pf * 32;
            CP_ASYNC_16(dA + ps * ASTGB,          a);
            CP_ASYNC_16(dA + ps * ASTGB + rowOff, a + ldA64);
            CP_ASYNC_16(dW + ps * ASTGB,          w);
            CP_ASYNC_16(dW + ps * ASTGB + rowOff, w + ldW64);
        }
        CP_COMMIT();

        uint32_t sa = aBase + (kt & (STAGES - 1)) * ASTGB;
        uint32_t sb = bBase + (kt & (STAGES - 1)) * ASTGB;
        #pragma unroll
        for (int ks = 0; ks < 2; ks++) {
            uint32_t afr[2][4], bfr[8][2];
            #pragma unroll
            for (int im = 0; im < 2; im++)
                ldsm_x4(afr[im], sa + im * (16 * ALD * 2) + ks * 32);
            #pragma unroll
            for (int jp = 0; jp < 4; jp++) {
                uint32_t rb[4];
                ldsm_x4(rb, sb + jp * (16 * ALD * 2) + ks * 32);
                bfr[2*jp][0]   = rb[0]; bfr[2*jp][1]   = rb[1];
                bfr[2*jp+1][0] = rb[2]; bfr[2*jp+1][1] = rb[3];
            }
            #pragma unroll
            for (int im = 0; im < 2; im++)
                #pragma unroll
                for (int jn = 0; jn < 8; jn++)
                    mma_fp16(acc[im][jn], afr[im], bfr[jn]);
        }
    }

    // epilogue
    __half* Ch = (__half*)Cv;
    float*  Cf = (float*)Cv;
    ll cb = (ll)b * bsC + (ll)h * hsC;
    #pragma unroll
    for (int im = 0; im < 2; im++) {
        int rr0 = m0 + wmb + im * 16 + g;
        #pragma unroll
        for (int jn = 0; jn < 8; jn++) {
            int c = n0 + wnb + jn * 8 + 2 * t4;
            float bv0 = biasp ? biasp[c]     : 0.f;
            float bv1 = biasp ? biasp[c + 1] : 0.f;
            #pragma unroll
            for (int hf = 0; hf < 2; hf++) {
                int r = rr0 + hf * 8;
                float v0 = acc[im][jn][hf*2+0] * alpha + bv0;
                float v1 = acc[im][jn][hf*2+1] * alpha + bv1;
                if (act) { v0 = gelu_exact(v0); v1 = gelu_exact(v1); }
                if (res) {
                    const float* rp = res + (ll)r * ldr + c;
                    v0 += rp[0]; v1 += rp[1];
                }
                if (cHalf)
                    *(__half2*)(Ch + cb + (ll)r * ldc + c) = __floats2half2_rn(v0, v1);
                else
                    *(float2*)(Cf + cb + (ll)r * ldc + c) = make_float2(v0, v1);
            }
        }
    }
}

// ---------------------------------------------------------------------------
// FP16 tensor-core NN GEMM (P@V), N=96, BM=128, BK=32, 4-stage pipeline.
// B fragments via ldmatrix.trans. Output fp16.
// ---------------------------------------------------------------------------
#define BLD   104                    // 96 + 8 pad halfs; stride 208B
#define BSTG  (32 * BLD)             // halfs per B stage
#define BSTGB (BSTG * 2)             // 6656 bytes
#define NN_SMEM (STAGES * (ASTGB + BSTGB))   // 67584

__global__ __launch_bounds__(256, 2) void hgemm_nn_kernel(
    const __half* __restrict__ A, int lda, ll bsA, ll hsA,
    const __half* __restrict__ Bm, int ldb, ll bsB, ll hsB,
    __half* __restrict__ C, int ldc, ll bsC, ll hsC,
    int Kd, int Hn)
{
    extern __shared__ __half hsm[];
    __half* Asm = hsm;
    __half* Bsm = hsm + STAGES * ASTG;

    int z = blockIdx.z;
    int b = z / Hn, h = z - b * Hn;
    A  += (ll)b * bsA + (ll)h * hsA;
    Bm += (ll)b * bsB + (ll)h * hsB;
    C  += (ll)b * bsC + (ll)h * hsC;

    int tid = threadIdx.x, lane = tid & 31, warp = tid >> 5;
    int wm = warp & 3, wn = warp >> 2;
    int wmb = wm * 32, wnb = wn * 48;
    int g = lane >> 2, t4 = lane & 3;
    int m0 = blockIdx.y * 128;

    // A copy (as NT)
    int r0 = tid >> 2, c0 = (tid & 3) * 8;
    const __half* Ap = A + (ll)(m0 + r0) * lda + c0;
    ll ldA64 = (ll)64 * lda;
    uint32_t dA = smem_u32(Asm) + (uint32_t)((r0 * ALD + c0) * 2);
    const uint32_t rowOff = 64 * ALD * 2;

    // B copy: 32 rows x 96 halfs = 384 16B-segs
    int rB0 = tid / 12, cB0 = (tid % 12) * 8;
    int sB1 = tid + 256;
    int rB1 = sB1 / 12, cB1 = (sB1 % 12) * 8;
    const __half* Bp0 = Bm + (ll)rB0 * ldb + cB0;
    const __half* Bp1 = Bm + (ll)rB1 * ldb + cB1;
    uint32_t dB0 = smem_u32(Bsm) + (uint32_t)((rB0 * BLD + cB0) * 2);
    uint32_t dB1 = smem_u32(Bsm) + (uint32_t)((rB1 * BLD + cB1) * 2);

    float acc[2][6][4];
    #pragma unroll
    for (int i = 0; i < 2; i++)
        #pragma unroll
        for (int j = 0; j < 6; j++)
            #pragma unroll
            for (int q = 0; q < 4; q++) acc[i][j][q] = 0.f;

    uint32_t aBase = smem_u32(Asm) +
        (uint32_t)((((lane & 15) + wmb) * ALD + ((lane >> 4) << 3)) * 2);
    // trans B: row = kb + (lane&7) + ((lane>>3)&1)*8 ; col = wnb + jp*16 + (lane>>4)*8
    uint32_t bBase = smem_u32(Bsm) +
        (uint32_t)((((lane & 7) + (((lane >> 3) & 1) << 3)) * BLD + wnb + ((lane >> 4) << 3)) * 2);

    int kTiles = Kd >> 5;

    #pragma unroll
    for (int s = 0; s < STAGES - 1; s++) {
        if (s < kTiles) {
            const __half* a = Ap + s * 32;
            CP_ASYNC_16(dA + s * ASTGB,          a);
            CP_ASYNC_16(dA + s * ASTGB + rowOff, a + ldA64);
            ll bo = (ll)(s * 32) * ldb;
            CP_ASYNC_16(dB0 + s * BSTGB, Bp0 + bo);
            if (tid < 128) CP_ASYNC_16(dB1 + s * BSTGB, Bp1 + bo);
        }
        CP_COMMIT();
    }

    for (int kt = 0; kt < kTiles; kt++) {
        CP_WAIT(STAGES - 2);
        __syncthreads();

        int pf = kt + STAGES - 1;
        if (pf < kTiles) {
            int ps = pf & (STAGES - 1);
            const __half* a = Ap + pf * 32;
            CP_ASYNC_16(dA + ps * ASTGB,          a);
            CP_ASYNC_16(dA + ps * ASTGB + rowOff, a + ldA64);
            ll bo = (ll)(pf * 32) * ldb;
            CP_ASYNC_16(dB0 + ps * BSTGB, Bp0 + bo);
            if (tid < 128) CP_ASYNC_16(dB1 + ps * BSTGB, Bp1 + bo);
        }
        CP_COMMIT();

        uint32_t sa = aBase + (kt & (STAGES - 1)) * ASTGB;
        uint32_t sb = bBase + (kt & (STAGES - 1)) * BSTGB;
        #pragma unroll
        for (int ks = 0; ks < 2; ks++) {
            uint32_t afr[2][4], bfr[6][2];
            #pragma unroll
            for (int im = 0; im < 2; im++)
                ldsm_x4(afr[im], sa + im * (16 * ALD * 2) + ks * 32);
            #pragma unroll
            for (int jp = 0; jp < 3; jp++) {
                uint32_t rb[4];
                ldsm_x4_t(rb, sb + ks * (16 * BLD * 2) + jp * 32);
                bfr[2*jp][0]   = rb[0]; bfr[2*jp][1]   = rb[1];
                bfr[2*jp+1][0] = rb[2]; bfr[2*jp+1][1] = rb[3];
            }
            #pragma unroll
            for (int im = 0; im < 2; im++)
                #pragma unroll
                for (int jn = 0; jn < 6; jn++)
                    mma_fp16(acc[im][jn], afr[im], bfr[jn]);
        }
    }

    #pragma unroll
    for (int im = 0; im < 2; im++) {
        int rr0 = m0 + wmb + im * 16 + g;
        #pragma unroll
        for (int jn = 0; jn < 6; jn++) {
            int c = wnb + jn * 8 + 2 * t4;
            #pragma unroll
            for (int hf = 0; hf < 2; hf++) {
                int r = rr0 + hf * 8;
                *(__half2*)(C + (ll)r * ldc + c) =
                    __floats2half2_rn(acc[im][jn][hf*2+0], acc[im][jn][hf*2+1]);
            }
        }
    }
}

// ---------------------------------------------------------------------------
// Orchestration
// ---------------------------------------------------------------------------
static void conv(const float* s, __half* d, ll n) {
    f2h_kernel<<<(int)((n/4 + 255) / 256), 256>>>(s, d, (int)n);
}

extern "C" void kernel_launch(void* const* d_in, const int* in_sizes, int n_in,
                              void* d_out, int out_size)
{
    const float* x        = (const float*)d_in[0];
    const float* rw1      = (const float*)d_in[1];
    const float* rb1      = (const float*)d_in[2];
    const float* rw2      = (const float*)d_in[3];
    const float* rb2      = (const float*)d_in[4];
    const float* nsg      = (const float*)d_in[5];
    const float* nsb      = (const float*)d_in[6];
    const float* ntg      = (const float*)d_in[7];
    const float* ntb      = (const float*)d_in[8];
    const float* nmg      = (const float*)d_in[9];
    const float* nmb      = (const float*)d_in[10];
    const float* sp_wqkv  = (const float*)d_in[11];
    const float* sp_bqkv  = (const float*)d_in[12];
    const float* sp_wo    = (const float*)d_in[13];
    const float* sp_bo    = (const float*)d_in[14];
    const float* tp_wq    = (const float*)d_in[15];
    const float* tp_bq    = (const float*)d_in[16];
    const float* tp_wk    = (const float*)d_in[17];
    const float* tp_bk    = (const float*)d_in[18];
    const float* tp_wv    = (const float*)d_in[19];
    const float* tp_bv    = (const float*)d_in[20];
    const float* tp_wo    = (const float*)d_in[21];
    const float* tp_bo    = (const float*)d_in[22];
    const float* c_wqkv   = (const float*)d_in[23];
    const float* c_bqkv   = (const float*)d_in[24];
    const float* c_wo     = (const float*)d_in[25];
    const float* c_bo     = (const float*)d_in[26];
    const float* mlp_w1   = (const float*)d_in[27];
    const float* mlp_b1   = (const float*)d_in[28];
    const float* mlp_w2   = (const float*)d_in[29];
    const float* mlp_b2   = (const float*)d_in[30];
    float* out = (float*)d_out;

    static int attr_done = 0;
    if (!attr_done) {
        cudaFuncSetAttribute(hgemm_nt_kernel, cudaFuncAttributeMaxDynamicSharedMemorySize, NT_SMEM);
        cudaFuncSetAttribute(hgemm_nn_kernel, cudaFuncAttributeMaxDynamicSharedMemorySize, NN_SMEM);
        attr_done = 1;
    }

    float *scores, *xtf, *x1;
    __half *probs, *qkv, *qkv2, *xnh, *xth, *attno, *spout, *tpout, *hid;
    __half *wspqkv, *wspo, *wtpq, *wtpk, *wtpv, *wtpo, *wcqkv, *wco, *wm1, *wm2;
    int* idx;
    cudaGetSymbolAddress((void**)&scores, g_scores);
    cudaGetSymbolAddress((void**)&probs,  g_probs);
    cudaGetSymbolAddress((void**)&qkv,    g_qkvh);
    cudaGetSymbolAddress((void**)&qkv2,   g_qkv2h);
    cudaGetSymbolAddress((void**)&xnh,    g_xnh);
    cudaGetSymbolAddress((void**)&xth,    g_xth);
    cudaGetSymbolAddress((void**)&xtf,    g_xtf);
    cudaGetSymbolAddress((void**)&attno,  g_attno);
    cudaGetSymbolAddress((void**)&spout,  g_spout);
    cudaGetSymbolAddress((void**)&tpout,  g_tpout);
    cudaGetSymbolAddress((void**)&x1,     g_x1);
    cudaGetSymbolAddress((void**)&hid,    g_hid);
    cudaGetSymbolAddress((void**)&idx,    g_idx);
    cudaGetSymbolAddress((void**)&wspqkv, g_wspqkv);
    cudaGetSymbolAddress((void**)&wspo,   g_wspo);
    cudaGetSymbolAddress((void**)&wtpq,   g_wtpq);
    cudaGetSymbolAddress((void**)&wtpk,   g_wtpk);
    cudaGetSymbolAddress((void**)&wtpv,   g_wtpv);
    cudaGetSymbolAddress((void**)&wtpo,   g_wtpo);
    cudaGetSymbolAddress((void**)&wcqkv,  g_wcqkv);
    cudaGetSymbolAddress((void**)&wco,    g_wco);
    cudaGetSymbolAddress((void**)&wm1,    g_wm1);
    cudaGetSymbolAddress((void**)&wm2,    g_wm2);

    const ll rowsBT = (ll)Bz * Tt;
    const ll sQKV   = (ll)Tt * D3;
    const ll sD     = (ll)Tt * Dd;
    const ll sScB   = (ll)Hh * Tt * Tt;
    const ll sScH   = (ll)Tt * Tt;

    // ---- weight conversion (fp32 -> fp16) ----
    conv(sp_wqkv, wspqkv, (ll)NEXP * D3 * Dd);
    conv(sp_wo,   wspo,   (ll)NEXP * Dd * Dd);
    conv(tp_wq,   wtpq,   (ll)NEXP * Dd * Dd);
    conv(tp_wk,   wtpk,   (ll)NEXP * Dd * Dd);
    conv(tp_wv,   wtpv,   (ll)NEXP * Dd * Dd);
    conv(tp_wo,   wtpo,   (ll)NEXP * Dd * Dd);
    conv(c_wqkv,  wcqkv,  (ll)3 * Dd * Dd);
    conv(c_wo,    wco,    (ll)Dd * Dd);
    conv(mlp_w1,  wm1,    (ll)D4 * Dd);
    conv(mlp_w2,  wm2,    (ll)Dd * D4);

    // ---- router ----
    router_kernel<<<Bz, Dd>>>(x, rw1, rb1, rw2, rb2, idx, idx + 8);

    // ---- spatial branch ----
    ln_kernel<<<(int)rowsBT, 256>>>(x, nsg, nsb, xnh, nullptr);

    hgemm_nt_kernel<<<dim3(D3/128, Tt/128, Bz), 256, NT_SMEM>>>(
        xnh, Dd, sD, 0,
        wspqkv, Dd, 0, 0, (ll)D3 * Dd, idx,
        sp_bqkv, D3, nullptr, 0, 0,
        qkv, D3, sQKV, 0, 1,
        Dd, 1, 1.0f, 0);

    hgemm_nt_kernel<<<dim3(Tt/128, Tt/128, Bz*Hh), 256, NT_SMEM>>>(
        qkv, D3, sQKV, HD,
        qkv + Dd, D3, sQKV, HD, 0, nullptr,
        nullptr, 0, nullptr, 0, 0,
        scores, Tt, sScB, sScH, 0,
        HD, Hh, SCALE_V, 0);

    softmax_kernel<<<Bz*Hh*Tt, 256>>>(scores, probs, 0);

    hgemm_nn_kernel<<<dim3(1, Tt/128, Bz*Hh), 256, NN_SMEM>>>(
        probs, Tt, sScB, sScH,
        qkv + 2*Dd, D3, sQKV, HD,
        attno, Dd, sD, HD,
        Tt, Hh);

    hgemm_nt_kernel<<<dim3(Dd/128, Tt/128, Bz), 256, NT_SMEM>>>(
        attno, Dd, sD, 0,
        wspo, Dd, 0, 0, (ll)Dd * Dd, idx,
        sp_bo, Dd, nullptr, 0, 0,
        spout, Dd, sD, 0, 1,
        Dd, 1, 1.0f, 0);

    // ---- temporal branch ----
    ln_kernel<<<(int)rowsBT, 256>>>(x, ntg, ntb, xth, xtf);

    hgemm_nt_kernel<<<dim3(Dd/128, Tt/128, Bz), 256, NT_SMEM>>>(
        xth, Dd, sD, 0, wtpq, Dd, 0, 0, (ll)Dd*Dd, idx + 8,
        tp_bq, Dd, nullptr, 0, 0,
        qkv2, D3, sQKV, 0, 1, Dd, 1, 1.0f, 0);
    hgemm_nt_kernel<<<dim3(Dd/128, Tt/128, Bz), 256, NT_SMEM>>>(
        xth, Dd, sD, 0, wtpk, Dd, 0, 0, (ll)Dd*Dd, idx + 8,
        tp_bk, Dd, nullptr, 0, 0,
        qkv2 + Dd, D3, sQKV, 0, 1, Dd, 1, 1.0f, 0);
    hgemm_nt_kernel<<<dim3(Dd/128, Tt/128, Bz), 256, NT_SMEM>>>(
        xth, Dd, sD, 0, wtpv, Dd, 0, 0, (ll)Dd*Dd, idx + 8,
        tp_bv, Dd, nullptr, 0, 0,
        qkv2 + 2*Dd, D3, sQKV, 0, 1, Dd, 1, 1.0f, 0);

    hgemm_nt_kernel<<<dim3(Tt/128, Tt/128, Bz*Hh), 256, NT_SMEM>>>(
        qkv2, D3, sQKV, HD,
        qkv2 + Dd, D3, sQKV, HD, 0, nullptr,
        nullptr, 0, nullptr, 0, 0,
        scores, Tt, sScB, sScH, 0,
        HD, Hh, SCALE_V, 0);

    softmax_kernel<<<Bz*Hh*Tt, 256>>>(scores, probs, 1);   // causal

    hgemm_nn_kernel<<<dim3(1, Tt/128, Bz*Hh), 256, NN_SMEM>>>(
        probs, Tt, sScB, sScH,
        qkv2 + 2*Dd, D3, sQKV, HD,
        attno, Dd, sD, HD,
        Tt, Hh);

    hgemm_nt_kernel<<<dim3(Dd/128, Tt/128, Bz), 256, NT_SMEM>>>(
        attno, Dd, sD, 0,
        wtpo, Dd, 0, 0, (ll)Dd * Dd, idx + 8,
        tp_bo, Dd,
        xtf, Dd, sD,
        tpout, Dd, sD, 0, 1,
        Dd, 1, 1.0f, 0);

    // ---- cross attention ----
    hgemm_nt_kernel<<<dim3(Dd/128, Tt/128, Bz), 256, NT_SMEM>>>(
        spout, Dd, sD, 0,
        wcqkv, Dd, 0, 0, 0, nullptr,
        c_bqkv, 0, nullptr, 0, 0,
        qkv, D3, sQKV, 0, 1, Dd, 1, 1.0f, 0);
    hgemm_nt_kernel<<<dim3(Dd/128, Tt/128, Bz), 256, NT_SMEM>>>(
        tpout, Dd, sD, 0,
        wcqkv + (ll)Dd * Dd, Dd, 0, 0, 0, nullptr,
        c_bqkv + Dd, 0, nullptr, 0, 0,
        qkv + Dd, D3, sQKV, 0, 1, Dd, 1, 1.0f, 0);
    hgemm_nt_kernel<<<dim3(Dd/128, Tt/128, Bz), 256, NT_SMEM>>>(
        tpout, Dd, sD, 0,
        wcqkv + 2LL * Dd * Dd, Dd, 0, 0, 0, nullptr,
        c_bqkv + 2*Dd, 0, nullptr, 0, 0,
        qkv + 2*Dd, D3, sQKV, 0, 1, Dd, 1, 1.0f, 0);

    hgemm_nt_kernel<<<dim3(Tt/128, Tt/128, Bz*Hh), 256, NT_SMEM>>>(
        qkv, D3, sQKV, HD,
        qkv + Dd, D3, sQKV, HD, 0, nullptr,
        nullptr, 0, nullptr, 0, 0,
        scores, Tt, sScB, sScH, 0,
        HD, Hh, SCALE_V, 0);

    softmax_kernel<<<Bz*Hh*Tt, 256>>>(scores, probs, 0);

    hgemm_nn_kernel<<<dim3(1, Tt/128, Bz*Hh), 256, NN_SMEM>>>(
        probs, Tt, sScB, sScH,
        qkv + 2*Dd, D3, sQKV, HD,
        attno, Dd, sD, HD,
        Tt, Hh);

    hgemm_nt_kernel<<<dim3(Dd/128, Tt/128, Bz), 256, NT_SMEM>>>(
        attno, Dd, sD, 0,
        wco, Dd, 0, 0, 0, nullptr,
        c_bo, 0,
        x, Dd, sD,
        x1, Dd, sD, 0, 0,
        Dd, 1, 1.0f, 0);

    // ---- MLP ----
    ln_kernel<<<(int)rowsBT, 256>>>(x1, nmg, nmb, xnh, nullptr);

    hgemm_nt_kernel<<<dim3(D4/128, (int)(rowsBT/128), 1), 256, NT_SMEM>>>(
        xnh, Dd, 0, 0,
        wm1, Dd, 0, 0, 0, nullptr,
        mlp_b1, 0, nullptr, 0, 0,
        hid, D4, 0, 0, 1,
        Dd, 1, 1.0f, 1);

    hgemm_nt_kernel<<<dim3(Dd/128, (int)(rowsBT/128), 1), 256, NT_SMEM>>>(
        hid, D4, 0, 0,
        wm2, D4, 0, 0, 0, nullptr,
        mlp_b2, 0,
        x1, Dd, 0,
        out, Dd, 0, 0, 0,
        D4, 1, 1.0f, 0);
}

// round 7
// speedup vs baseline: 6.2191x; 1.3094x over previous
#include <cuda_runtime.h>
#include <cuda_fp16.h>
#include <math.h>
#include <stdint.h>

typedef long long ll;

// ---------------------------------------------------------------------------
// Problem constants
// ---------------------------------------------------------------------------
#define Bz   8
#define Tt   512
#define Dd   768
#define Hh   8
#define HD   96
#define NEXP 4
#define RH   128
#define D3   (3*Dd)     // 2304
#define D4   (4*Dd)     // 3072
#define SCALE_V (0.10206207261596575f)  // 1/sqrt(96)
#define LN_EPS 1e-5f
#define STAGES 4

// ---------------------------------------------------------------------------
// Scratch (static device arrays -- no allocation allowed)
// ---------------------------------------------------------------------------
__device__ __half g_qkvh  [(ll)Bz*Tt*D3];
__device__ __half g_qkv2h [(ll)Bz*Tt*D3];
__device__ __half g_xnh   [(ll)Bz*Tt*Dd];
__device__ __half g_xth   [(ll)Bz*Tt*Dd];
__device__ float  g_xtf   [(ll)Bz*Tt*Dd];
__device__ __half g_attno [(ll)Bz*Tt*Dd];
__device__ __half g_spout [(ll)Bz*Tt*Dd];
__device__ __half g_tpout [(ll)Bz*Tt*Dd];
__device__ float  g_x1    [(ll)Bz*Tt*Dd];
__device__ __half g_hid   [(ll)Bz*Tt*D4];
__device__ int    g_idx   [16];
__device__ float  g_btp   [(ll)NEXP*D3];
// fp16 weight copies
__device__ __half g_wspqkv[(ll)NEXP*D3*Dd];
__device__ __half g_wspo  [(ll)NEXP*Dd*Dd];
__device__ __half g_wtpqkv[(ll)NEXP*D3*Dd];   // packed q/k/v
__device__ __half g_wtpo  [(ll)NEXP*Dd*Dd];
__device__ __half g_wcqkv [(ll)3*Dd*Dd];
__device__ __half g_wco   [(ll)Dd*Dd];
__device__ __half g_wm1   [(ll)D4*Dd];
__device__ __half g_wm2   [(ll)Dd*D4];

__device__ __forceinline__ float gelu_exact(float v) {
    return 0.5f * v * (1.0f + erff(v * 0.70710678118654752f));
}
__device__ __forceinline__ uint32_t smem_u32(const void* p) {
    return (uint32_t)__cvta_generic_to_shared(p);
}

#define CP_ASYNC_16(dst_u32, src_ptr) \
    asm volatile("cp.async.cg.shared.global [%0], [%1], 16;\n" :: "r"(dst_u32), "l"(src_ptr))
#define CP_COMMIT() asm volatile("cp.async.commit_group;\n")
#define CP_WAIT(N)  asm volatile("cp.async.wait_group %0;\n" :: "n"(N))

__device__ __forceinline__ void ldsm_x4(uint32_t* r, uint32_t addr) {
    asm volatile("ldmatrix.sync.aligned.m8n8.x4.shared.b16 {%0,%1,%2,%3}, [%4];"
        : "=r"(r[0]), "=r"(r[1]), "=r"(r[2]), "=r"(r[3]) : "r"(addr));
}
__device__ __forceinline__ void ldsm_x4_t(uint32_t* r, uint32_t addr) {
    asm volatile("ldmatrix.sync.aligned.m8n8.x4.trans.shared.b16 {%0,%1,%2,%3}, [%4];"
        : "=r"(r[0]), "=r"(r[1]), "=r"(r[2]), "=r"(r[3]) : "r"(addr));
}
__device__ __forceinline__ void mma_fp16(float* c, const uint32_t* a, const uint32_t* b) {
    asm volatile(
        "mma.sync.aligned.m16n8k16.row.col.f32.f16.f16.f32 "
        "{%0,%1,%2,%3}, {%4,%5,%6,%7}, {%8,%9}, {%0,%1,%2,%3};"
        : "+f"(c[0]), "+f"(c[1]), "+f"(c[2]), "+f"(c[3])
        : "r"(a[0]), "r"(a[1]), "r"(a[2]), "r"(a[3]),
          "r"(b[0]), "r"(b[1]));
}
__device__ __forceinline__ uint32_t packh2(float a, float b) {
    __half2 h = __floats2half2_rn(a, b);
    return *(uint32_t*)&h;
}

// ---------------------------------------------------------------------------
// Mega weight convert: all fp32 weights -> fp16, temporal q/k/v packed
// ---------------------------------------------------------------------------
#define SEG_SPQKV ((ll)NEXP*D3*Dd)   // 7077888
#define SEG_DD    ((ll)NEXP*Dd*Dd)   // 2359296
#define SEG_CQKV  ((ll)3*Dd*Dd)      // 1769472
#define SEG_CO    ((ll)Dd*Dd)        // 589824
#define SEG_M     ((ll)D4*Dd)        // 2359296
#define CONV_TOTAL (SEG_SPQKV + SEG_DD + 3*SEG_DD + SEG_DD + SEG_CQKV + SEG_CO + 2*SEG_M)

__device__ __forceinline__ void cvt4(__half* d, const float* s) {
    float4 v = *(const float4*)s;
    *(__half2*)(d)     = __floats2half2_rn(v.x, v.y);
    *(__half2*)(d + 2) = __floats2half2_rn(v.z, v.w);
}

__global__ __launch_bounds__(256) void convert_all_kernel(
    const float* __restrict__ spqkv, const float* __restrict__ spo,
    const float* __restrict__ tq, const float* __restrict__ tk,
    const float* __restrict__ tv, const float* __restrict__ to,
    const float* __restrict__ cqkv, const float* __restrict__ cwo,
    const float* __restrict__ m1, const float* __restrict__ m2)
{
    ll i = ((ll)blockIdx.x * 256 + threadIdx.x) * 4;
    if (i >= CONV_TOTAL) return;
    ll o = i;
    if (o < SEG_SPQKV) { cvt4(g_wspqkv + o, spqkv + o); return; }
    o -= SEG_SPQKV;
    if (o < SEG_DD)    { cvt4(g_wspo + o, spo + o); return; }
    o -= SEG_DD;
    if (o < SEG_DD) {   // tp_wq -> packed rows [0,768)
        ll e = o / SEG_CO, rem = o - e * SEG_CO;
        cvt4(g_wtpqkv + e * ((ll)D3*Dd) + rem, tq + o); return;
    }
    o -= SEG_DD;
    if (o < SEG_DD) {   // tp_wk -> rows [768,1536)
        ll e = o / SEG_CO, rem = o - e * SEG_CO;
        cvt4(g_wtpqkv + e * ((ll)D3*Dd) + (ll)Dd*Dd + rem, tk + o); return;
    }
    o -= SEG_DD;
    if (o < SEG_DD) {   // tp_wv -> rows [1536,2304)
        ll e = o / SEG_CO, rem = o - e * SEG_CO;
        cvt4(g_wtpqkv + e * ((ll)D3*Dd) + (ll)2*Dd*Dd + rem, tv + o); return;
    }
    o -= SEG_DD;
    if (o < SEG_DD)   { cvt4(g_wtpo + o, to + o); return; }
    o -= SEG_DD;
    if (o < SEG_CQKV) { cvt4(g_wcqkv + o, cqkv + o); return; }
    o -= SEG_CQKV;
    if (o < SEG_CO)   { cvt4(g_wco + o, cwo + o); return; }
    o -= SEG_CO;
    if (o < SEG_M)    { cvt4(g_wm1 + o, m1 + o); return; }
    o -= SEG_M;
    cvt4(g_wm2 + o, m2 + o);
}

__global__ void pack_btp_kernel(const float* __restrict__ bq,
                                const float* __restrict__ bk,
                                const float* __restrict__ bv)
{
    int i = blockIdx.x * 256 + threadIdx.x;
    if (i >= NEXP * D3) return;
    int e = i / D3, j = i - e * D3;
    float v = (j < Dd) ? bq[e*Dd + j] : (j < 2*Dd) ? bk[e*Dd + j - Dd] : bv[e*Dd + j - 2*Dd];
    g_btp[i] = v;
}

// ---------------------------------------------------------------------------
// Router
// ---------------------------------------------------------------------------
__global__ void router_kernel(const float* __restrict__ x,
                              const float* __restrict__ w1, const float* __restrict__ b1,
                              const float* __restrict__ w2, const float* __restrict__ b2,
                              int* __restrict__ idx_s, int* __restrict__ idx_t)
{
    __shared__ float xm[Dd];
    __shared__ float hbuf[RH];
    __shared__ float lg[8];
    int b = blockIdx.x;
    int d = threadIdx.x;
    const float* xb = x + (ll)b * Tt * Dd;
    float s = 0.f;
    for (int t = 0; t < Tt; t++) s += xb[(ll)t * Dd + d];
    xm[d] = s * (1.0f / Tt);
    __syncthreads();
    if (d < RH) {
        float a = b1[d];
        const float* wr = w1 + (ll)d * Dd;
        for (int k = 0; k < Dd; k++) a += xm[k] * wr[k];
        hbuf[d] = gelu_exact(a);
    }
    __syncthreads();
    if (d < 8) {
        float a = b2[d];
        const float* wr = w2 + d * RH;
        for (int k = 0; k < RH; k++) a += hbuf[k] * wr[k];
        lg[d] = a;
    }
    __syncthreads();
    if (d == 0) {
        int is = 0; for (int i = 1; i < NEXP; i++) if (lg[i] > lg[is]) is = i;
        int it = 0; for (int i = 1; i < NEXP; i++) if (lg[NEXP+i] > lg[NEXP+it]) it = i;
        idx_s[b] = is;
        idx_t[b] = it;
    }
}

// ---------------------------------------------------------------------------
// LayerNorm over last dim (768): fp16 out (+ optional fp32 copy)
// ---------------------------------------------------------------------------
__global__ __launch_bounds__(256) void ln_kernel(const float* __restrict__ x,
                                                 const float* __restrict__ g,
                                                 const float* __restrict__ bb,
                                                 __half* __restrict__ yh,
                                                 float* __restrict__ yf)
{
    __shared__ float sd[256];
    ll row = blockIdx.x;
    int t = threadIdx.x;
    const float* xr = x + row * Dd;
    float a0 = xr[t], a1 = xr[t+256], a2 = xr[t+512];
    sd[t] = a0 + a1 + a2;
    __syncthreads();
    for (int s = 128; s > 0; s >>= 1) { if (t < s) sd[t] += sd[t+s]; __syncthreads(); }
    float mean = sd[0] * (1.0f / Dd);
    __syncthreads();
    float d0 = a0 - mean, d1 = a1 - mean, d2 = a2 - mean;
    sd[t] = d0*d0 + d1*d1 + d2*d2;
    __syncthreads();
    for (int s = 128; s > 0; s >>= 1) { if (t < s) sd[t] += sd[t+s]; __syncthreads(); }
    float inv = rsqrtf(sd[0] * (1.0f / Dd) + LN_EPS);
    float v0 = d0 * inv * g[t]     + bb[t];
    float v1 = d1 * inv * g[t+256] + bb[t+256];
    float v2 = d2 * inv * g[t+512] + bb[t+512];
    __half* yr = yh + row * Dd;
    yr[t]     = __float2half_rn(v0);
    yr[t+256] = __float2half_rn(v1);
    yr[t+512] = __float2half_rn(v2);
    if (yf) {
        float* yfr = yf + row * Dd;
        yfr[t] = v0; yfr[t+256] = v1; yfr[t+512] = v2;
    }
}

// ---------------------------------------------------------------------------
// Flash attention: one block = 64 queries x one (b,h). 128 threads, 4 warps,
// each warp owns 16 query rows. K/V tiles of 128 keys streamed via cp.async.
// Online softmax; P kept in registers (C-frag -> A-frag fp16 repack).
// ---------------------------------------------------------------------------
#define FL_KLD  104                    // halfs per smem row (96 + 8 pad)
#define FL_TILE (128 * FL_KLD)         // halfs per tile
#define FL_TILEB (FL_TILE * 2)         // 26624 bytes
#define FL_SMEM (3 * FL_TILEB)         // K + 2xV = 79872

__device__ __forceinline__ void fl_load_tile(const __half* gbase, int row0,
                                             __half* dstsm, int cr, int cc)
{
    #pragma unroll
    for (int rp = 0; rp < 4; rp++) {
        int r = rp * 32 + cr;
        const __half* src = gbase + (ll)(row0 + r) * D3 + cc;
        uint32_t dst = smem_u32(dstsm) + (uint32_t)((r * FL_KLD + cc) * 2);
        CP_ASYNC_16(dst,      src);
        CP_ASYNC_16(dst + 16, src + 8);
        CP_ASYNC_16(dst + 32, src + 16);
    }
}

__global__ __launch_bounds__(128, 2) void flash_kernel(
    const __half* __restrict__ QKV, __half* __restrict__ O, int causal)
{
    extern __shared__ __half fsm[];
    __half* Ksm = fsm;                 // FL_TILE
    __half* Vsm = fsm + FL_TILE;       // 2 x FL_TILE

    int qt = blockIdx.x, h = blockIdx.y, b = blockIdx.z;
    int q0 = qt * 64;
    int tid = threadIdx.x, lane = tid & 31, w = tid >> 5;
    int g = lane >> 2, t4 = lane & 3;

    const __half* Qg = QKV + (ll)b * (Tt * D3) + (ll)q0 * D3 + h * HD;
    const __half* Kg = QKV + (ll)b * (Tt * D3) + Dd + h * HD;
    const __half* Vg = Kg + Dd;

    int cr = tid >> 2;            // 0..31 (row within pass)
    int cc = (tid & 3) * 24;      // col chunk (24 halfs = 48B)

    // ---- stage Q (64 rows) through Ksm, extract fragments ----
    #pragma unroll
    for (int rp = 0; rp < 2; rp++) {
        int r = rp * 32 + cr;
        const __half* src = Qg + (ll)r * D3 + cc;
        uint32_t dst = smem_u32(Ksm) + (uint32_t)((r * FL_KLD + cc) * 2);
        CP_ASYNC_16(dst,      src);
        CP_ASYNC_16(dst + 16, src + 8);
        CP_ASYNC_16(dst + 32, src + 16);
    }
    CP_COMMIT(); CP_WAIT(0);
    __syncthreads();

    uint32_t qfr[6][4];
    {
        uint32_t aBase = smem_u32(Ksm) +
            (uint32_t)(((((lane & 15) + w * 16)) * FL_KLD + ((lane >> 4) << 3)) * 2);
        #pragma unroll
        for (int ks = 0; ks < 6; ks++) ldsm_x4(qfr[ks], aBase + ks * 32);
    }
    __syncthreads();

    int nk = causal ? ((q0 + 63) / 128 + 1) : (Tt / 128);

    // prologue loads
    fl_load_tile(Kg, 0, Ksm, cr, cc);
    fl_load_tile(Vg, 0, Vsm, cr, cc);
    CP_COMMIT();

    float mrow[2] = {-1e30f, -1e30f};
    float lrow[2] = {0.f, 0.f};
    float oacc[12][4];
    #pragma unroll
    for (int j = 0; j < 12; j++)
        #pragma unroll
        for (int q = 0; q < 4; q++) oacc[j][q] = 0.f;

    uint32_t kBase = smem_u32(Ksm) +
        (uint32_t)(((((lane & 7) + ((lane >> 4) << 3))) * FL_KLD + (((lane >> 3) & 1) << 3)) * 2);
    uint32_t vBase = smem_u32(Vsm) +
        (uint32_t)(((((lane & 7) + (((lane >> 3) & 1) << 3))) * FL_KLD + ((lane >> 4) << 3)) * 2);

    for (int kt = 0; kt < nk; kt++) {
        CP_WAIT(0);
        __syncthreads();
        int cur = kt & 1;

        // ---- S = scale * Q @ K^T  (16 rows x 128 keys per warp) ----
        float s[16][4];
        #pragma unroll
        for (int j = 0; j < 16; j++)
            #pragma unroll
            for (int q = 0; q < 4; q++) s[j][q] = 0.f;

        #pragma unroll
        for (int ks = 0; ks < 6; ks++) {
            #pragma unroll
            for (int jp = 0; jp < 8; jp++) {
                uint32_t rb[4];
                ldsm_x4(rb, kBase + jp * (16 * FL_KLD * 2) + ks * 32);
                mma_fp16(s[2*jp],   qfr[ks], rb);
                mma_fp16(s[2*jp+1], qfr[ks], rb + 2);
            }
        }

        bool domask = causal && (kt * 128 + 127 > q0);
        #pragma unroll
        for (int j = 0; j < 16; j++)
            #pragma unroll
            for (int q = 0; q < 4; q++) s[j][q] *= SCALE_V;
        if (domask) {
            int rbase = q0 + w * 16 + g;
            #pragma unroll
            for (int j = 0; j < 16; j++) {
                int key0 = kt * 128 + j * 8 + 2 * t4;
                #pragma unroll
                for (int q = 0; q < 4; q++) {
                    int key = key0 + (q & 1);
                    int row = rbase + ((q >> 1) << 3);
                    if (key > row) s[j][q] = -1e30f;
                }
            }
        }

        // ---- online softmax (rows g / g+8 per thread) ----
        uint32_t p[8][4];
        #pragma unroll
        for (int hf = 0; hf < 2; hf++) {
            float mx = -1e30f;
            #pragma unroll
            for (int j = 0; j < 16; j++)
                mx = fmaxf(mx, fmaxf(s[j][hf*2], s[j][hf*2+1]));
            mx = fmaxf(mx, __shfl_xor_sync(0xFFFFFFFFu, mx, 1));
            mx = fmaxf(mx, __shfl_xor_sync(0xFFFFFFFFu, mx, 2));
            float mnew = fmaxf(mrow[hf], mx);
            float corr = expf(mrow[hf] - mnew);
            mrow[hf] = mnew;
            float rsum = 0.f;
            #pragma unroll
            for (int j = 0; j < 16; j++) {
                float e0 = expf(s[j][hf*2]   - mnew);
                float e1 = expf(s[j][hf*2+1] - mnew);
                s[j][hf*2] = e0; s[j][hf*2+1] = e1;
                rsum += e0 + e1;
            }
            rsum += __shfl_xor_sync(0xFFFFFFFFu, rsum, 1);
            rsum += __shfl_xor_sync(0xFFFFFFFFu, rsum, 2);
            lrow[hf] = lrow[hf] * corr + rsum;
            #pragma unroll
            for (int j = 0; j < 12; j++) {
                oacc[j][hf*2]   *= corr;
                oacc[j][hf*2+1] *= corr;
            }
        }
        // pack P: C-frag pairs -> A-frags (16 keys per ksv)
        #pragma unroll
        for (int ksv = 0; ksv < 8; ksv++) {
            p[ksv][0] = packh2(s[2*ksv][0],   s[2*ksv][1]);
            p[ksv][1] = packh2(s[2*ksv][2],   s[2*ksv][3]);
            p[ksv][2] = packh2(s[2*ksv+1][0], s[2*ksv+1][1]);
            p[ksv][3] = packh2(s[2*ksv+1][2], s[2*ksv+1][3]);
        }

        __syncthreads();   // all warps done reading Ksm
        if (kt + 1 < nk) {
            fl_load_tile(Kg, (kt+1) * 128, Ksm, cr, cc);
            fl_load_tile(Vg, (kt+1) * 128, Vsm + (1 - cur) * FL_TILE, cr, cc);
            CP_COMMIT();
        }

        // ---- O += P @ V ----
        uint32_t vb = vBase + cur * FL_TILEB;
        #pragma unroll
        for (int ksv = 0; ksv < 8; ksv++) {
            #pragma unroll
            for (int jp = 0; jp < 6; jp++) {
                uint32_t rb[4];
                ldsm_x4_t(rb, vb + ksv * (16 * FL_KLD * 2) + jp * 32);
                mma_fp16(oacc[2*jp],   p[ksv], rb);
                mma_fp16(oacc[2*jp+1], p[ksv], rb + 2);
            }
        }
    }

    // ---- epilogue: O /= l ----
    #pragma unroll
    for (int hf = 0; hf < 2; hf++) {
        float inv = 1.f / lrow[hf];
        int r = q0 + w * 16 + g + hf * 8;
        __half* orow = O + (ll)b * (Tt * Dd) + (ll)r * Dd + h * HD;
        #pragma unroll
        for (int j = 0; j < 12; j++) {
            *(__half2*)(orow + j * 8 + 2 * t4) =
                __floats2half2_rn(oacc[j][hf*2] * inv, oacc[j][hf*2+1] * inv);
        }
    }
}

// ---------------------------------------------------------------------------
// FP16 tensor-core NT GEMM, 4-stage cp.async, ldmatrix fragments (unchanged).
// ---------------------------------------------------------------------------
#define ALD   40
#define ASTG  (128 * ALD)
#define ASTGB (ASTG * 2)
#define NT_SMEM (2 * STAGES * ASTGB)   // 81920

__global__ __launch_bounds__(256, 2) void hgemm_nt_kernel(
    const __half* __restrict__ A, int lda, ll bsA, ll hsA,
    const __half* __restrict__ W, int ldw, ll bsW, ll hsW,
    ll esW, const int* __restrict__ eidx,
    const float* __restrict__ bias, int esBias,
    const float* __restrict__ res, int ldr, ll bsR,
    void* __restrict__ Cv, int ldc, ll bsC, ll hsC, int cHalf,
    int Kd, int Hn, float alpha, int act)
{
    extern __shared__ __half hsm[];
    __half* Asm = hsm;
    __half* Wsm = hsm + STAGES * ASTG;

    int z = blockIdx.z;
    int b = z / Hn, h = z - b * Hn;
    A += (ll)b * bsA + (ll)h * hsA;
    ll woff = (ll)b * bsW + (ll)h * hsW;
    const float* biasp = bias;
    if (eidx) {
        int e = eidx[b];
        woff += (ll)e * esW;
        if (bias) biasp = bias + (ll)e * esBias;
    }
    W += woff;
    if (res) res += (ll)b * bsR;

    int tid = threadIdx.x, lane = tid & 31, warp = tid >> 5;
    int wm = warp & 3, wn = warp >> 2;
    int wmb = wm * 32, wnb = wn * 64;
    int g = lane >> 2, t4 = lane & 3;
    int m0 = blockIdx.y * 128, n0 = blockIdx.x * 128;

    int r0 = tid >> 2, c0 = (tid & 3) * 8;
    const __half* Ap = A + (ll)(m0 + r0) * lda + c0;
    const __half* Wp = W + (ll)(n0 + r0) * ldw + c0;
    ll ldA64 = (ll)64 * lda, ldW64 = (ll)64 * ldw;
    uint32_t dA = smem_u32(Asm) + (uint32_t)((r0 * ALD + c0) * 2);
    uint32_t dW = smem_u32(Wsm) + (uint32_t)((r0 * ALD + c0) * 2);
    const uint32_t rowOff = 64 * ALD * 2;

    float acc[2][8][4];
    #pragma unroll
    for (int i = 0; i < 2; i++)
        #pragma unroll
        for (int j = 0; j < 8; j++)
            #pragma unroll
            for (int q = 0; q < 4; q++) acc[i][j][q] = 0.f;

    uint32_t aBase = smem_u32(Asm) +
        (uint32_t)((((lane & 15) + wmb) * ALD + ((lane >> 4) << 3)) * 2);
    uint32_t bBase = smem_u32(Wsm) +
        (uint32_t)((((lane & 7) + ((lane >> 4) << 3) + wnb) * ALD + (((lane >> 3) & 1) << 3)) * 2);

    int kTiles = Kd >> 5;

    #pragma unroll
    for (int s = 0; s < STAGES - 1; s++) {
        if (s < kTiles) {
            const __half* a = Ap + s * 32;
            const __half* w = Wp + s * 32;
            CP_ASYNC_16(dA + s * ASTGB,          a);
            CP_ASYNC_16(dA + s * ASTGB + rowOff, a + ldA64);
            CP_ASYNC_16(dW + s * ASTGB,          w);
            CP_ASYNC_16(dW + s * ASTGB + rowOff, w + ldW64);
        }
        CP_COMMIT();
    }

    for (int kt = 0; kt < kTiles; kt++) {
        CP_WAIT(STAGES - 2);
        __syncthreads();

        int pf = kt + STAGES - 1;
        if (pf < kTiles) {
            int ps = pf & (STAGES - 1);
            const __half* a = Ap + pf * 32;
            const __half* w = Wp + pf * 32;
            CP_ASYNC_16(dA + ps * ASTGB,          a);
            CP_ASYNC_16(dA + ps * ASTGB + rowOff, a + ldA64);
            CP_ASYNC_16(dW + ps * ASTGB,          w);
            CP_ASYNC_16(dW + ps * ASTGB + rowOff, w + ldW64);
        }
        CP_COMMIT();

        uint32_t sa = aBase + (kt & (STAGES - 1)) * ASTGB;
        uint32_t sb = bBase + (kt & (STAGES - 1)) * ASTGB;
        #pragma unroll
        for (int ks = 0; ks < 2; ks++) {
            uint32_t afr[2][4], bfr[8][2];
            #pragma unroll
            for (int im = 0; im < 2; im++)
                ldsm_x4(afr[im], sa + im * (16 * ALD * 2) + ks * 32);
            #pragma unroll
            for (int jp = 0; jp < 4; jp++) {
                uint32_t rb[4];
                ldsm_x4(rb, sb + jp * (16 * ALD * 2) + ks * 32);
                bfr[2*jp][0]   = rb[0]; bfr[2*jp][1]   = rb[1];
                bfr[2*jp+1][0] = rb[2]; bfr[2*jp+1][1] = rb[3];
            }
            #pragma unroll
            for (int im = 0; im < 2; im++)
                #pragma unroll
                for (int jn = 0; jn < 8; jn++)
                    mma_fp16(acc[im][jn], afr[im], bfr[jn]);
        }
    }

    __half* Ch = (__half*)Cv;
    float*  Cf = (float*)Cv;
    ll cb = (ll)b * bsC + (ll)h * hsC;
    #pragma unroll
    for (int im = 0; im < 2; im++) {
        int rr0 = m0 + wmb + im * 16 + g;
        #pragma unroll
        for (int jn = 0; jn < 8; jn++) {
            int c = n0 + wnb + jn * 8 + 2 * t4;
            float bv0 = biasp ? biasp[c]     : 0.f;
            float bv1 = biasp ? biasp[c + 1] : 0.f;
            #pragma unroll
            for (int hf = 0; hf < 2; hf++) {
                int r = rr0 + hf * 8;
                float v0 = acc[im][jn][hf*2+0] * alpha + bv0;
                float v1 = acc[im][jn][hf*2+1] * alpha + bv1;
                if (act) { v0 = gelu_exact(v0); v1 = gelu_exact(v1); }
                if (res) {
                    const float* rp = res + (ll)r * ldr + c;
                    v0 += rp[0]; v1 += rp[1];
                }
                if (cHalf)
                    *(__half2*)(Ch + cb + (ll)r * ldc + c) = __floats2half2_rn(v0, v1);
                else
                    *(float2*)(Cf + cb + (ll)r * ldc + c) = make_float2(v0, v1);
            }
        }
    }
}

// ---------------------------------------------------------------------------
// Orchestration
// ---------------------------------------------------------------------------
extern "C" void kernel_launch(void* const* d_in, const int* in_sizes, int n_in,
                              void* d_out, int out_size)
{
    const float* x        = (const float*)d_in[0];
    const float* rw1      = (const float*)d_in[1];
    const float* rb1      = (const float*)d_in[2];
    const float* rw2      = (const float*)d_in[3];
    const float* rb2      = (const float*)d_in[4];
    const float* nsg      = (const float*)d_in[5];
    const float* nsb      = (const float*)d_in[6];
    const float* ntg      = (const float*)d_in[7];
    const float* ntb      = (const float*)d_in[8];
    const float* nmg      = (const float*)d_in[9];
    const float* nmb      = (const float*)d_in[10];
    const float* sp_wqkv  = (const float*)d_in[11];
    const float* sp_bqkv  = (const float*)d_in[12];
    const float* sp_wo    = (const float*)d_in[13];
    const float* sp_bo    = (const float*)d_in[14];
    const float* tp_wq    = (const float*)d_in[15];
    const float* tp_bq    = (const float*)d_in[16];
    const float* tp_wk    = (const float*)d_in[17];
    const float* tp_bk    = (const float*)d_in[18];
    const float* tp_wv    = (const float*)d_in[19];
    const float* tp_bv    = (const float*)d_in[20];
    const float* tp_wo    = (const float*)d_in[21];
    const float* tp_bo    = (const float*)d_in[22];
    const float* c_wqkv   = (const float*)d_in[23];
    const float* c_bqkv   = (const float*)d_in[24];
    const float* c_wo     = (const float*)d_in[25];
    const float* c_bo     = (const float*)d_in[26];
    const float* mlp_w1   = (const float*)d_in[27];
    const float* mlp_b1   = (const float*)d_in[28];
    const float* mlp_w2   = (const float*)d_in[29];
    const float* mlp_b2   = (const float*)d_in[30];
    float* out = (float*)d_out;

    static int attr_done = 0;
    if (!attr_done) {
        cudaFuncSetAttribute(hgemm_nt_kernel, cudaFuncAttributeMaxDynamicSharedMemorySize, NT_SMEM);
        cudaFuncSetAttribute(flash_kernel,    cudaFuncAttributeMaxDynamicSharedMemorySize, FL_SMEM);
        attr_done = 1;
    }

    float *xtf, *x1, *btp;
    __half *qkv, *qkv2, *xnh, *xth, *attno, *spout, *tpout, *hid;
    __half *wspqkv, *wspo, *wtpqkv, *wtpo, *wcqkv, *wco, *wm1, *wm2;
    int* idx;
    cudaGetSymbolAddress((void**)&qkv,    g_qkvh);
    cudaGetSymbolAddress((void**)&qkv2,   g_qkv2h);
    cudaGetSymbolAddress((void**)&xnh,    g_xnh);
    cudaGetSymbolAddress((void**)&xth,    g_xth);
    cudaGetSymbolAddress((void**)&xtf,    g_xtf);
    cudaGetSymbolAddress((void**)&attno,  g_attno);
    cudaGetSymbolAddress((void**)&spout,  g_spout);
    cudaGetSymbolAddress((void**)&tpout,  g_tpout);
    cudaGetSymbolAddress((void**)&x1,     g_x1);
    cudaGetSymbolAddress((void**)&hid,    g_hid);
    cudaGetSymbolAddress((void**)&idx,    g_idx);
    cudaGetSymbolAddress((void**)&btp,    g_btp);
    cudaGetSymbolAddress((void**)&wspqkv, g_wspqkv);
    cudaGetSymbolAddress((void**)&wspo,   g_wspo);
    cudaGetSymbolAddress((void**)&wtpqkv, g_wtpqkv);
    cudaGetSymbolAddress((void**)&wtpo,   g_wtpo);
    cudaGetSymbolAddress((void**)&wcqkv,  g_wcqkv);
    cudaGetSymbolAddress((void**)&wco,    g_wco);
    cudaGetSymbolAddress((void**)&wm1,    g_wm1);
    cudaGetSymbolAddress((void**)&wm2,    g_wm2);

    const ll rowsBT = (ll)Bz * Tt;
    const ll sQKV   = (ll)Tt * D3;
    const ll sD     = (ll)Tt * Dd;

    // ---- weight conversion (single kernel) + bias packing ----
    {
        int blocks = (int)((CONV_TOTAL / 4 + 255) / 256);
        convert_all_kernel<<<blocks, 256>>>(sp_wqkv, sp_wo, tp_wq, tp_wk, tp_wv,
                                            tp_wo, c_wqkv, c_wo, mlp_w1, mlp_w2);
        pack_btp_kernel<<<(NEXP*D3 + 255)/256, 256>>>(tp_bq, tp_bk, tp_bv);
    }

    // ---- router ----
    router_kernel<<<Bz, Dd>>>(x, rw1, rb1, rw2, rb2, idx, idx + 8);

    // ---- spatial branch ----
    ln_kernel<<<(int)rowsBT, 256>>>(x, nsg, nsb, xnh, nullptr);

    hgemm_nt_kernel<<<dim3(D3/128, Tt/128, Bz), 256, NT_SMEM>>>(
        xnh, Dd, sD, 0,
        wspqkv, Dd, 0, 0, (ll)D3 * Dd, idx,
        sp_bqkv, D3, nullptr, 0, 0,
        qkv, D3, sQKV, 0, 1,
        Dd, 1, 1.0f, 0);

    flash_kernel<<<dim3(Tt/64, Hh, Bz), 128, FL_SMEM>>>(qkv, attno, 0);

    hgemm_nt_kernel<<<dim3(Dd/128, Tt/128, Bz), 256, NT_SMEM>>>(
        attno, Dd, sD, 0,
        wspo, Dd, 0, 0, (ll)Dd * Dd, idx,
        sp_bo, Dd, nullptr, 0, 0,
        spout, Dd, sD, 0, 1,
        Dd, 1, 1.0f, 0);

    // ---- temporal branch ----
    ln_kernel<<<(int)rowsBT, 256>>>(x, ntg, ntb, xth, xtf);

    hgemm_nt_kernel<<<dim3(D3/128, Tt/128, Bz), 256, NT_SMEM>>>(
        xth, Dd, sD, 0,
        wtpqkv, Dd, 0, 0, (ll)D3 * Dd, idx + 8,
        btp, D3, nullptr, 0, 0,
        qkv2, D3, sQKV, 0, 1,
        Dd, 1, 1.0f, 0);

    flash_kernel<<<dim3(Tt/64, Hh, Bz), 128, FL_SMEM>>>(qkv2, attno, 1);

    hgemm_nt_kernel<<<dim3(Dd/128, Tt/128, Bz), 256, NT_SMEM>>>(
        attno, Dd, sD, 0,
        wtpo, Dd, 0, 0, (ll)Dd * Dd, idx + 8,
        tp_bo, Dd,
        xtf, Dd, sD,
        tpout, Dd, sD, 0, 1,
        Dd, 1, 1.0f, 0);

    // ---- cross attention ----
    hgemm_nt_kernel<<<dim3(Dd/128, Tt/128, Bz), 256, NT_SMEM>>>(
        spout, Dd, sD, 0,
        wcqkv, Dd, 0, 0, 0, nullptr,
        c_bqkv, 0, nullptr, 0, 0,
        qkv, D3, sQKV, 0, 1, Dd, 1, 1.0f, 0);
    hgemm_nt_kernel<<<dim3((2*Dd)/128, Tt/128, Bz), 256, NT_SMEM>>>(
        tpout, Dd, sD, 0,
        wcqkv + (ll)Dd * Dd, Dd, 0, 0, 0, nullptr,
        c_bqkv + Dd, 0, nullptr, 0, 0,
        qkv + Dd, D3, sQKV, 0, 1, Dd, 1, 1.0f, 0);

    flash_kernel<<<dim3(Tt/64, Hh, Bz), 128, FL_SMEM>>>(qkv, attno, 0);

    hgemm_nt_kernel<<<dim3(Dd/128, Tt/128, Bz), 256, NT_SMEM>>>(
        attno, Dd, sD, 0,
        wco, Dd, 0, 0, 0, nullptr,
        c_bo, 0,
        x, Dd, sD,
        x1, Dd, sD, 0, 0,
        Dd, 1, 1.0f, 0);

    // ---- MLP ----
    ln_kernel<<<(int)rowsBT, 256>>>(x1, nmg, nmb, xnh, nullptr);

    hgemm_nt_kernel<<<dim3(D4/128, (int)(rowsBT/128), 1), 256, NT_SMEM>>>(
        xnh, Dd, 0, 0,
        wm1, Dd, 0, 0, 0, nullptr,
        mlp_b1, 0, nullptr, 0, 0,
        hid, D4, 0, 0, 1,
        Dd, 1, 1.0f, 1);

    hgemm_nt_kernel<<<dim3(Dd/128, (int)(rowsBT/128), 1), 256, NT_SMEM>>>(
        hid, D4, 0, 0,
        wm2, D4, 0, 0, 0, nullptr,
        mlp_b2, 0,
        x1, Dd, 0,
        out, Dd, 0, 0, 0,
        D4, 1, 1.0f, 0);
}

// round 8
// speedup vs baseline: 6.3089x; 1.0144x over previous
#include <cuda_runtime.h>
#include <cuda_fp16.h>
#include <math.h>
#include <stdint.h>

typedef long long ll;

// ---------------------------------------------------------------------------
// Problem constants
// ---------------------------------------------------------------------------
#define Bz   8
#define Tt   512
#define Dd   768
#define Hh   8
#define HD   96
#define NEXP 4
#define RH   128
#define D3   (3*Dd)     // 2304
#define D4   (4*Dd)     // 3072
#define SCALE_V (0.10206207261596575f)  // 1/sqrt(96)
#define LN_EPS 1e-5f
#define STAGES 4

// ---------------------------------------------------------------------------
// Scratch (static device arrays -- no allocation allowed)
// ---------------------------------------------------------------------------
__device__ __half g_qkvh  [(ll)Bz*Tt*D3];
__device__ __half g_qkv2h [(ll)Bz*Tt*D3];
__device__ __half g_xnh   [(ll)Bz*Tt*Dd];
__device__ __half g_xth   [(ll)Bz*Tt*Dd];
__device__ float  g_xtf   [(ll)Bz*Tt*Dd];
__device__ __half g_attno [(ll)Bz*Tt*Dd];
__device__ __half g_attno2[(ll)Bz*Tt*Dd];
__device__ __half g_spout [(ll)Bz*Tt*Dd];
__device__ __half g_tpout [(ll)Bz*Tt*Dd];
__device__ float  g_x1    [(ll)Bz*Tt*Dd];
__device__ __half g_hid   [(ll)Bz*Tt*D4];
__device__ int    g_idx   [16];
__device__ float  g_btp   [(ll)NEXP*D3];
// fp16 weight copies
__device__ __half g_wspqkv[(ll)NEXP*D3*Dd];
__device__ __half g_wspo  [(ll)NEXP*Dd*Dd];
__device__ __half g_wtpqkv[(ll)NEXP*D3*Dd];   // packed q/k/v
__device__ __half g_wtpo  [(ll)NEXP*Dd*Dd];
__device__ __half g_wcqkv [(ll)3*Dd*Dd];
__device__ __half g_wco   [(ll)Dd*Dd];
__device__ __half g_wm1   [(ll)D4*Dd];
__device__ __half g_wm2   [(ll)Dd*D4];

__device__ __forceinline__ float gelu_exact(float v) {
    return 0.5f * v * (1.0f + erff(v * 0.70710678118654752f));
}
__device__ __forceinline__ uint32_t smem_u32(const void* p) {
    return (uint32_t)__cvta_generic_to_shared(p);
}

#define CP_ASYNC_16(dst_u32, src_ptr) \
    asm volatile("cp.async.cg.shared.global [%0], [%1], 16;\n" :: "r"(dst_u32), "l"(src_ptr))
#define CP_COMMIT() asm volatile("cp.async.commit_group;\n")
#define CP_WAIT(N)  asm volatile("cp.async.wait_group %0;\n" :: "n"(N))

__device__ __forceinline__ void ldsm_x4(uint32_t* r, uint32_t addr) {
    asm volatile("ldmatrix.sync.aligned.m8n8.x4.shared.b16 {%0,%1,%2,%3}, [%4];"
        : "=r"(r[0]), "=r"(r[1]), "=r"(r[2]), "=r"(r[3]) : "r"(addr));
}
__device__ __forceinline__ void ldsm_x4_t(uint32_t* r, uint32_t addr) {
    asm volatile("ldmatrix.sync.aligned.m8n8.x4.trans.shared.b16 {%0,%1,%2,%3}, [%4];"
        : "=r"(r[0]), "=r"(r[1]), "=r"(r[2]), "=r"(r[3]) : "r"(addr));
}
__device__ __forceinline__ void mma_fp16(float* c, const uint32_t* a, const uint32_t* b) {
    asm volatile(
        "mma.sync.aligned.m16n8k16.row.col.f32.f16.f16.f32 "
        "{%0,%1,%2,%3}, {%4,%5,%6,%7}, {%8,%9}, {%0,%1,%2,%3};"
        : "+f"(c[0]), "+f"(c[1]), "+f"(c[2]), "+f"(c[3])
        : "r"(a[0]), "r"(a[1]), "r"(a[2]), "r"(a[3]),
          "r"(b[0]), "r"(b[1]));
}
__device__ __forceinline__ uint32_t packh2(float a, float b) {
    __half2 h = __floats2half2_rn(a, b);
    return *(uint32_t*)&h;
}

// ---------------------------------------------------------------------------
// Mega weight convert + temporal qkv packing
// ---------------------------------------------------------------------------
#define SEG_SPQKV ((ll)NEXP*D3*Dd)
#define SEG_DD    ((ll)NEXP*Dd*Dd)
#define SEG_CQKV  ((ll)3*Dd*Dd)
#define SEG_CO    ((ll)Dd*Dd)
#define SEG_M     ((ll)D4*Dd)
#define CONV_TOTAL (SEG_SPQKV + SEG_DD + 3*SEG_DD + SEG_DD + SEG_CQKV + SEG_CO + 2*SEG_M)

__device__ __forceinline__ void cvt4(__half* d, const float* s) {
    float4 v = *(const float4*)s;
    *(__half2*)(d)     = __floats2half2_rn(v.x, v.y);
    *(__half2*)(d + 2) = __floats2half2_rn(v.z, v.w);
}

__global__ __launch_bounds__(256) void convert_all_kernel(
    const float* __restrict__ spqkv, const float* __restrict__ spo,
    const float* __restrict__ tq, const float* __restrict__ tk,
    const float* __restrict__ tv, const float* __restrict__ to,
    const float* __restrict__ cqkv, const float* __restrict__ cwo,
    const float* __restrict__ m1, const float* __restrict__ m2)
{
    ll i = ((ll)blockIdx.x * 256 + threadIdx.x) * 4;
    if (i >= CONV_TOTAL) return;
    ll o = i;
    if (o < SEG_SPQKV) { cvt4(g_wspqkv + o, spqkv + o); return; }
    o -= SEG_SPQKV;
    if (o < SEG_DD)    { cvt4(g_wspo + o, spo + o); return; }
    o -= SEG_DD;
    if (o < SEG_DD) {
        ll e = o / SEG_CO, rem = o - e * SEG_CO;
        cvt4(g_wtpqkv + e * ((ll)D3*Dd) + rem, tq + o); return;
    }
    o -= SEG_DD;
    if (o < SEG_DD) {
        ll e = o / SEG_CO, rem = o - e * SEG_CO;
        cvt4(g_wtpqkv + e * ((ll)D3*Dd) + (ll)Dd*Dd + rem, tk + o); return;
    }
    o -= SEG_DD;
    if (o < SEG_DD) {
        ll e = o / SEG_CO, rem = o - e * SEG_CO;
        cvt4(g_wtpqkv + e * ((ll)D3*Dd) + (ll)2*Dd*Dd + rem, tv + o); return;
    }
    o -= SEG_DD;
    if (o < SEG_DD)   { cvt4(g_wtpo + o, to + o); return; }
    o -= SEG_DD;
    if (o < SEG_CQKV) { cvt4(g_wcqkv + o, cqkv + o); return; }
    o -= SEG_CQKV;
    if (o < SEG_CO)   { cvt4(g_wco + o, cwo + o); return; }
    o -= SEG_CO;
    if (o < SEG_M)    { cvt4(g_wm1 + o, m1 + o); return; }
    o -= SEG_M;
    cvt4(g_wm2 + o, m2 + o);
}

__global__ void pack_btp_kernel(const float* __restrict__ bq,
                                const float* __restrict__ bk,
                                const float* __restrict__ bv)
{
    int i = blockIdx.x * 256 + threadIdx.x;
    if (i >= NEXP * D3) return;
    int e = i / D3, j = i - e * D3;
    float v = (j < Dd) ? bq[e*Dd + j] : (j < 2*Dd) ? bk[e*Dd + j - Dd] : bv[e*Dd + j - 2*Dd];
    g_btp[i] = v;
}

// ---------------------------------------------------------------------------
// Router
// ---------------------------------------------------------------------------
__global__ void router_kernel(const float* __restrict__ x,
                              const float* __restrict__ w1, const float* __restrict__ b1,
                              const float* __restrict__ w2, const float* __restrict__ b2,
                              int* __restrict__ idx_s, int* __restrict__ idx_t)
{
    __shared__ float xm[Dd];
    __shared__ float hbuf[RH];
    __shared__ float lg[8];
    int b = blockIdx.x;
    int d = threadIdx.x;
    const float* xb = x + (ll)b * Tt * Dd;
    float s = 0.f;
    for (int t = 0; t < Tt; t++) s += xb[(ll)t * Dd + d];
    xm[d] = s * (1.0f / Tt);
    __syncthreads();
    if (d < RH) {
        float a = b1[d];
        const float* wr = w1 + (ll)d * Dd;
        for (int k = 0; k < Dd; k++) a += xm[k] * wr[k];
        hbuf[d] = gelu_exact(a);
    }
    __syncthreads();
    if (d < 8) {
        float a = b2[d];
        const float* wr = w2 + d * RH;
        for (int k = 0; k < RH; k++) a += hbuf[k] * wr[k];
        lg[d] = a;
    }
    __syncthreads();
    if (d == 0) {
        int is = 0; for (int i = 1; i < NEXP; i++) if (lg[i] > lg[is]) is = i;
        int it = 0; for (int i = 1; i < NEXP; i++) if (lg[NEXP+i] > lg[NEXP+it]) it = i;
        idx_s[b] = is;
        idx_t[b] = it;
    }
}

// ---------------------------------------------------------------------------
// LayerNorm (dual-set): single-pass sum/sumsq, warp-shuffle reduce.
// grid = nsets*4096; set = blockIdx.x >> 12.
// ---------------------------------------------------------------------------
__global__ __launch_bounds__(256) void ln_kernel(const float* __restrict__ x,
    const float* __restrict__ g0, const float* __restrict__ b0,
    __half* __restrict__ yh0, float* __restrict__ yf0,
    const float* __restrict__ g1, const float* __restrict__ b1,
    __half* __restrict__ yh1, float* __restrict__ yf1)
{
    __shared__ float2 sw[8];
    int set = blockIdx.x >> 12;
    ll row = blockIdx.x & 4095;
    const float* g = set ? g1 : g0;
    const float* bb = set ? b1 : b0;
    __half* yh = set ? yh1 : yh0;
    float* yf = set ? yf1 : yf0;

    int t = threadIdx.x, lane = t & 31, wid = t >> 5;
    const float* xr = x + row * Dd;
    float a0 = xr[t], a1 = xr[t+256], a2 = xr[t+512];
    float s = a0 + a1 + a2;
    float s2 = a0*a0 + a1*a1 + a2*a2;
    #pragma unroll
    for (int o = 16; o; o >>= 1) {
        s  += __shfl_xor_sync(0xFFFFFFFFu, s, o);
        s2 += __shfl_xor_sync(0xFFFFFFFFu, s2, o);
    }
    if (lane == 0) sw[wid] = make_float2(s, s2);
    __syncthreads();
    if (t < 8) {
        float2 v = sw[t];
        float u = v.x, u2 = v.y;
        #pragma unroll
        for (int o = 4; o; o >>= 1) {
            u  += __shfl_xor_sync(0xFFu, u, o);
            u2 += __shfl_xor_sync(0xFFu, u2, o);
        }
        if (t == 0) sw[0] = make_float2(u, u2);
    }
    __syncthreads();
    float2 tot = sw[0];
    float mean = tot.x * (1.0f / Dd);
    float var = tot.y * (1.0f / Dd) - mean * mean;
    float inv = rsqrtf(var + LN_EPS);
    float v0 = (a0 - mean) * inv * g[t]     + bb[t];
    float v1 = (a1 - mean) * inv * g[t+256] + bb[t+256];
    float v2 = (a2 - mean) * inv * g[t+512] + bb[t+512];
    __half* yr = yh + row * Dd;
    yr[t]     = __float2half_rn(v0);
    yr[t+256] = __float2half_rn(v1);
    yr[t+512] = __float2half_rn(v2);
    if (yf) {
        float* yfr = yf + row * Dd;
        yfr[t] = v0; yfr[t+256] = v1; yfr[t+512] = v2;
    }
}

// ---------------------------------------------------------------------------
// Flash attention (dual-set): 256 threads, 128 queries/block, 8 warps.
// K/V tiles of 128 keys; online softmax; P in registers.
// ---------------------------------------------------------------------------
#define FL_KLD  104
#define FL_TILE (128 * FL_KLD)
#define FL_TILEB (FL_TILE * 2)
#define FL_SMEM (3 * FL_TILEB)         // 79872

__device__ __forceinline__ void fl_load_tile(const __half* gbase, int row0,
                                             __half* dstsm, int cr, int cc)
{
    #pragma unroll
    for (int rp = 0; rp < 2; rp++) {
        int r = rp * 64 + cr;
        const __half* src = gbase + (ll)(row0 + r) * D3 + cc;
        uint32_t dst = smem_u32(dstsm) + (uint32_t)((r * FL_KLD + cc) * 2);
        CP_ASYNC_16(dst,      src);
        CP_ASYNC_16(dst + 16, src + 8);
        CP_ASYNC_16(dst + 32, src + 16);
    }
}

__global__ __launch_bounds__(256, 1) void flash_kernel(
    const __half* __restrict__ QKVa, __half* __restrict__ Oa, int causalA,
    const __half* __restrict__ QKVb, __half* __restrict__ Ob, int causalB)
{
    extern __shared__ __half fsm[];
    __half* Ksm = fsm;
    __half* Vsm = fsm + FL_TILE;

    int z = blockIdx.z;
    const __half* QKV; __half* O; int causal; int b;
    if (z < Bz) { QKV = QKVa; O = Oa; causal = causalA; b = z; }
    else        { QKV = QKVb; O = Ob; causal = causalB; b = z - Bz; }

    int qt = blockIdx.x, h = blockIdx.y;
    int q0 = qt * 128;
    int tid = threadIdx.x, lane = tid & 31, w = tid >> 5;
    int g = lane >> 2, t4 = lane & 3;

    const __half* Qg = QKV + (ll)b * (Tt * D3) + (ll)q0 * D3 + h * HD;
    const __half* Kg = QKV + (ll)b * (Tt * D3) + Dd + h * HD;
    const __half* Vg = Kg + Dd;

    int cr = tid >> 2;            // 0..63
    int cc = (tid & 3) * 24;

    // ---- stage Q (128 rows) through Ksm, extract fragments ----
    #pragma unroll
    for (int rp = 0; rp < 2; rp++) {
        int r = rp * 64 + cr;
        const __half* src = Qg + (ll)r * D3 + cc;
        uint32_t dst = smem_u32(Ksm) + (uint32_t)((r * FL_KLD + cc) * 2);
        CP_ASYNC_16(dst,      src);
        CP_ASYNC_16(dst + 16, src + 8);
        CP_ASYNC_16(dst + 32, src + 16);
    }
    CP_COMMIT(); CP_WAIT(0);
    __syncthreads();

    uint32_t qfr[6][4];
    {
        uint32_t aBase = smem_u32(Ksm) +
            (uint32_t)(((((lane & 15) + w * 16)) * FL_KLD + ((lane >> 4) << 3)) * 2);
        #pragma unroll
        for (int ks = 0; ks < 6; ks++) ldsm_x4(qfr[ks], aBase + ks * 32);
    }
    __syncthreads();

    int nk = causal ? (q0 / 128 + 1) : (Tt / 128);

    fl_load_tile(Kg, 0, Ksm, cr, cc);
    fl_load_tile(Vg, 0, Vsm, cr, cc);
    CP_COMMIT();

    float mrow[2] = {-1e30f, -1e30f};
    float lrow[2] = {0.f, 0.f};
    float oacc[12][4];
    #pragma unroll
    for (int j = 0; j < 12; j++)
        #pragma unroll
        for (int q = 0; q < 4; q++) oacc[j][q] = 0.f;

    uint32_t kBase = smem_u32(Ksm) +
        (uint32_t)(((((lane & 7) + ((lane >> 4) << 3))) * FL_KLD + (((lane >> 3) & 1) << 3)) * 2);
    uint32_t vBase = smem_u32(Vsm) +
        (uint32_t)(((((lane & 7) + (((lane >> 3) & 1) << 3))) * FL_KLD + ((lane >> 4) << 3)) * 2);

    for (int kt = 0; kt < nk; kt++) {
        CP_WAIT(0);
        __syncthreads();
        int cur = kt & 1;

        float s[16][4];
        #pragma unroll
        for (int j = 0; j < 16; j++)
            #pragma unroll
            for (int q = 0; q < 4; q++) s[j][q] = 0.f;

        #pragma unroll
        for (int ks = 0; ks < 6; ks++) {
            #pragma unroll
            for (int jp = 0; jp < 8; jp++) {
                uint32_t rb[4];
                ldsm_x4(rb, kBase + jp * (16 * FL_KLD * 2) + ks * 32);
                mma_fp16(s[2*jp],   qfr[ks], rb);
                mma_fp16(s[2*jp+1], qfr[ks], rb + 2);
            }
        }

        bool domask = causal && (kt * 128 + 127 > q0);
        #pragma unroll
        for (int j = 0; j < 16; j++)
            #pragma unroll
            for (int q = 0; q < 4; q++) s[j][q] *= SCALE_V;
        if (domask) {
            int rbase = q0 + w * 16 + g;
            #pragma unroll
            for (int j = 0; j < 16; j++) {
                int key0 = kt * 128 + j * 8 + 2 * t4;
                #pragma unroll
                for (int q = 0; q < 4; q++) {
                    int key = key0 + (q & 1);
                    int row = rbase + ((q >> 1) << 3);
                    if (key > row) s[j][q] = -1e30f;
                }
            }
        }

        uint32_t p[8][4];
        #pragma unroll
        for (int hf = 0; hf < 2; hf++) {
            float mx = -1e30f;
            #pragma unroll
            for (int j = 0; j < 16; j++)
                mx = fmaxf(mx, fmaxf(s[j][hf*2], s[j][hf*2+1]));
            mx = fmaxf(mx, __shfl_xor_sync(0xFFFFFFFFu, mx, 1));
            mx = fmaxf(mx, __shfl_xor_sync(0xFFFFFFFFu, mx, 2));
            float mnew = fmaxf(mrow[hf], mx);
            float corr = expf(mrow[hf] - mnew);
            mrow[hf] = mnew;
            float rsum = 0.f;
            #pragma unroll
            for (int j = 0; j < 16; j++) {
                float e0 = expf(s[j][hf*2]   - mnew);
                float e1 = expf(s[j][hf*2+1] - mnew);
                s[j][hf*2] = e0; s[j][hf*2+1] = e1;
                rsum += e0 + e1;
            }
            rsum += __shfl_xor_sync(0xFFFFFFFFu, rsum, 1);
            rsum += __shfl_xor_sync(0xFFFFFFFFu, rsum, 2);
            lrow[hf] = lrow[hf] * corr + rsum;
            #pragma unroll
            for (int j = 0; j < 12; j++) {
                oacc[j][hf*2]   *= corr;
                oacc[j][hf*2+1] *= corr;
            }
        }
        #pragma unroll
        for (int ksv = 0; ksv < 8; ksv++) {
            p[ksv][0] = packh2(s[2*ksv][0],   s[2*ksv][1]);
            p[ksv][1] = packh2(s[2*ksv][2],   s[2*ksv][3]);
            p[ksv][2] = packh2(s[2*ksv+1][0], s[2*ksv+1][1]);
            p[ksv][3] = packh2(s[2*ksv+1][2], s[2*ksv+1][3]);
        }

        __syncthreads();
        if (kt + 1 < nk) {
            fl_load_tile(Kg, (kt+1) * 128, Ksm, cr, cc);
            fl_load_tile(Vg, (kt+1) * 128, Vsm + (1 - cur) * FL_TILE, cr, cc);
            CP_COMMIT();
        }

        uint32_t vb = vBase + cur * FL_TILEB;
        #pragma unroll
        for (int ksv = 0; ksv < 8; ksv++) {
            #pragma unroll
            for (int jp = 0; jp < 6; jp++) {
                uint32_t rb[4];
                ldsm_x4_t(rb, vb + ksv * (16 * FL_KLD * 2) + jp * 32);
                mma_fp16(oacc[2*jp],   p[ksv], rb);
                mma_fp16(oacc[2*jp+1], p[ksv], rb + 2);
            }
        }
    }

    #pragma unroll
    for (int hf = 0; hf < 2; hf++) {
        float inv = 1.f / lrow[hf];
        int r = q0 + w * 16 + g + hf * 8;
        __half* orow = O + (ll)b * (Tt * Dd) + (ll)r * Dd + h * HD;
        #pragma unroll
        for (int j = 0; j < 12; j++) {
            *(__half2*)(orow + j * 8 + 2 * t4) =
                __floats2half2_rn(oacc[j][hf*2] * inv, oacc[j][hf*2+1] * inv);
        }
    }
}

// ---------------------------------------------------------------------------
// FP16 NT GEMM engine: 128 threads, 4 warps (2m x 2n), warp tile 64x64,
// block 128x128, BK=32, 4-stage cp.async.
// ---------------------------------------------------------------------------
#define ALD   40
#define ASTG  (128 * ALD)
#define ASTGB (ASTG * 2)
#define NT_SMEM (2 * STAGES * ASTGB)   // 81920

struct GemmP {
    const __half* A;     // [rows, Kd], batch stride Tt*Kd
    const __half* W;     // [N, Kd] (+ expert stride)
    ll esW;
    const int* eidx;
    const float* bias;   // fp32 [N] (+ expert stride esBias)
    int esBias;
    const float* res;    // fp32 [rows, Dd], batch stride Tt*Dd
    void* C;             // ldc, batch stride Tt*ldc
    int ldc;
    int cHalf;
    int Kd;
    int act;
};

__device__ __forceinline__ void gemm_body(const GemmP p, int b, int m0, int n0)
{
    extern __shared__ __half hsm[];
    __half* Asm = hsm;
    __half* Wsm = hsm + STAGES * ASTG;

    const __half* A = p.A + (ll)b * Tt * p.Kd;
    ll woff = 0;
    const float* biasp = p.bias;
    if (p.eidx) {
        int e = p.eidx[b];
        woff = (ll)e * p.esW;
        if (biasp) biasp += (ll)e * p.esBias;
    }
    const __half* W = p.W + woff;
    const float* res = p.res ? (p.res + (ll)b * (Tt * Dd)) : nullptr;

    int tid = threadIdx.x, lane = tid & 31, warp = tid >> 5;
    int wm = warp & 1, wn = warp >> 1;
    int wmb = wm * 64, wnb = wn * 64;
    int g = lane >> 2, t4 = lane & 3;

    int r0 = tid >> 2, c0 = (tid & 3) * 8;
    const __half* Ap = A + (ll)(m0 + r0) * p.Kd + c0;
    const __half* Wp = W + (ll)(n0 + r0) * p.Kd + c0;
    uint32_t dA = smem_u32(Asm) + (uint32_t)((r0 * ALD + c0) * 2);
    uint32_t dW = smem_u32(Wsm) + (uint32_t)((r0 * ALD + c0) * 2);
    ll rowStep = (ll)32 * p.Kd;

    float acc[4][8][4];
    #pragma unroll
    for (int i = 0; i < 4; i++)
        #pragma unroll
        for (int j = 0; j < 8; j++)
            #pragma unroll
            for (int q = 0; q < 4; q++) acc[i][j][q] = 0.f;

    uint32_t aBase = smem_u32(Asm) +
        (uint32_t)((((lane & 15) + wmb) * ALD + ((lane >> 4) << 3)) * 2);
    uint32_t bBase = smem_u32(Wsm) +
        (uint32_t)((((lane & 7) + ((lane >> 4) << 3) + wnb) * ALD + (((lane >> 3) & 1) << 3)) * 2);

    int kTiles = p.Kd >> 5;

    #pragma unroll
    for (int s = 0; s < STAGES - 1; s++) {
        if (s < kTiles) {
            const __half* a = Ap + s * 32;
            const __half* w = Wp + s * 32;
            #pragma unroll
            for (int rp = 0; rp < 4; rp++) {
                CP_ASYNC_16(dA + s * ASTGB + rp * (32 * ALD * 2), a + rp * rowStep);
                CP_ASYNC_16(dW + s * ASTGB + rp * (32 * ALD * 2), w + rp * rowStep);
            }
        }
        CP_COMMIT();
    }

    for (int kt = 0; kt < kTiles; kt++) {
        CP_WAIT(STAGES - 2);
        __syncthreads();

        int pf = kt + STAGES - 1;
        if (pf < kTiles) {
            int ps = pf & (STAGES - 1);
            const __half* a = Ap + pf * 32;
            const __half* w = Wp + pf * 32;
            #pragma unroll
            for (int rp = 0; rp < 4; rp++) {
                CP_ASYNC_16(dA + ps * ASTGB + rp * (32 * ALD * 2), a + rp * rowStep);
                CP_ASYNC_16(dW + ps * ASTGB + rp * (32 * ALD * 2), w + rp * rowStep);
            }
        }
        CP_COMMIT();

        uint32_t sa = aBase + (kt & (STAGES - 1)) * ASTGB;
        uint32_t sb = bBase + (kt & (STAGES - 1)) * ASTGB;
        #pragma unroll
        for (int ks = 0; ks < 2; ks++) {
            uint32_t afr[4][4], bfr[8][2];
            #pragma unroll
            for (int im = 0; im < 4; im++)
                ldsm_x4(afr[im], sa + im * (16 * ALD * 2) + ks * 32);
            #pragma unroll
            for (int jp = 0; jp < 4; jp++) {
                uint32_t rb[4];
                ldsm_x4(rb, sb + jp * (16 * ALD * 2) + ks * 32);
                bfr[2*jp][0]   = rb[0]; bfr[2*jp][1]   = rb[1];
                bfr[2*jp+1][0] = rb[2]; bfr[2*jp+1][1] = rb[3];
            }
            #pragma unroll
            for (int im = 0; im < 4; im++)
                #pragma unroll
                for (int jn = 0; jn < 8; jn++)
                    mma_fp16(acc[im][jn], afr[im], bfr[jn]);
        }
    }

    __half* Ch = (__half*)p.C;
    float*  Cf = (float*)p.C;
    ll cb = (ll)b * Tt * p.ldc;
    #pragma unroll
    for (int im = 0; im < 4; im++) {
        int rr0 = m0 + wmb + im * 16 + g;
        #pragma unroll
        for (int jn = 0; jn < 8; jn++) {
            int c = n0 + wnb + jn * 8 + 2 * t4;
            float bv0 = biasp ? biasp[c]     : 0.f;
            float bv1 = biasp ? biasp[c + 1] : 0.f;
            #pragma unroll
            for (int hf = 0; hf < 2; hf++) {
                int r = rr0 + hf * 8;
                float v0 = acc[im][jn][hf*2+0] + bv0;
                float v1 = acc[im][jn][hf*2+1] + bv1;
                if (p.act) { v0 = gelu_exact(v0); v1 = gelu_exact(v1); }
                if (res) {
                    const float* rp2 = res + (ll)r * Dd + c;
                    v0 += rp2[0]; v1 += rp2[1];
                }
                if (p.cHalf)
                    *(__half2*)(Ch + cb + (ll)r * p.ldc + c) = __floats2half2_rn(v0, v1);
                else
                    *(float2*)(Cf + cb + (ll)r * p.ldc + c) = make_float2(v0, v1);
            }
        }
    }
}

__global__ __launch_bounds__(128, 2) void hgemm_one(GemmP p) {
    gemm_body(p, blockIdx.z, blockIdx.y * 128, blockIdx.x * 128);
}
__global__ __launch_bounds__(128, 2) void hgemm_dualz(GemmP p0, GemmP p1) {
    int z = blockIdx.z;
    if (z < Bz) gemm_body(p0, z, blockIdx.y * 128, blockIdx.x * 128);
    else        gemm_body(p1, z - Bz, blockIdx.y * 128, blockIdx.x * 128);
}
__global__ __launch_bounds__(128, 2) void hgemm_dualx(GemmP p0, GemmP p1, int xsplit) {
    int xb = blockIdx.x;
    if (xb < xsplit) gemm_body(p0, blockIdx.z, blockIdx.y * 128, xb * 128);
    else             gemm_body(p1, blockIdx.z, blockIdx.y * 128, (xb - xsplit) * 128);
}

// ---------------------------------------------------------------------------
// Orchestration
// ---------------------------------------------------------------------------
extern "C" void kernel_launch(void* const* d_in, const int* in_sizes, int n_in,
                              void* d_out, int out_size)
{
    const float* x        = (const float*)d_in[0];
    const float* rw1      = (const float*)d_in[1];
    const float* rb1      = (const float*)d_in[2];
    const float* rw2      = (const float*)d_in[3];
    const float* rb2      = (const float*)d_in[4];
    const float* nsg      = (const float*)d_in[5];
    const float* nsb      = (const float*)d_in[6];
    const float* ntg      = (const float*)d_in[7];
    const float* ntb      = (const float*)d_in[8];
    const float* nmg      = (const float*)d_in[9];
    const float* nmb      = (const float*)d_in[10];
    const float* sp_wqkv  = (const float*)d_in[11];
    const float* sp_bqkv  = (const float*)d_in[12];
    const float* sp_wo    = (const float*)d_in[13];
    const float* sp_bo    = (const float*)d_in[14];
    const float* tp_wq    = (const float*)d_in[15];
    const float* tp_bq    = (const float*)d_in[16];
    const float* tp_wk    = (const float*)d_in[17];
    const float* tp_bk    = (const float*)d_in[18];
    const float* tp_wv    = (const float*)d_in[19];
    const float* tp_bv    = (const float*)d_in[20];
    const float* tp_wo    = (const float*)d_in[21];
    const float* tp_bo    = (const float*)d_in[22];
    const float* c_wqkv   = (const float*)d_in[23];
    const float* c_bqkv   = (const float*)d_in[24];
    const float* c_wo     = (const float*)d_in[25];
    const float* c_bo     = (const float*)d_in[26];
    const float* mlp_w1   = (const float*)d_in[27];
    const float* mlp_b1   = (const float*)d_in[28];
    const float* mlp_w2   = (const float*)d_in[29];
    const float* mlp_b2   = (const float*)d_in[30];
    float* out = (float*)d_out;

    static int attr_done = 0;
    if (!attr_done) {
        cudaFuncSetAttribute(hgemm_one,   cudaFuncAttributeMaxDynamicSharedMemorySize, NT_SMEM);
        cudaFuncSetAttribute(hgemm_dualz, cudaFuncAttributeMaxDynamicSharedMemorySize, NT_SMEM);
        cudaFuncSetAttribute(hgemm_dualx, cudaFuncAttributeMaxDynamicSharedMemorySize, NT_SMEM);
        cudaFuncSetAttribute(flash_kernel, cudaFuncAttributeMaxDynamicSharedMemorySize, FL_SMEM);
        attr_done = 1;
    }

    float *xtf, *x1, *btp;
    __half *qkv, *qkv2, *xnh, *xth, *attno, *attno2, *spout, *tpout, *hid;
    __half *wspqkv, *wspo, *wtpqkv, *wtpo, *wcqkv, *wco, *wm1, *wm2;
    int* idx;
    cudaGetSymbolAddress((void**)&qkv,    g_qkvh);
    cudaGetSymbolAddress((void**)&qkv2,   g_qkv2h);
    cudaGetSymbolAddress((void**)&xnh,    g_xnh);
    cudaGetSymbolAddress((void**)&xth,    g_xth);
    cudaGetSymbolAddress((void**)&xtf,    g_xtf);
    cudaGetSymbolAddress((void**)&attno,  g_attno);
    cudaGetSymbolAddress((void**)&attno2, g_attno2);
    cudaGetSymbolAddress((void**)&spout,  g_spout);
    cudaGetSymbolAddress((void**)&tpout,  g_tpout);
    cudaGetSymbolAddress((void**)&x1,     g_x1);
    cudaGetSymbolAddress((void**)&hid,    g_hid);
    cudaGetSymbolAddress((void**)&idx,    g_idx);
    cudaGetSymbolAddress((void**)&btp,    g_btp);
    cudaGetSymbolAddress((void**)&wspqkv, g_wspqkv);
    cudaGetSymbolAddress((void**)&wspo,   g_wspo);
    cudaGetSymbolAddress((void**)&wtpqkv, g_wtpqkv);
    cudaGetSymbolAddress((void**)&wtpo,   g_wtpo);
    cudaGetSymbolAddress((void**)&wcqkv,  g_wcqkv);
    cudaGetSymbolAddress((void**)&wco,    g_wco);
    cudaGetSymbolAddress((void**)&wm1,    g_wm1);
    cudaGetSymbolAddress((void**)&wm2,    g_wm2);

    // ---- weight conversion + bias packing + router ----
    {
        int blocks = (int)((CONV_TOTAL / 4 + 255) / 256);
        convert_all_kernel<<<blocks, 256>>>(sp_wqkv, sp_wo, tp_wq, tp_wk, tp_wv,
                                            tp_wo, c_wqkv, c_wo, mlp_w1, mlp_w2);
        pack_btp_kernel<<<(NEXP*D3 + 255)/256, 256>>>(tp_bq, tp_bk, tp_bv);
    }
    router_kernel<<<Bz, Dd>>>(x, rw1, rb1, rw2, rb2, idx, idx + 8);

    // ---- LN (spatial + temporal fused) ----
    ln_kernel<<<2 * 4096, 256>>>(x, nsg, nsb, xnh, nullptr, ntg, ntb, xth, xtf);

    // ---- QKV GEMMs (spatial + temporal fused) ----
    {
        GemmP p0 = { xnh, wspqkv, (ll)D3 * Dd, idx,     sp_bqkv, D3, nullptr, qkv,  D3, 1, Dd, 0 };
        GemmP p1 = { xth, wtpqkv, (ll)D3 * Dd, idx + 8, btp,     D3, nullptr, qkv2, D3, 1, Dd, 0 };
        hgemm_dualz<<<dim3(D3/128, Tt/128, 2*Bz), 128, NT_SMEM>>>(p0, p1);
    }

    // ---- flash (spatial non-causal + temporal causal fused) ----
    flash_kernel<<<dim3(Tt/128, Hh, 2*Bz), 256, FL_SMEM>>>(qkv, attno, 0, qkv2, attno2, 1);

    // ---- output projections (spatial + temporal fused) ----
    {
        GemmP p0 = { attno,  wspo, (ll)Dd * Dd, idx,     sp_bo, Dd, nullptr, spout, Dd, 1, Dd, 0 };
        GemmP p1 = { attno2, wtpo, (ll)Dd * Dd, idx + 8, tp_bo, Dd, xtf,     tpout, Dd, 1, Dd, 0 };
        hgemm_dualz<<<dim3(Dd/128, Tt/128, 2*Bz), 128, NT_SMEM>>>(p0, p1);
    }

    // ---- cross q (from spout) + cross kv (from tpout), fused over grid.x ----
    {
        GemmP p0 = { spout, wcqkv,                0, nullptr, c_bqkv,      0, nullptr, qkv,      D3, 1, Dd, 0 };
        GemmP p1 = { tpout, wcqkv + (ll)Dd * Dd,  0, nullptr, c_bqkv + Dd, 0, nullptr, qkv + Dd, D3, 1, Dd, 0 };
        hgemm_dualx<<<dim3(18, Tt/128, Bz), 128, NT_SMEM>>>(p0, p1, 6);
    }

    // ---- cross flash ----
    flash_kernel<<<dim3(Tt/128, Hh, Bz), 256, FL_SMEM>>>(qkv, attno, 0, qkv, attno, 0);

    // ---- cross out: x1 = x + attno @ wco^T + c_bo (fp32) ----
    {
        GemmP p = { attno, wco, 0, nullptr, c_bo, 0, x, x1, Dd, 0, Dd, 0 };
        hgemm_one<<<dim3(Dd/128, Tt/128, Bz), 128, NT_SMEM>>>(p);
    }

    // ---- MLP ----
    ln_kernel<<<4096, 256>>>(x1, nmg, nmb, xnh, nullptr, nmg, nmb, xnh, nullptr);

    {
        GemmP p = { xnh, wm1, 0, nullptr, mlp_b1, 0, nullptr, hid, D4, 1, Dd, 1 };
        hgemm_one<<<dim3(D4/128, (Bz*Tt)/128, 1), 128, NT_SMEM>>>(p);
    }
    {
        GemmP p = { hid, wm2, 0, nullptr, mlp_b2, 0, x1, out, Dd, 0, D4, 0 };
        hgemm_one<<<dim3(Dd/128, (Bz*Tt)/128, 1), 128, NT_SMEM>>>(p);
    }
}